// round 1
// baseline (speedup 1.0000x reference)
#include <cuda_runtime.h>
#include <math.h>

#define SEQL 2048
#define DIMN 2048
#define NHEADS 16
#define HDIM 128
#define HIDDEN 8192
#define LTCN 256
#define RMS_EPS 1.1920929e-07f

// ---------------- scratch (device globals; allocation-free) ----------------
__device__ float g_xn[SEQL * DIMN];
__device__ float g_q[SEQL * DIMN];
__device__ float g_k[SEQL * DIMN];
__device__ float g_v[SEQL * DIMN];
__device__ float g_scores[(long long)NHEADS * SEQL * SEQL];   // 256 MB
__device__ float g_attn[SEQL * DIMN];
__device__ float g_h[SEQL * DIMN];
__device__ float g_gate[SEQL * HIDDEN];
__device__ float g_up[SEQL * HIDDEN];
__device__ float g_inter[SEQL * HIDDEN];
__device__ float g_t0[SEQL * LTCN];
__device__ float g_g0[SEQL * LTCN];
__device__ float g_i0[SEQL * LTCN];
__device__ float g_l0[SEQL * LTCN];
__device__ float g_l1[SEQL * LTCN];

// ---------------- generic fp32 SGEMM: C = alpha*A@B(^T) (+ D) ----------------
// BM=BN=128, BK=8, 256 threads, 8x8 microtile. All dims assumed multiples of tile
// (true for every call in this problem). Batched via blockIdx.z strides.
template <bool TB, bool ADD>
__global__ __launch_bounds__(256) void sgemm(
    const float* __restrict__ A, const float* __restrict__ B,
    const float* __restrict__ D, float* __restrict__ C,
    int K, int lda, int ldb, int ldd, int ldc, float alpha,
    long long sA, long long sB, long long sD, long long sC)
{
    A += (long long)blockIdx.z * sA;
    B += (long long)blockIdx.z * sB;
    C += (long long)blockIdx.z * sC;
    if (ADD) D += (long long)blockIdx.z * sD;

    __shared__ float As[8][128];
    __shared__ float Bs[8][128];

    const int bm = blockIdx.y * 128;
    const int bn = blockIdx.x * 128;
    const int tid = threadIdx.x;

    // A-tile load map: 128 rows x 8 k; each thread: 4 consecutive k of one row
    const int arow = tid >> 1;
    const int ak0  = (tid & 1) * 4;
    // B-tile (NN) load map: 8 k x 128 n; each thread: 4 consecutive n of one k
    const int bk  = tid >> 5;
    const int bn0 = (tid & 31) * 4;

    const int ty = tid >> 4;   // 0..15 -> rows ty*8..ty*8+7
    const int tx = tid & 15;   // 0..15 -> cols tx*8..tx*8+7

    float acc[8][8];
#pragma unroll
    for (int i = 0; i < 8; i++)
#pragma unroll
        for (int j = 0; j < 8; j++) acc[i][j] = 0.f;

    for (int k0 = 0; k0 < K; k0 += 8) {
        // load A tile (k-major in shared)
        {
            float4 va = *reinterpret_cast<const float4*>(
                &A[(long long)(bm + arow) * lda + (k0 + ak0)]);
            As[ak0 + 0][arow] = va.x;
            As[ak0 + 1][arow] = va.y;
            As[ak0 + 2][arow] = va.z;
            As[ak0 + 3][arow] = va.w;
        }
        if (TB) {
            // B is [N,K] row-major: Bs[k][n] = B[(bn+n)*ldb + k]
            float4 vb = *reinterpret_cast<const float4*>(
                &B[(long long)(bn + arow) * ldb + (k0 + ak0)]);
            Bs[ak0 + 0][arow] = vb.x;
            Bs[ak0 + 1][arow] = vb.y;
            Bs[ak0 + 2][arow] = vb.z;
            Bs[ak0 + 3][arow] = vb.w;
        } else {
            float4 vb = *reinterpret_cast<const float4*>(
                &B[(long long)(k0 + bk) * ldb + (bn + bn0)]);
            *reinterpret_cast<float4*>(&Bs[bk][bn0]) = vb;
        }
        __syncthreads();

#pragma unroll
        for (int kk = 0; kk < 8; kk++) {
            float4 a0 = *reinterpret_cast<const float4*>(&As[kk][ty * 8]);
            float4 a1 = *reinterpret_cast<const float4*>(&As[kk][ty * 8 + 4]);
            float4 b0 = *reinterpret_cast<const float4*>(&Bs[kk][tx * 8]);
            float4 b1 = *reinterpret_cast<const float4*>(&Bs[kk][tx * 8 + 4]);
            float a[8] = {a0.x, a0.y, a0.z, a0.w, a1.x, a1.y, a1.z, a1.w};
            float b[8] = {b0.x, b0.y, b0.z, b0.w, b1.x, b1.y, b1.z, b1.w};
#pragma unroll
            for (int i = 0; i < 8; i++)
#pragma unroll
                for (int j = 0; j < 8; j++) acc[i][j] = fmaf(a[i], b[j], acc[i][j]);
        }
        __syncthreads();
    }

#pragma unroll
    for (int i = 0; i < 8; i++) {
        const long long r = bm + ty * 8 + i;
#pragma unroll
        for (int j = 0; j < 8; j++) {
            const int c = bn + tx * 8 + j;
            float vv = alpha * acc[i][j];
            if (ADD) vv += D[r * ldd + c];
            C[r * ldc + c] = vv;
        }
    }
}

// ---------------- RMSNorm ----------------
__global__ __launch_bounds__(256) void rmsnorm_k(
    const float* __restrict__ x, const float* __restrict__ w, float* __restrict__ y)
{
    const int r = blockIdx.x;
    const int tid = threadIdx.x;
    const float* xr = x + (long long)r * DIMN;
    float ss = 0.f;
    for (int i = tid; i < DIMN; i += 256) { float v = xr[i]; ss += v * v; }
    __shared__ float red[256];
    red[tid] = ss; __syncthreads();
    for (int s = 128; s > 0; s >>= 1) { if (tid < s) red[tid] += red[tid + s]; __syncthreads(); }
    const float scale = rsqrtf(red[0] * (1.0f / DIMN) + RMS_EPS);
    float* yr = y + (long long)r * DIMN;
    for (int i = tid; i < DIMN; i += 256) yr[i] = xr[i] * scale * w[i];
}

// ---------------- spike (+ optional RoPE), in place ----------------
__global__ __launch_bounds__(256) void spike_rope_k(float* __restrict__ q, int do_rope)
{
    const int idx = blockIdx.x * 256 + threadIdx.x;   // SEQL*NHEADS*64 exactly
    const int d = idx & 63;
    const int h = (idx >> 6) & (NHEADS - 1);
    const int s = idx >> 10;
    const long long base = (long long)s * DIMN + h * HDIM;
    const float a = q[base + d];
    const float b = q[base + d + 64];
    const float sa = a > 1.0f ? 1.f : 0.f;
    const float sb = b > 1.0f ? 1.f : 0.f;
    if (do_rope) {
        const float invf = powf(10000.0f, -(float)d * (1.0f / 64.0f));
        const float fr = (float)s * invf;          // f32-rounded arg, like reference
        double sd, cd;
        sincos((double)fr, &sd, &cd);              // accurate trig of that arg
        const float c = (float)cd, si = (float)sd;
        q[base + d]      = sa * c - sb * si;
        q[base + d + 64] = sb * c + sa * si;
    } else {
        q[base + d] = sa;
        q[base + d + 64] = sb;
    }
}

// ---------------- causal softmax over one (head,row) ----------------
__global__ __launch_bounds__(256) void softmax_causal_k(float* __restrict__ sc)
{
    const int q = blockIdx.x;
    const int h = blockIdx.y;
    float* row = sc + ((long long)h * SEQL + q) * SEQL;
    const int n = q + 1;
    const int tid = threadIdx.x;
    __shared__ float red[256];

    float m = -1e30f;
    for (int i = tid; i < n; i += 256) m = fmaxf(m, row[i]);
    red[tid] = m; __syncthreads();
    for (int s = 128; s > 0; s >>= 1) { if (tid < s) red[tid] = fmaxf(red[tid], red[tid + s]); __syncthreads(); }
    m = red[0]; __syncthreads();

    float sum = 0.f;
    for (int i = tid; i < n; i += 256) { float e = expf(row[i] - m); row[i] = e; sum += e; }
    red[tid] = sum; __syncthreads();
    for (int s = 128; s > 0; s >>= 1) { if (tid < s) red[tid] += red[tid + s]; __syncthreads(); }
    const float inv = 1.0f / red[0];

    for (int i = tid; i < n; i += 256) row[i] *= inv;
    for (int i = n + tid; i < SEQL; i += 256) row[i] = 0.f;
}

// ---------------- SwiGLU elementwise ----------------
__global__ __launch_bounds__(256) void silu_mul_k(
    const float* __restrict__ g, const float* __restrict__ u, float* __restrict__ o)
{
    const long long i = (long long)blockIdx.x * 256 + threadIdx.x;
    const float x = g[i];
    o[i] = (x / (1.f + expf(-x))) * u[i];
}

// ---------------- LTC cell combine (h = 0 closed form) ----------------
__global__ __launch_bounds__(256) void ltc_combine_k(
    const float* __restrict__ t0, const float* __restrict__ g0, const float* __restrict__ i0,
    const float* __restrict__ tb, const float* __restrict__ gb,
    const float* __restrict__ ib, const float* __restrict__ hb,
    float* __restrict__ out)
{
    const int i = blockIdx.x * 256 + threadIdx.x;
    const int n = i & (LTCN - 1);
    const float tau = 0.1f + 9.9f / (1.f + expf(-(t0[i] + tb[n])));
    const float gt  = 1.f / (1.f + expf(-(g0[i] + gb[n])));
    const float ic  = tanhf(i0[i] + ib[n]);
    const float hc  = tanhf(hb[n]);
    const float target = gt * ic + (1.f - gt) * hc;
    out[i] = tanhf(target / (tau + 1e-8f));
}

// ---------------- launcher ----------------
extern "C" void kernel_launch(void* const* d_in, const int* in_sizes, int n_in,
                              void* d_out, int out_size)
{
    (void)in_sizes; (void)n_in; (void)out_size;
    const float* x       = (const float*)d_in[0];
    const float* anw     = (const float*)d_in[1];
    const float* fnw     = (const float*)d_in[2];
    const float* qw      = (const float*)d_in[3];
    const float* kw      = (const float*)d_in[4];
    const float* vw      = (const float*)d_in[5];
    const float* ow      = (const float*)d_in[6];
    const float* gatew   = (const float*)d_in[7];
    const float* upw     = (const float*)d_in[8];
    const float* downw   = (const float*)d_in[9];
    const float* projw   = (const float*)d_in[10];
    const float* c0tw    = (const float*)d_in[11];
    const float* c0tb    = (const float*)d_in[12];
    const float* c0gw    = (const float*)d_in[13];
    const float* c0gb    = (const float*)d_in[14];
    const float* c0iw    = (const float*)d_in[15];
    const float* c0ib    = (const float*)d_in[16];
    const float* c0hb    = (const float*)d_in[18];   // c0_hid_w at 17 unused (h=0)
    const float* c1tw    = (const float*)d_in[19];
    const float* c1tb    = (const float*)d_in[20];
    const float* c1gw    = (const float*)d_in[21];
    const float* c1gb    = (const float*)d_in[22];
    const float* c1iw    = (const float*)d_in[23];
    const float* c1ib    = (const float*)d_in[24];
    const float* c1hb    = (const float*)d_in[26];   // c1_hid_w at 25 unused
    float* out = (float*)d_out;

    float *xn, *q, *k, *v, *sc, *attn, *h, *gate, *up, *inter, *t0, *g0, *i0, *l0, *l1;
    cudaGetSymbolAddress((void**)&xn, g_xn);
    cudaGetSymbolAddress((void**)&q, g_q);
    cudaGetSymbolAddress((void**)&k, g_k);
    cudaGetSymbolAddress((void**)&v, g_v);
    cudaGetSymbolAddress((void**)&sc, g_scores);
    cudaGetSymbolAddress((void**)&attn, g_attn);
    cudaGetSymbolAddress((void**)&h, g_h);
    cudaGetSymbolAddress((void**)&gate, g_gate);
    cudaGetSymbolAddress((void**)&up, g_up);
    cudaGetSymbolAddress((void**)&inter, g_inter);
    cudaGetSymbolAddress((void**)&t0, g_t0);
    cudaGetSymbolAddress((void**)&g0, g_g0);
    cudaGetSymbolAddress((void**)&i0, g_i0);
    cudaGetSymbolAddress((void**)&l0, g_l0);
    cudaGetSymbolAddress((void**)&l1, g_l1);

    const float att_scale = 0.08838834764831845f;    // 1/sqrt(128)
    const dim3 gDD(DIMN / 128, SEQL / 128);           // 2048x2048 out
    const dim3 gHID(HIDDEN / 128, SEQL / 128);        // 2048x8192 out
    const dim3 gLTC(LTCN / 128, SEQL / 128);          // 2048x256 out

    // --- attention ---
    rmsnorm_k<<<SEQL, 256>>>(x, anw, xn);
    sgemm<false, false><<<gDD, 256>>>(xn, qw, nullptr, q, DIMN, DIMN, DIMN, 0, DIMN, 1.f, 0, 0, 0, 0);
    sgemm<false, false><<<gDD, 256>>>(xn, kw, nullptr, k, DIMN, DIMN, DIMN, 0, DIMN, 1.f, 0, 0, 0, 0);
    sgemm<false, false><<<gDD, 256>>>(xn, vw, nullptr, v, DIMN, DIMN, DIMN, 0, DIMN, 1.f, 0, 0, 0, 0);
    spike_rope_k<<<SEQL * NHEADS * 64 / 256, 256>>>(q, 1);
    spike_rope_k<<<SEQL * NHEADS * 64 / 256, 256>>>(k, 1);
    spike_rope_k<<<SEQL * NHEADS * 64 / 256, 256>>>(v, 0);
    // scores[h] = rq_h @ rk_h^T * scale   (batched over heads)
    sgemm<true, false><<<dim3(SEQL / 128, SEQL / 128, NHEADS), 256>>>(
        q, k, nullptr, sc, HDIM, DIMN, DIMN, 0, SEQL, att_scale,
        HDIM, HDIM, 0, (long long)SEQL * SEQL);
    softmax_causal_k<<<dim3(SEQL, NHEADS), 256>>>(sc);
    // out_h = probs_h @ sv_h
    sgemm<false, false><<<dim3(1, SEQL / 128, NHEADS), 256>>>(
        sc, v, nullptr, attn, SEQL, SEQL, DIMN, 0, DIMN, 1.f,
        (long long)SEQL * SEQL, HDIM, 0, HDIM);
    // h = x + attn @ o_w
    sgemm<false, true><<<gDD, 256>>>(attn, ow, x, h, DIMN, DIMN, DIMN, DIMN, DIMN, 1.f, 0, 0, 0, 0);

    // --- LTC feed-forward ---
    rmsnorm_k<<<SEQL, 256>>>(h, fnw, xn);
    sgemm<false, false><<<gHID, 256>>>(xn, gatew, nullptr, gate, DIMN, DIMN, HIDDEN, 0, HIDDEN, 1.f, 0, 0, 0, 0);
    sgemm<false, false><<<gHID, 256>>>(xn, upw, nullptr, up, DIMN, DIMN, HIDDEN, 0, HIDDEN, 1.f, 0, 0, 0, 0);
    silu_mul_k<<<SEQL * (HIDDEN / 256), 256>>>(gate, up, inter);

    // cell 0: inputs inter [2048, 8192]; h=0 so only first HIDDEN rows of tau/gate weights
    sgemm<false, false><<<gLTC, 256>>>(inter, c0tw, nullptr, t0, HIDDEN, HIDDEN, LTCN, 0, LTCN, 1.f, 0, 0, 0, 0);
    sgemm<false, false><<<gLTC, 256>>>(inter, c0gw, nullptr, g0, HIDDEN, HIDDEN, LTCN, 0, LTCN, 1.f, 0, 0, 0, 0);
    sgemm<false, false><<<gLTC, 256>>>(inter, c0iw, nullptr, i0, HIDDEN, HIDDEN, LTCN, 0, LTCN, 1.f, 0, 0, 0, 0);
    ltc_combine_k<<<SEQL * LTCN / 256, 256>>>(t0, g0, i0, c0tb, c0gb, c0ib, c0hb, l0);

    // cell 1: inputs l0 [2048, 256]
    sgemm<false, false><<<gLTC, 256>>>(l0, c1tw, nullptr, t0, LTCN, LTCN, LTCN, 0, LTCN, 1.f, 0, 0, 0, 0);
    sgemm<false, false><<<gLTC, 256>>>(l0, c1gw, nullptr, g0, LTCN, LTCN, LTCN, 0, LTCN, 1.f, 0, 0, 0, 0);
    sgemm<false, false><<<gLTC, 256>>>(l0, c1iw, nullptr, i0, LTCN, LTCN, LTCN, 0, LTCN, 1.f, 0, 0, 0, 0);
    ltc_combine_k<<<SEQL * LTCN / 256, 256>>>(t0, g0, i0, c1tb, c1gb, c1ib, c1hb, l1);

    // enhanced = inter + l1 @ proj   (into g_up)
    sgemm<false, true><<<gHID, 256>>>(l1, projw, inter, up, LTCN, LTCN, HIDDEN, HIDDEN, HIDDEN, 1.f, 0, 0, 0, 0);
    // out = h + enhanced @ down_w
    sgemm<false, true><<<gDD, 256>>>(up, downw, h, out, HIDDEN, HIDDEN, DIMN, DIMN, DIMN, 1.f, 0, 0, 0, 0);
}

// round 3
// speedup vs baseline: 2.9271x; 2.9271x over previous
#include <cuda_runtime.h>
#include <cuda_bf16.h>
#include <math.h>
#include <stdint.h>

#define SEQL 2048
#define DIMN 2048
#define NHEADS 16
#define HDIM 128
#define HIDDEN 8192
#define LTCN 256
#define RMS_EPS 1.1920929e-07f
typedef long long ll;

// ======================= fp32 scratch =======================
__align__(256) __device__ float g_xn[SEQL * DIMN];
__align__(256) __device__ float g_q[SEQL * DIMN];
__align__(256) __device__ float g_k[SEQL * DIMN];
__align__(256) __device__ float g_v[SEQL * DIMN];
__align__(256) __device__ float g_scores[(ll)NHEADS * SEQL * SEQL];
__align__(256) __device__ float g_attn[SEQL * DIMN];
__align__(256) __device__ float g_h[SEQL * DIMN];
__align__(256) __device__ float g_gate[SEQL * HIDDEN];
__align__(256) __device__ float g_up[SEQL * HIDDEN];
__align__(256) __device__ float g_inter[SEQL * HIDDEN];
__align__(256) __device__ float g_ltc3[3LL * SEQL * LTCN];
__align__(256) __device__ float g_l0[SEQL * LTCN];
__align__(256) __device__ float g_l1[SEQL * LTCN];

// ======================= packed bf16 operands =======================
__align__(256) __device__ __nv_bfloat16 p_xn[2048LL * 6144];
__align__(256) __device__ __nv_bfloat16 p_qw[2048LL * 6144];
__align__(256) __device__ __nv_bfloat16 p_kw[2048LL * 6144];
__align__(256) __device__ __nv_bfloat16 p_vw[2048LL * 6144];
__align__(256) __device__ __nv_bfloat16 p_ow[2048LL * 6144];
__align__(256) __device__ __nv_bfloat16 p_gw[8192LL * 6144];
__align__(256) __device__ __nv_bfloat16 p_uw[8192LL * 6144];
__align__(256) __device__ __nv_bfloat16 p_dw[2048LL * 24576];
__align__(256) __device__ __nv_bfloat16 p_pw[8192LL * 768];
__align__(256) __device__ __nv_bfloat16 p_c0w[3LL * 256 * 24576];
__align__(256) __device__ __nv_bfloat16 p_c1w[3LL * 256 * 768];
__align__(256) __device__ __nv_bfloat16 p_q[16LL * 2048 * 384];
__align__(256) __device__ __nv_bfloat16 p_k[16LL * 2048 * 384];
__align__(256) __device__ __nv_bfloat16 p_probs[16LL * 2048 * 4096];
__align__(256) __device__ __nv_bfloat16 p_vt[16LL * 128 * 4096];
__align__(256) __device__ __nv_bfloat16 p_attn[2048LL * 6144];
__align__(256) __device__ __nv_bfloat16 p_inter[2048LL * 24576];
__align__(256) __device__ __nv_bfloat16 p_l0[2048LL * 768];
__align__(256) __device__ __nv_bfloat16 p_l1[2048LL * 768];

// ======================= helpers =======================
__device__ __forceinline__ uint32_t smem_u32(const void* p) {
    uint32_t a;
    asm("{ .reg .u64 t; cvta.to.shared.u64 t, %1; cvt.u32.u64 %0, t; }" : "=r"(a) : "l"(p));
    return a;
}
__device__ __forceinline__ void cp16(uint32_t dst, const void* src) {
    asm volatile("cp.async.cg.shared.global [%0], [%1], 16;" :: "r"(dst), "l"(src));
}
#define CP_COMMIT()  asm volatile("cp.async.commit_group;" ::: "memory")
#define CP_WAIT1()   asm volatile("cp.async.wait_group 1;" ::: "memory")

__device__ __forceinline__ void ldmx4(uint32_t* r, uint32_t addr) {
    asm volatile("ldmatrix.sync.aligned.m8n8.x4.shared.b16 {%0,%1,%2,%3}, [%4];"
                 : "=r"(r[0]), "=r"(r[1]), "=r"(r[2]), "=r"(r[3]) : "r"(addr));
}
__device__ __forceinline__ void mma16816(float* d, const uint32_t* a, uint32_t b0, uint32_t b1) {
    asm volatile(
        "mma.sync.aligned.m16n8k16.row.col.f32.bf16.bf16.f32 "
        "{%0,%1,%2,%3}, {%4,%5,%6,%7}, {%8,%9}, {%0,%1,%2,%3};"
        : "+f"(d[0]), "+f"(d[1]), "+f"(d[2]), "+f"(d[3])
        : "r"(a[0]), "r"(a[1]), "r"(a[2]), "r"(a[3]), "r"(b0), "r"(b1));
}

// ======================= HMMA GEMM =======================
// C[M][N] = alpha * A[M][Kp] x B[N][Kp]^T (+ Dadd). A,B K-major bf16.
// CTA tile 128x128, BK=32. 8 warps (4M x 2N), warp tile 32x64.
// SMEM rows padded to 80B => ldmatrix conflict-free (gcd(80,128)=16).
#define PITCH 80
template <bool CAUSAL>
__global__ __launch_bounds__(256) void hgemm(
    const __nv_bfloat16* __restrict__ A, int lda, ll sA,
    const __nv_bfloat16* __restrict__ B, int ldb, ll sB,
    float* __restrict__ C, int ldc, ll sC,
    const float* __restrict__ Dadd, int ldd, ll sD,
    int Kp, float alpha)
{
    const int bm = blockIdx.y * 128;
    const int bn = blockIdx.x * 128;
    if (CAUSAL && bn > bm + 127) return;

    const int z = blockIdx.z;
    A += (ll)z * sA;
    B += (ll)z * sB;
    C += (ll)z * sC;
    if (Dadd) Dadd += (ll)z * sD;

    __shared__ char smem[4 * 128 * PITCH];          // A0 A1 B0 B1
    const uint32_t sb = smem_u32(smem);
    const uint32_t Abase[2] = {sb, sb + 128 * PITCH};
    const uint32_t Bbase[2] = {sb + 2 * 128 * PITCH, sb + 3 * 128 * PITCH};

    const int tid = threadIdx.x;
    const int lane = tid & 31;
    const int wid = tid >> 5;
    const int wm = wid & 3;       // 0..3  -> M offset wm*32
    const int wn = wid >> 2;      // 0..1  -> N offset wn*64

    float acc[2][8][4];
#pragma unroll
    for (int i = 0; i < 2; i++)
#pragma unroll
        for (int j = 0; j < 8; j++)
#pragma unroll
            for (int t = 0; t < 4; t++) acc[i][j][t] = 0.f;

    const int nK = Kp >> 5;

    auto load_stage = [&](int s, int b) {
        const char* Ag = (const char*)A + (ll)s * 64;
#pragma unroll
        for (int j = 0; j < 2; j++) {
            int q = tid + j * 256;
            int r = q >> 2, c = q & 3;
            cp16(Abase[b] + r * PITCH + c * 16, Ag + (ll)(bm + r) * lda * 2 + c * 16);
        }
        const char* Bg = (const char*)B + (ll)s * 64;
#pragma unroll
        for (int j = 0; j < 2; j++) {
            int q = tid + j * 256;
            int r = q >> 2, c = q & 3;
            cp16(Bbase[b] + r * PITCH + c * 16, Bg + (ll)(bn + r) * ldb * 2 + c * 16);
        }
    };

    load_stage(0, 0); CP_COMMIT();
    if (nK > 1) load_stage(1, 1);
    CP_COMMIT();

    for (int i = 0; i < nK; i++) {
        const int buf = i & 1;
        CP_WAIT1();
        __syncthreads();

        const uint32_t Ab = Abase[buf], Bb = Bbase[buf];
#pragma unroll
        for (int ks = 0; ks < 2; ks++) {
            uint32_t a[2][4];
#pragma unroll
            for (int mt = 0; mt < 2; mt++) {
                const int row = wm * 32 + mt * 16 + (lane & 15);
                ldmx4(a[mt], Ab + row * PITCH + (ks * 2 + (lane >> 4)) * 16);
            }
            uint32_t bf[4][4];
#pragma unroll
            for (int p = 0; p < 4; p++) {
                const int nrow = wn * 64 + p * 16 + ((lane >> 4) << 3) + (lane & 7);
                ldmx4(bf[p], Bb + nrow * PITCH + (ks * 2 + ((lane >> 3) & 1)) * 16);
            }
#pragma unroll
            for (int mt = 0; mt < 2; mt++)
#pragma unroll
                for (int j = 0; j < 8; j++)
                    mma16816(acc[mt][j], a[mt], bf[j >> 1][(j & 1) * 2], bf[j >> 1][(j & 1) * 2 + 1]);
        }
        __syncthreads();
        if (i + 2 < nK) load_stage(i + 2, buf);
        CP_COMMIT();
    }

    // epilogue: direct register -> global, fused alpha + residual
    const int r0 = lane >> 2;
    const int c0 = (lane & 3) * 2;
#pragma unroll
    for (int mt = 0; mt < 2; mt++) {
#pragma unroll
        for (int j = 0; j < 8; j++) {
            const int col = bn + wn * 64 + j * 8 + c0;
            const ll row0 = bm + wm * 32 + mt * 16 + r0;
            const ll row1 = row0 + 8;
            float2 v0 = {alpha * acc[mt][j][0], alpha * acc[mt][j][1]};
            float2 v1 = {alpha * acc[mt][j][2], alpha * acc[mt][j][3]};
            if (Dadd) {
                float2 d0 = *reinterpret_cast<const float2*>(Dadd + row0 * ldd + col);
                float2 d1 = *reinterpret_cast<const float2*>(Dadd + row1 * ldd + col);
                v0.x += d0.x; v0.y += d0.y; v1.x += d1.x; v1.y += d1.y;
            }
            *reinterpret_cast<float2*>(C + row0 * ldc + col) = v0;
            *reinterpret_cast<float2*>(C + row1 * ldc + col) = v1;
        }
    }
}

// ======================= pack kernels =======================
__device__ __forceinline__ void split2f(float x, unsigned short& h, unsigned short& l) {
    __nv_bfloat16 hb = __float2bfloat16_rn(x);
    __nv_bfloat16 lb = __float2bfloat16_rn(x - __bfloat162float(hb));
    h = __bfloat16_as_ushort(hb);
    l = __bfloat16_as_ushort(lb);
}

// mode 0: [hi|hi|lo]   mode 1: [hi|lo|hi]   mode 2: [hi|lo]   mode 3: [x|x]
__global__ __launch_bounds__(256) void split_k(
    const float* __restrict__ in, ll inZ, int ldin,
    __nv_bfloat16* __restrict__ out, ll outZ, int C, int mode)
{
    const ll idx = (ll)blockIdx.x * 256 + threadIdx.x;
    const int c4n = C >> 2;
    const ll r = idx / c4n;
    const int c = (int)(idx % c4n) * 4;
    const float4 v = *reinterpret_cast<const float4*>(in + (ll)blockIdx.z * inZ + r * ldin + c);
    ushort4 hi, lo;
    split2f(v.x, hi.x, lo.x); split2f(v.y, hi.y, lo.y);
    split2f(v.z, hi.z, lo.z); split2f(v.w, hi.w, lo.w);
    const int terms = (mode < 2) ? 3 : 2;
    __nv_bfloat16* op = out + (ll)blockIdx.z * outZ + r * ((ll)terms * C) + c;
    ushort4* s0 = reinterpret_cast<ushort4*>(op);
    ushort4* s1 = reinterpret_cast<ushort4*>(op + C);
    ushort4* s2 = reinterpret_cast<ushort4*>(op + 2 * C);
    if (mode == 0)      { *s0 = hi; *s1 = hi; *s2 = lo; }
    else if (mode == 1) { *s0 = hi; *s1 = lo; *s2 = hi; }
    else if (mode == 2) { *s0 = hi; *s1 = lo; }
    else                { *s0 = hi; *s1 = hi; }
}

// transpose+split: out[n][slot*K + k] = f(in[k][zcol + n])
__global__ void splitT_k(
    const float* __restrict__ in, int ldin, ll inZcols,
    __nv_bfloat16* __restrict__ out, ll outZ, int K, int mode)
{
    __shared__ float t[32][33];
    const int k0 = blockIdx.x * 32, n0 = blockIdx.y * 32;
    const int tx = threadIdx.x, ty = threadIdx.y;
    const float* ip = in + (ll)blockIdx.z * inZcols;
#pragma unroll
    for (int j = 0; j < 4; j++)
        t[ty + j * 8][tx] = ip[(ll)(k0 + ty + j * 8) * ldin + n0 + tx];
    __syncthreads();
    const int terms = (mode < 2) ? 3 : 2;
    __nv_bfloat16* op = out + (ll)blockIdx.z * outZ;
#pragma unroll
    for (int j = 0; j < 4; j++) {
        const int n = n0 + ty + j * 8, k = k0 + tx;
        const float x = t[tx][ty + j * 8];
        unsigned short h, l;
        split2f(x, h, l);
        __nv_bfloat16* base = op + (ll)n * ((ll)terms * K) + k;
        const __nv_bfloat16 hb = __ushort_as_bfloat16(h), lb = __ushort_as_bfloat16(l);
        if (mode == 0)      { base[0] = hb; base[K] = hb; base[2 * K] = lb; }
        else if (mode == 1) { base[0] = hb; base[K] = lb; base[2 * K] = hb; }
        else if (mode == 2) { base[0] = hb; base[K] = lb; }
        else                { base[0] = hb; base[K] = hb; }
    }
}

// ======================= elementwise kernels =======================
__global__ __launch_bounds__(256) void rmsnorm_k(
    const float* __restrict__ x, const float* __restrict__ w, float* __restrict__ y)
{
    const int r = blockIdx.x, tid = threadIdx.x;
    const float* xr = x + (ll)r * DIMN;
    float ss = 0.f;
    for (int i = tid; i < DIMN; i += 256) { float v = xr[i]; ss += v * v; }
    __shared__ float red[256];
    red[tid] = ss; __syncthreads();
    for (int s = 128; s > 0; s >>= 1) { if (tid < s) red[tid] += red[tid + s]; __syncthreads(); }
    const float scale = rsqrtf(red[0] * (1.0f / DIMN) + RMS_EPS);
    float* yr = y + (ll)r * DIMN;
    for (int i = tid; i < DIMN; i += 256) yr[i] = xr[i] * scale * w[i];
}

__global__ __launch_bounds__(256) void spike_rope_k(float* __restrict__ q, int do_rope)
{
    const int idx = blockIdx.x * 256 + threadIdx.x;
    const int d = idx & 63;
    const int h = (idx >> 6) & (NHEADS - 1);
    const int s = idx >> 10;
    const ll base = (ll)s * DIMN + h * HDIM;
    const float a = q[base + d];
    const float b = q[base + d + 64];
    const float sa = a > 1.0f ? 1.f : 0.f;
    const float sb = b > 1.0f ? 1.f : 0.f;
    if (do_rope) {
        const float invf = powf(10000.0f, -(float)d * (1.0f / 64.0f));
        const float fr = (float)s * invf;
        double sd, cd;
        sincos((double)fr, &sd, &cd);
        const float c = (float)cd, si = (float)sd;
        q[base + d]      = sa * c - sb * si;
        q[base + d + 64] = sb * c + sa * si;
    } else {
        q[base + d] = sa;
        q[base + d + 64] = sb;
    }
}

__global__ __launch_bounds__(256) void softmax_causal_k(float* __restrict__ sc)
{
    const int q = blockIdx.x, h = blockIdx.y, tid = threadIdx.x;
    float* row = sc + ((ll)h * SEQL + q) * SEQL;
    const int n = q + 1;
    __shared__ float red[256];
    float m = -1e30f;
    for (int i = tid; i < n; i += 256) m = fmaxf(m, row[i]);
    red[tid] = m; __syncthreads();
    for (int s = 128; s > 0; s >>= 1) { if (tid < s) red[tid] = fmaxf(red[tid], red[tid + s]); __syncthreads(); }
    m = red[0]; __syncthreads();
    float sum = 0.f;
    for (int i = tid; i < n; i += 256) { float e = expf(row[i] - m); row[i] = e; sum += e; }
    red[tid] = sum; __syncthreads();
    for (int s = 128; s > 0; s >>= 1) { if (tid < s) red[tid] += red[tid + s]; __syncthreads(); }
    const float inv = 1.0f / red[0];
    for (int i = tid; i < n; i += 256) row[i] *= inv;
    for (int i = n + tid; i < SEQL; i += 256) row[i] = 0.f;
}

__global__ __launch_bounds__(256) void silu_mul_k(
    const float* __restrict__ g, const float* __restrict__ u, float* __restrict__ o)
{
    const ll i = (ll)blockIdx.x * 256 + threadIdx.x;
    const float x = g[i];
    o[i] = (x / (1.f + expf(-x))) * u[i];
}

__global__ __launch_bounds__(256) void ltc_combine_k(
    const float* __restrict__ t0, const float* __restrict__ g0, const float* __restrict__ i0,
    const float* __restrict__ tb, const float* __restrict__ gb,
    const float* __restrict__ ib, const float* __restrict__ hb,
    float* __restrict__ out)
{
    const int i = blockIdx.x * 256 + threadIdx.x;
    const int n = i & (LTCN - 1);
    const float tau = 0.1f + 9.9f / (1.f + expf(-(t0[i] + tb[n])));
    const float gt  = 1.f / (1.f + expf(-(g0[i] + gb[n])));
    const float ic  = tanhf(i0[i] + ib[n]);
    const float hc  = tanhf(hb[n]);
    const float target = gt * ic + (1.f - gt) * hc;
    out[i] = tanhf(target / (tau + 1e-8f));
}

// ======================= launcher =======================
static inline float* SYMF(const void* s) { void* p; cudaGetSymbolAddress(&p, s); return (float*)p; }
static inline __nv_bfloat16* SYMB(const void* s) { void* p; cudaGetSymbolAddress(&p, s); return (__nv_bfloat16*)p; }

extern "C" void kernel_launch(void* const* d_in, const int* in_sizes, int n_in,
                              void* d_out, int out_size)
{
    (void)in_sizes; (void)n_in; (void)out_size;
    const float* x     = (const float*)d_in[0];
    const float* anw   = (const float*)d_in[1];
    const float* fnw   = (const float*)d_in[2];
    const float* qw    = (const float*)d_in[3];
    const float* kw    = (const float*)d_in[4];
    const float* vw    = (const float*)d_in[5];
    const float* ow    = (const float*)d_in[6];
    const float* gatew = (const float*)d_in[7];
    const float* upw   = (const float*)d_in[8];
    const float* downw = (const float*)d_in[9];
    const float* projw = (const float*)d_in[10];
    const float* c0tw  = (const float*)d_in[11];
    const float* c0tb  = (const float*)d_in[12];
    const float* c0gw  = (const float*)d_in[13];
    const float* c0gb  = (const float*)d_in[14];
    const float* c0iw  = (const float*)d_in[15];
    const float* c0ib  = (const float*)d_in[16];
    const float* c0hb  = (const float*)d_in[18];
    const float* c1tw  = (const float*)d_in[19];
    const float* c1tb  = (const float*)d_in[20];
    const float* c1gw  = (const float*)d_in[21];
    const float* c1gb  = (const float*)d_in[22];
    const float* c1iw  = (const float*)d_in[23];
    const float* c1ib  = (const float*)d_in[24];
    const float* c1hb  = (const float*)d_in[26];
    float* out = (float*)d_out;

    float* xn    = SYMF(g_xn);   float* q    = SYMF(g_q);    float* k   = SYMF(g_k);
    float* v     = SYMF(g_v);    float* sc   = SYMF(g_scores);
    float* attn  = SYMF(g_attn); float* h    = SYMF(g_h);
    float* gate  = SYMF(g_gate); float* up   = SYMF(g_up);   float* inter = SYMF(g_inter);
    float* ltc3  = SYMF(g_ltc3); float* l0   = SYMF(g_l0);   float* l1  = SYMF(g_l1);

    __nv_bfloat16* Pxn = SYMB(p_xn);   __nv_bfloat16* Pqw = SYMB(p_qw);
    __nv_bfloat16* Pkw = SYMB(p_kw);   __nv_bfloat16* Pvw = SYMB(p_vw);
    __nv_bfloat16* Pow = SYMB(p_ow);   __nv_bfloat16* Pgw = SYMB(p_gw);
    __nv_bfloat16* Puw = SYMB(p_uw);   __nv_bfloat16* Pdw = SYMB(p_dw);
    __nv_bfloat16* Ppw = SYMB(p_pw);   __nv_bfloat16* Pc0 = SYMB(p_c0w);
    __nv_bfloat16* Pc1 = SYMB(p_c1w);  __nv_bfloat16* Pq  = SYMB(p_q);
    __nv_bfloat16* Pk  = SYMB(p_k);    __nv_bfloat16* Ppr = SYMB(p_probs);
    __nv_bfloat16* Pvt = SYMB(p_vt);   __nv_bfloat16* Pat = SYMB(p_attn);
    __nv_bfloat16* Pin = SYMB(p_inter);
    __nv_bfloat16* Pl0 = SYMB(p_l0);   __nv_bfloat16* Pl1 = SYMB(p_l1);

    const dim3 t32x8(32, 8);
    const float att_scale = 0.08838834764831845f;

    // ---- pack all weights ----
    splitT_k<<<dim3(64, 64), t32x8>>>(qw, 2048, 0, Pqw, 0, 2048, 1);
    splitT_k<<<dim3(64, 64), t32x8>>>(kw, 2048, 0, Pkw, 0, 2048, 1);
    splitT_k<<<dim3(64, 64), t32x8>>>(vw, 2048, 0, Pvw, 0, 2048, 1);
    splitT_k<<<dim3(64, 64), t32x8>>>(ow, 2048, 0, Pow, 0, 2048, 1);
    splitT_k<<<dim3(64, 256), t32x8>>>(gatew, 8192, 0, Pgw, 0, 2048, 1);
    splitT_k<<<dim3(64, 256), t32x8>>>(upw, 8192, 0, Puw, 0, 2048, 1);
    splitT_k<<<dim3(256, 64), t32x8>>>(downw, 2048, 0, Pdw, 0, 8192, 1);
    splitT_k<<<dim3(8, 256), t32x8>>>(projw, 8192, 0, Ppw, 0, 256, 1);
    splitT_k<<<dim3(256, 8), t32x8>>>(c0tw, 256, 0, Pc0 + 0LL * 256 * 24576, 0, 8192, 1);
    splitT_k<<<dim3(256, 8), t32x8>>>(c0gw, 256, 0, Pc0 + 1LL * 256 * 24576, 0, 8192, 1);
    splitT_k<<<dim3(256, 8), t32x8>>>(c0iw, 256, 0, Pc0 + 2LL * 256 * 24576, 0, 8192, 1);
    splitT_k<<<dim3(8, 8), t32x8>>>(c1tw, 256, 0, Pc1 + 0LL * 256 * 768, 0, 256, 1);
    splitT_k<<<dim3(8, 8), t32x8>>>(c1gw, 256, 0, Pc1 + 1LL * 256 * 768, 0, 256, 1);
    splitT_k<<<dim3(8, 8), t32x8>>>(c1iw, 256, 0, Pc1 + 2LL * 256 * 768, 0, 256, 1);

    // ---- attention ----
    rmsnorm_k<<<SEQL, 256>>>(x, anw, xn);
    split_k<<<2048 * 2048 / 1024, 256>>>(xn, 0, 2048, Pxn, 0, 2048, 0);
    hgemm<false><<<dim3(16, 16), 256>>>(Pxn, 6144, 0, Pqw, 6144, 0, q, 2048, 0, nullptr, 0, 0, 6144, 1.f);
    hgemm<false><<<dim3(16, 16), 256>>>(Pxn, 6144, 0, Pkw, 6144, 0, k, 2048, 0, nullptr, 0, 0, 6144, 1.f);
    hgemm<false><<<dim3(16, 16), 256>>>(Pxn, 6144, 0, Pvw, 6144, 0, v, 2048, 0, nullptr, 0, 0, 6144, 1.f);
    spike_rope_k<<<SEQL * NHEADS * 64 / 256, 256>>>(q, 1);
    spike_rope_k<<<SEQL * NHEADS * 64 / 256, 256>>>(k, 1);
    spike_rope_k<<<SEQL * NHEADS * 64 / 256, 256>>>(v, 0);
    // per-head packs
    split_k<<<dim3(256, 1, 16), 256>>>(q, 128, 2048, Pq, 2048LL * 384, 128, 0);
    split_k<<<dim3(256, 1, 16), 256>>>(k, 128, 2048, Pk, 2048LL * 384, 128, 1);
    splitT_k<<<dim3(64, 4, 16), t32x8>>>(v, 2048, 128, Pvt, 128LL * 4096, 2048, 3);
    // scores (causal-skipped tiles)
    hgemm<true><<<dim3(16, 16, 16), 256>>>(
        Pq, 384, 2048LL * 384, Pk, 384, 2048LL * 384,
        sc, 2048, (ll)SEQL * SEQL, nullptr, 0, 0, 384, att_scale);
    softmax_causal_k<<<dim3(SEQL, NHEADS), 256>>>(sc);
    split_k<<<(ll)16 * 2048 * 2048 / 1024, 256>>>(sc, 0, 2048, Ppr, 0, 2048, 2);
    // attn out per head
    hgemm<false><<<dim3(1, 16, 16), 256>>>(
        Ppr, 4096, 2048LL * 4096, Pvt, 4096, 128LL * 4096,
        attn, 2048, 128, nullptr, 0, 0, 4096, 1.f);
    split_k<<<2048 * 2048 / 1024, 256>>>(attn, 0, 2048, Pat, 0, 2048, 0);
    hgemm<false><<<dim3(16, 16), 256>>>(Pat, 6144, 0, Pow, 6144, 0, h, 2048, 0, x, 2048, 0, 6144, 1.f);

    // ---- LTC feed-forward ----
    rmsnorm_k<<<SEQL, 256>>>(h, fnw, xn);
    split_k<<<2048 * 2048 / 1024, 256>>>(xn, 0, 2048, Pxn, 0, 2048, 0);
    hgemm<false><<<dim3(64, 16), 256>>>(Pxn, 6144, 0, Pgw, 6144, 0, gate, 8192, 0, nullptr, 0, 0, 6144, 1.f);
    hgemm<false><<<dim3(64, 16), 256>>>(Pxn, 6144, 0, Puw, 6144, 0, up, 8192, 0, nullptr, 0, 0, 6144, 1.f);
    silu_mul_k<<<SEQL * (HIDDEN / 256), 256>>>(gate, up, inter);
    split_k<<<2048 * 8192 / 1024, 256>>>(inter, 0, 8192, Pin, 0, 8192, 0);
    // cell 0 (tau/gate/in batched over z)
    hgemm<false><<<dim3(2, 16, 3), 256>>>(
        Pin, 24576, 0, Pc0, 24576, 256LL * 24576,
        ltc3, 256, (ll)SEQL * LTCN, nullptr, 0, 0, 24576, 1.f);
    ltc_combine_k<<<SEQL * LTCN / 256, 256>>>(
        ltc3, ltc3 + (ll)SEQL * LTCN, ltc3 + 2LL * SEQL * LTCN, c0tb, c0gb, c0ib, c0hb, l0);
    split_k<<<2048 * 256 / 1024, 256>>>(l0, 0, 256, Pl0, 0, 256, 0);
    // cell 1
    hgemm<false><<<dim3(2, 16, 3), 256>>>(
        Pl0, 768, 0, Pc1, 768, 256LL * 768,
        ltc3, 256, (ll)SEQL * LTCN, nullptr, 0, 0, 768, 1.f);
    ltc_combine_k<<<SEQL * LTCN / 256, 256>>>(
        ltc3, ltc3 + (ll)SEQL * LTCN, ltc3 + 2LL * SEQL * LTCN, c1tb, c1gb, c1ib, c1hb, l1);
    split_k<<<2048 * 256 / 1024, 256>>>(l1, 0, 256, Pl1, 0, 256, 0);
    // enhanced = inter + l1 @ proj   (into g_up)
    hgemm<false><<<dim3(64, 16), 256>>>(Pl1, 768, 0, Ppw, 768, 0, up, 8192, 0, inter, 8192, 0, 768, 1.f);
    split_k<<<2048 * 8192 / 1024, 256>>>(up, 0, 8192, Pin, 0, 8192, 0);
    // out = h + enhanced @ down_w
    hgemm<false><<<dim3(16, 16), 256>>>(Pin, 24576, 0, Pdw, 24576, 0, out, 2048, 0, h, 2048, 0, 24576, 1.f);
}

// round 6
// speedup vs baseline: 2.9755x; 1.0165x over previous
#include <cuda_runtime.h>
#include <cuda_bf16.h>
#include <math.h>
#include <stdint.h>

#define SEQL 2048
#define DIMN 2048
#define NHEADS 16
#define HDIM 128
#define HIDDEN 8192
#define LTCN 256
#define RMS_EPS 1.1920929e-07f
typedef long long ll;

// ======================= fp32 scratch =======================
__align__(256) __device__ float g_qkv[2048LL * 6144];
__align__(256) __device__ float g_scores[(ll)NHEADS * SEQL * SEQL];
__align__(256) __device__ float g_attn[SEQL * DIMN];
__align__(256) __device__ float g_h[SEQL * DIMN];
__align__(256) __device__ float g_gu[2048LL * 16384];
__align__(256) __device__ float g_up[SEQL * HIDDEN];
__align__(256) __device__ float g_inter[SEQL * HIDDEN];
__align__(256) __device__ float g_part[8LL * 2048 * 768];
__align__(256) __device__ float g_l0[SEQL * LTCN];
__align__(256) __device__ float g_l1[SEQL * LTCN];

// ======================= packed bf16 operands =======================
__align__(256) __device__ __nv_bfloat16 p_xn[2048LL * 6144];
__align__(256) __device__ __nv_bfloat16 p_qkvw[6144LL * 6144];
__align__(256) __device__ __nv_bfloat16 p_ow[2048LL * 6144];
__align__(256) __device__ __nv_bfloat16 p_guw[16384LL * 6144];
__align__(256) __device__ __nv_bfloat16 p_dw[2048LL * 24576];
__align__(256) __device__ __nv_bfloat16 p_pw[8192LL * 768];
__align__(256) __device__ __nv_bfloat16 p_c0w[768LL * 24576];
__align__(256) __device__ __nv_bfloat16 p_c1w[768LL * 768];
__align__(256) __device__ __nv_bfloat16 p_q[16LL * 2048 * 384];
__align__(256) __device__ __nv_bfloat16 p_k[16LL * 2048 * 384];
__align__(256) __device__ __nv_bfloat16 p_probs[16LL * 2048 * 4096];
__align__(256) __device__ __nv_bfloat16 p_vt[16LL * 128 * 4096];
__align__(256) __device__ __nv_bfloat16 p_attn[2048LL * 6144];
__align__(256) __device__ __nv_bfloat16 p_inter[2048LL * 24576];
__align__(256) __device__ __nv_bfloat16 p_l0[2048LL * 768];
__align__(256) __device__ __nv_bfloat16 p_l1[2048LL * 768];

// ======================= helpers =======================
__device__ __forceinline__ uint32_t smem_u32(const void* p) {
    uint32_t a;
    asm("{ .reg .u64 t; cvta.to.shared.u64 t, %1; cvt.u32.u64 %0, t; }" : "=r"(a) : "l"(p));
    return a;
}
__device__ __forceinline__ void cp16(uint32_t dst, const void* src) {
    asm volatile("cp.async.cg.shared.global [%0], [%1], 16;" :: "r"(dst), "l"(src));
}
#define CP_COMMIT()  asm volatile("cp.async.commit_group;" ::: "memory")
#define CP_WAIT1()   asm volatile("cp.async.wait_group 1;" ::: "memory")
#define CP_WAIT2()   asm volatile("cp.async.wait_group 2;" ::: "memory")

__device__ __forceinline__ void ldmx4(uint32_t* r, uint32_t addr) {
    asm volatile("ldmatrix.sync.aligned.m8n8.x4.shared.b16 {%0,%1,%2,%3}, [%4];"
                 : "=r"(r[0]), "=r"(r[1]), "=r"(r[2]), "=r"(r[3]) : "r"(addr));
}
__device__ __forceinline__ void mma16816(float* d, const uint32_t* a, uint32_t b0, uint32_t b1) {
    asm volatile(
        "mma.sync.aligned.m16n8k16.row.col.f32.bf16.bf16.f32 "
        "{%0,%1,%2,%3}, {%4,%5,%6,%7}, {%8,%9}, {%0,%1,%2,%3};"
        : "+f"(d[0]), "+f"(d[1]), "+f"(d[2]), "+f"(d[3])
        : "r"(a[0]), "r"(a[1]), "r"(a[2]), "r"(a[3]), "r"(b0), "r"(b1));
}

#define PITCH 80

// ======================= HMMA GEMM 128x256, 3-stage =======================
// C[M][N] = alpha * A[M][Kp] x B[N][Kp]^T (+ Dadd). A,B K-major bf16.
// 8 warps as 2(M) x 4(N); warp tile 64x64. BK=32.
template <bool CAUSAL>
__global__ __launch_bounds__(256, 1) void hgemm256(
    const __nv_bfloat16* __restrict__ A, int lda, ll sA,
    const __nv_bfloat16* __restrict__ B, int ldb, ll sB,
    float* __restrict__ C, int ldc, ll sC,
    const float* __restrict__ Dadd, int ldd, ll sD,
    int Kp, float alpha)
{
    const int bm = blockIdx.y * 128;
    const int bn = blockIdx.x * 256;
    if (CAUSAL && bn > bm + 127) return;

    const int z = blockIdx.z;
    A += (ll)z * sA;
    B += (ll)z * sB;
    C += (ll)z * sC;
    if (Dadd) Dadd += (ll)z * sD;

    extern __shared__ char smem[];
    const uint32_t sb = smem_u32(smem);
    const int tid = threadIdx.x;
    const int lane = tid & 31;
    const int wid = tid >> 5;
    const int wm = wid & 1;       // M offset wm*64
    const int wn = wid >> 1;      // N offset wn*64

    float acc[4][8][4];
#pragma unroll
    for (int i = 0; i < 4; i++)
#pragma unroll
        for (int j = 0; j < 8; j++)
#pragma unroll
            for (int t = 0; t < 4; t++) acc[i][j][t] = 0.f;

    const int nK = Kp >> 5;

    auto load_stage = [&](int s, int b) {
        const uint32_t Ad = sb + b * 30720;
        const char* Ag = (const char*)A + (ll)s * 64;
#pragma unroll
        for (int j = 0; j < 2; j++) {
            int q = tid + j * 256;
            int r = q >> 2, c = q & 3;
            cp16(Ad + r * PITCH + c * 16, Ag + (ll)(bm + r) * lda * 2 + c * 16);
        }
        const uint32_t Bd = Ad + 10240;
        const char* Bg = (const char*)B + (ll)s * 64;
#pragma unroll
        for (int j = 0; j < 4; j++) {
            int q = tid + j * 256;
            int r = q >> 2, c = q & 3;
            cp16(Bd + r * PITCH + c * 16, Bg + (ll)(bn + r) * ldb * 2 + c * 16);
        }
    };

    load_stage(0, 0); CP_COMMIT();
    if (nK > 1) load_stage(1, 1);
    CP_COMMIT();
    if (nK > 2) load_stage(2, 2);
    CP_COMMIT();

    int buf = 0;
    for (int i = 0; i < nK; i++) {
        CP_WAIT2();
        __syncthreads();
        const uint32_t Ab = sb + buf * 30720;
        const uint32_t Bb = Ab + 10240;
#pragma unroll
        for (int ks = 0; ks < 2; ks++) {
            uint32_t a[4][4];
#pragma unroll
            for (int mt = 0; mt < 4; mt++) {
                const int row = wm * 64 + mt * 16 + (lane & 15);
                ldmx4(a[mt], Ab + row * PITCH + (ks * 2 + (lane >> 4)) * 16);
            }
            uint32_t bf[4][4];
#pragma unroll
            for (int p = 0; p < 4; p++) {
                const int nrow = wn * 64 + p * 16 + ((lane >> 4) << 3) + (lane & 7);
                ldmx4(bf[p], Bb + nrow * PITCH + (ks * 2 + ((lane >> 3) & 1)) * 16);
            }
#pragma unroll
            for (int mt = 0; mt < 4; mt++)
#pragma unroll
                for (int j = 0; j < 8; j++)
                    mma16816(acc[mt][j], a[mt], bf[j >> 1][(j & 1) * 2], bf[j >> 1][(j & 1) * 2 + 1]);
        }
        __syncthreads();
        if (i + 3 < nK) load_stage(i + 3, buf);
        CP_COMMIT();
        buf = (buf == 2) ? 0 : buf + 1;
    }

    const int r0 = lane >> 2;
    const int c0 = (lane & 3) * 2;
#pragma unroll
    for (int mt = 0; mt < 4; mt++) {
#pragma unroll
        for (int j = 0; j < 8; j++) {
            const int col = bn + wn * 64 + j * 8 + c0;
            const ll row0 = bm + wm * 64 + mt * 16 + r0;
            const ll row1 = row0 + 8;
            float2 v0 = {alpha * acc[mt][j][0], alpha * acc[mt][j][1]};
            float2 v1 = {alpha * acc[mt][j][2], alpha * acc[mt][j][3]};
            if (Dadd) {
                float2 d0 = *reinterpret_cast<const float2*>(Dadd + row0 * ldd + col);
                float2 d1 = *reinterpret_cast<const float2*>(Dadd + row1 * ldd + col);
                v0.x += d0.x; v0.y += d0.y; v1.x += d1.x; v1.y += d1.y;
            }
            *reinterpret_cast<float2*>(C + row0 * ldc + col) = v0;
            *reinterpret_cast<float2*>(C + row1 * ldc + col) = v1;
        }
    }
}

// ======================= HMMA GEMM 128x128, 2-stage (for AV) =======================
__global__ __launch_bounds__(256) void hgemm(
    const __nv_bfloat16* __restrict__ A, int lda, ll sA,
    const __nv_bfloat16* __restrict__ B, int ldb, ll sB,
    float* __restrict__ C, int ldc, ll sC,
    int Kp, float alpha)
{
    const int bm = blockIdx.y * 128;
    const int bn = blockIdx.x * 128;
    const int z = blockIdx.z;
    A += (ll)z * sA;
    B += (ll)z * sB;
    C += (ll)z * sC;

    __shared__ char smem[4 * 128 * PITCH];
    const uint32_t sb = smem_u32(smem);
    const uint32_t Abase[2] = {sb, sb + 128 * PITCH};
    const uint32_t Bbase[2] = {sb + 2 * 128 * PITCH, sb + 3 * 128 * PITCH};

    const int tid = threadIdx.x;
    const int lane = tid & 31;
    const int wid = tid >> 5;
    const int wm = wid & 3;
    const int wn = wid >> 2;

    float acc[2][8][4];
#pragma unroll
    for (int i = 0; i < 2; i++)
#pragma unroll
        for (int j = 0; j < 8; j++)
#pragma unroll
            for (int t = 0; t < 4; t++) acc[i][j][t] = 0.f;

    const int nK = Kp >> 5;

    auto load_stage = [&](int s, int b) {
        const char* Ag = (const char*)A + (ll)s * 64;
#pragma unroll
        for (int j = 0; j < 2; j++) {
            int q = tid + j * 256;
            int r = q >> 2, c = q & 3;
            cp16(Abase[b] + r * PITCH + c * 16, Ag + (ll)(bm + r) * lda * 2 + c * 16);
        }
        const char* Bg = (const char*)B + (ll)s * 64;
#pragma unroll
        for (int j = 0; j < 2; j++) {
            int q = tid + j * 256;
            int r = q >> 2, c = q & 3;
            cp16(Bbase[b] + r * PITCH + c * 16, Bg + (ll)(bn + r) * ldb * 2 + c * 16);
        }
    };

    load_stage(0, 0); CP_COMMIT();
    if (nK > 1) load_stage(1, 1);
    CP_COMMIT();

    for (int i = 0; i < nK; i++) {
        const int buf = i & 1;
        CP_WAIT1();
        __syncthreads();
        const uint32_t Ab = Abase[buf], Bb = Bbase[buf];
#pragma unroll
        for (int ks = 0; ks < 2; ks++) {
            uint32_t a[2][4];
#pragma unroll
            for (int mt = 0; mt < 2; mt++) {
                const int row = wm * 32 + mt * 16 + (lane & 15);
                ldmx4(a[mt], Ab + row * PITCH + (ks * 2 + (lane >> 4)) * 16);
            }
            uint32_t bf[4][4];
#pragma unroll
            for (int p = 0; p < 4; p++) {
                const int nrow = wn * 64 + p * 16 + ((lane >> 4) << 3) + (lane & 7);
                ldmx4(bf[p], Bb + nrow * PITCH + (ks * 2 + ((lane >> 3) & 1)) * 16);
            }
#pragma unroll
            for (int mt = 0; mt < 2; mt++)
#pragma unroll
                for (int j = 0; j < 8; j++)
                    mma16816(acc[mt][j], a[mt], bf[j >> 1][(j & 1) * 2], bf[j >> 1][(j & 1) * 2 + 1]);
        }
        __syncthreads();
        if (i + 2 < nK) load_stage(i + 2, buf);
        CP_COMMIT();
    }

    const int r0 = lane >> 2;
    const int c0 = (lane & 3) * 2;
#pragma unroll
    for (int mt = 0; mt < 2; mt++) {
#pragma unroll
        for (int j = 0; j < 8; j++) {
            const int col = bn + wn * 64 + j * 8 + c0;
            const ll row0 = bm + wm * 32 + mt * 16 + r0;
            const ll row1 = row0 + 8;
            float2 v0 = {alpha * acc[mt][j][0], alpha * acc[mt][j][1]};
            float2 v1 = {alpha * acc[mt][j][2], alpha * acc[mt][j][3]};
            *reinterpret_cast<float2*>(C + row0 * ldc + col) = v0;
            *reinterpret_cast<float2*>(C + row1 * ldc + col) = v1;
        }
    }
}

// ======================= split helpers =======================
__device__ __forceinline__ void split2f(float x, unsigned short& h, unsigned short& l) {
    __nv_bfloat16 hb = __float2bfloat16_rn(x);
    __nv_bfloat16 lb = __float2bfloat16_rn(x - __bfloat162float(hb));
    h = __bfloat16_as_ushort(hb);
    l = __bfloat16_as_ushort(lb);
}

// mode 0: [hi|hi|lo]   mode 1: [hi|lo|hi]   mode 2: [hi|lo]   mode 3: [x|x]
__global__ __launch_bounds__(256) void split_k(
    const float* __restrict__ in, ll inZ, int ldin,
    __nv_bfloat16* __restrict__ out, ll outZ, int C, int mode)
{
    const ll idx = (ll)blockIdx.x * 256 + threadIdx.x;
    const int c4n = C >> 2;
    const ll r = idx / c4n;
    const int c = (int)(idx % c4n) * 4;
    const float4 v = *reinterpret_cast<const float4*>(in + (ll)blockIdx.z * inZ + r * ldin + c);
    ushort4 hi, lo;
    split2f(v.x, hi.x, lo.x); split2f(v.y, hi.y, lo.y);
    split2f(v.z, hi.z, lo.z); split2f(v.w, hi.w, lo.w);
    const int terms = (mode < 2) ? 3 : 2;
    __nv_bfloat16* op = out + (ll)blockIdx.z * outZ + r * ((ll)terms * C) + c;
    ushort4* s0 = reinterpret_cast<ushort4*>(op);
    ushort4* s1 = reinterpret_cast<ushort4*>(op + C);
    ushort4* s2 = reinterpret_cast<ushort4*>(op + 2 * C);
    if (mode == 0)      { *s0 = hi; *s1 = hi; *s2 = lo; }
    else if (mode == 1) { *s0 = hi; *s1 = lo; *s2 = hi; }
    else if (mode == 2) { *s0 = hi; *s1 = lo; }
    else                { *s0 = hi; *s1 = hi; }
}

// transpose+split: out[n][slot*K + k] = f(in[k][zcol + n])
__global__ void splitT_k(
    const float* __restrict__ in, int ldin, ll inZcols,
    __nv_bfloat16* __restrict__ out, ll outZ, int K, int mode)
{
    __shared__ float t[32][33];
    const int k0 = blockIdx.x * 32, n0 = blockIdx.y * 32;
    const int tx = threadIdx.x, ty = threadIdx.y;
    const float* ip = in + (ll)blockIdx.z * inZcols;
#pragma unroll
    for (int j = 0; j < 4; j++)
        t[ty + j * 8][tx] = ip[(ll)(k0 + ty + j * 8) * ldin + n0 + tx];
    __syncthreads();
    const int terms = (mode < 2) ? 3 : 2;
    __nv_bfloat16* op = out + (ll)blockIdx.z * outZ;
#pragma unroll
    for (int j = 0; j < 4; j++) {
        const int n = n0 + ty + j * 8, k = k0 + tx;
        const float x = t[tx][ty + j * 8];
        unsigned short h, l;
        split2f(x, h, l);
        __nv_bfloat16* base = op + (ll)n * ((ll)terms * K) + k;
        const __nv_bfloat16 hb = __ushort_as_bfloat16(h), lb = __ushort_as_bfloat16(l);
        if (mode == 0)      { base[0] = hb; base[K] = hb; base[2 * K] = lb; }
        else if (mode == 1) { base[0] = hb; base[K] = lb; base[2 * K] = hb; }
        else if (mode == 2) { base[0] = hb; base[K] = lb; }
        else                { base[0] = hb; base[K] = hb; }
    }
}

// ======================= fused elementwise kernels =======================
__global__ __launch_bounds__(256) void rmsnorm_pack_k(
    const float* __restrict__ x, const float* __restrict__ w, __nv_bfloat16* __restrict__ out)
{
    const int r = blockIdx.x, tid = threadIdx.x;
    const float* xr = x + (ll)r * DIMN;
    float ss = 0.f;
    for (int i = tid; i < DIMN; i += 256) { float v = xr[i]; ss += v * v; }
    __shared__ float red[256];
    red[tid] = ss; __syncthreads();
    for (int s = 128; s > 0; s >>= 1) { if (tid < s) red[tid] += red[tid + s]; __syncthreads(); }
    const float scale = rsqrtf(red[0] * (1.0f / DIMN) + RMS_EPS);
    __nv_bfloat16* orow = out + (ll)r * 6144;
    for (int i = tid; i < DIMN; i += 256) {
        const float v = xr[i] * scale * w[i];
        unsigned short h, l;
        split2f(v, h, l);
        orow[i] = __ushort_as_bfloat16(h);
        orow[2048 + i] = __ushort_as_bfloat16(h);
        orow[4096 + i] = __ushort_as_bfloat16(l);
    }
}

__global__ __launch_bounds__(256) void spike_rope_k(float* __restrict__ q, int stride, int do_rope)
{
    const int idx = blockIdx.x * 256 + threadIdx.x;
    const int d = idx & 63;
    const int h = (idx >> 6) & (NHEADS - 1);
    const int s = idx >> 10;
    const ll base = (ll)s * stride + h * HDIM;
    const float a = q[base + d];
    const float b = q[base + d + 64];
    const float sa = a > 1.0f ? 1.f : 0.f;
    const float sb = b > 1.0f ? 1.f : 0.f;
    if (do_rope) {
        const float invf = powf(10000.0f, -(float)d * (1.0f / 64.0f));
        const float fr = (float)s * invf;
        double sd, cd;
        sincos((double)fr, &sd, &cd);
        const float c = (float)cd, si = (float)sd;
        q[base + d]      = sa * c - sb * si;
        q[base + d + 64] = sb * c + sa * si;
    } else {
        q[base + d] = sa;
        q[base + d + 64] = sb;
    }
}

__global__ __launch_bounds__(256) void softmax_pack_k(
    const float* __restrict__ sc, __nv_bfloat16* __restrict__ pr)
{
    const int q = blockIdx.x, h = blockIdx.y, tid = threadIdx.x;
    const float* row = sc + ((ll)h * SEQL + q) * SEQL;
    __nv_bfloat16* orow = pr + (ll)h * SEQL * 4096 + (ll)q * 4096;
    const int n = q + 1;
    __shared__ float red[256];
    float m = -1e30f;
    for (int i = tid; i < n; i += 256) m = fmaxf(m, row[i]);
    red[tid] = m; __syncthreads();
    for (int s = 128; s > 0; s >>= 1) { if (tid < s) red[tid] = fmaxf(red[tid], red[tid + s]); __syncthreads(); }
    m = red[0]; __syncthreads();
    float sum = 0.f;
    for (int i = tid; i < n; i += 256) sum += expf(row[i] - m);
    red[tid] = sum; __syncthreads();
    for (int s = 128; s > 0; s >>= 1) { if (tid < s) red[tid] += red[tid + s]; __syncthreads(); }
    const float inv = 1.0f / red[0];
    const __nv_bfloat16 z = __float2bfloat16_rn(0.f);
    for (int i = tid; i < n; i += 256) {
        const float p = expf(row[i] - m) * inv;
        unsigned short hb, lb;
        split2f(p, hb, lb);
        orow[i] = __ushort_as_bfloat16(hb);
        orow[2048 + i] = __ushort_as_bfloat16(lb);
    }
    for (int i = n + tid; i < SEQL; i += 256) { orow[i] = z; orow[2048 + i] = z; }
}

__global__ __launch_bounds__(256) void silu_mul_pack_k(
    const float* __restrict__ gu, float* __restrict__ inter, __nv_bfloat16* __restrict__ pin)
{
    const ll idx = (ll)blockIdx.x * 256 + threadIdx.x;
    const ll r = idx / 2048;
    const int c = (int)(idx % 2048) * 4;
    const float4 g = *reinterpret_cast<const float4*>(gu + r * 16384 + c);
    const float4 u = *reinterpret_cast<const float4*>(gu + r * 16384 + 8192 + c);
    float4 v;
    v.x = (g.x / (1.f + expf(-g.x))) * u.x;
    v.y = (g.y / (1.f + expf(-g.y))) * u.y;
    v.z = (g.z / (1.f + expf(-g.z))) * u.z;
    v.w = (g.w / (1.f + expf(-g.w))) * u.w;
    *reinterpret_cast<float4*>(inter + r * 8192 + c) = v;
    ushort4 hi, lo;
    split2f(v.x, hi.x, lo.x); split2f(v.y, hi.y, lo.y);
    split2f(v.z, hi.z, lo.z); split2f(v.w, hi.w, lo.w);
    __nv_bfloat16* op = pin + r * 24576 + c;
    *reinterpret_cast<ushort4*>(op) = hi;
    *reinterpret_cast<ushort4*>(op + 8192) = hi;
    *reinterpret_cast<ushort4*>(op + 16384) = lo;
}

__global__ __launch_bounds__(256) void ltc_combine_k(
    const float* __restrict__ t, int nz, ll zstride,
    const float* __restrict__ tb, const float* __restrict__ gb,
    const float* __restrict__ ib, const float* __restrict__ hb,
    float* __restrict__ out)
{
    const int i = blockIdx.x * 256 + threadIdx.x;
    const int r = i >> 8;
    const int n = i & (LTCN - 1);
    float tv = 0.f, gv = 0.f, iv = 0.f;
    for (int z = 0; z < nz; z++) {
        const float* base = t + (ll)z * zstride + (ll)r * 768;
        tv += base[n]; gv += base[256 + n]; iv += base[512 + n];
    }
    const float tau = 0.1f + 9.9f / (1.f + expf(-(tv + tb[n])));
    const float gt  = 1.f / (1.f + expf(-(gv + gb[n])));
    const float ic  = tanhf(iv + ib[n]);
    const float hc  = tanhf(hb[n]);
    const float target = gt * ic + (1.f - gt) * hc;
    out[i] = tanhf(target / (tau + 1e-8f));
}

// ======================= launcher =======================
static inline float* SYMF(const void* s) { void* p; cudaGetSymbolAddress(&p, s); return (float*)p; }
static inline __nv_bfloat16* SYMB(const void* s) { void* p; cudaGetSymbolAddress(&p, s); return (__nv_bfloat16*)p; }

extern "C" void kernel_launch(void* const* d_in, const int* in_sizes, int n_in,
                              void* d_out, int out_size)
{
    (void)in_sizes; (void)n_in; (void)out_size;
    const float* x     = (const float*)d_in[0];
    const float* anw   = (const float*)d_in[1];
    const float* fnw   = (const float*)d_in[2];
    const float* qw    = (const float*)d_in[3];
    const float* kw    = (const float*)d_in[4];
    const float* vw    = (const float*)d_in[5];
    const float* ow    = (const float*)d_in[6];
    const float* gatew = (const float*)d_in[7];
    const float* upw   = (const float*)d_in[8];
    const float* downw = (const float*)d_in[9];
    const float* projw = (const float*)d_in[10];
    const float* c0tw  = (const float*)d_in[11];
    const float* c0tb  = (const float*)d_in[12];
    const float* c0gw  = (const float*)d_in[13];
    const float* c0gb  = (const float*)d_in[14];
    const float* c0iw  = (const float*)d_in[15];
    const float* c0ib  = (const float*)d_in[16];
    const float* c0hb  = (const float*)d_in[18];
    const float* c1tw  = (const float*)d_in[19];
    const float* c1tb  = (const float*)d_in[20];
    const float* c1gw  = (const float*)d_in[21];
    const float* c1gb  = (const float*)d_in[22];
    const float* c1iw  = (const float*)d_in[23];
    const float* c1ib  = (const float*)d_in[24];
    const float* c1hb  = (const float*)d_in[26];
    float* out = (float*)d_out;

    float* qkv   = SYMF(g_qkv);   float* sc    = SYMF(g_scores);
    float* attn  = SYMF(g_attn);  float* h     = SYMF(g_h);
    float* gu    = SYMF(g_gu);    float* up    = SYMF(g_up);
    float* inter = SYMF(g_inter); float* part  = SYMF(g_part);
    float* l0    = SYMF(g_l0);    float* l1    = SYMF(g_l1);

    __nv_bfloat16* Pxn  = SYMB(p_xn);    __nv_bfloat16* Pqkv = SYMB(p_qkvw);
    __nv_bfloat16* Pow  = SYMB(p_ow);    __nv_bfloat16* Pgu  = SYMB(p_guw);
    __nv_bfloat16* Pdw  = SYMB(p_dw);    __nv_bfloat16* Ppw  = SYMB(p_pw);
    __nv_bfloat16* Pc0  = SYMB(p_c0w);   __nv_bfloat16* Pc1  = SYMB(p_c1w);
    __nv_bfloat16* Pq   = SYMB(p_q);     __nv_bfloat16* Pk   = SYMB(p_k);
    __nv_bfloat16* Ppr  = SYMB(p_probs); __nv_bfloat16* Pvt  = SYMB(p_vt);
    __nv_bfloat16* Pat  = SYMB(p_attn);  __nv_bfloat16* Pin  = SYMB(p_inter);
    __nv_bfloat16* Pl0  = SYMB(p_l0);    __nv_bfloat16* Pl1  = SYMB(p_l1);

    const int SMEM3 = 3 * 30720;
    cudaFuncSetAttribute((const void*)hgemm256<false>, cudaFuncAttributeMaxDynamicSharedMemorySize, SMEM3);
    cudaFuncSetAttribute((const void*)hgemm256<true>,  cudaFuncAttributeMaxDynamicSharedMemorySize, SMEM3);

    const dim3 t32x8(32, 8);
    const float att_scale = 0.08838834764831845f;

    // ---- pack weights ----
    splitT_k<<<dim3(64, 64), t32x8>>>(qw, 2048, 0, Pqkv, 0, 2048, 1);
    splitT_k<<<dim3(64, 64), t32x8>>>(kw, 2048, 0, Pqkv + 2048LL * 6144, 0, 2048, 1);
    splitT_k<<<dim3(64, 64), t32x8>>>(vw, 2048, 0, Pqkv + 4096LL * 6144, 0, 2048, 1);
    splitT_k<<<dim3(64, 64), t32x8>>>(ow, 2048, 0, Pow, 0, 2048, 1);
    splitT_k<<<dim3(64, 256), t32x8>>>(gatew, 8192, 0, Pgu, 0, 2048, 1);
    splitT_k<<<dim3(64, 256), t32x8>>>(upw, 8192, 0, Pgu + 8192LL * 6144, 0, 2048, 1);
    splitT_k<<<dim3(256, 64), t32x8>>>(downw, 2048, 0, Pdw, 0, 8192, 1);
    splitT_k<<<dim3(8, 256), t32x8>>>(projw, 8192, 0, Ppw, 0, 256, 1);
    // c0 packs: source K = 8192 -> grid.x = 256 (grid.x=768 was the R4 bug)
    splitT_k<<<dim3(256, 8), t32x8>>>(c0tw, 256, 0, Pc0, 0, 8192, 1);
    splitT_k<<<dim3(256, 8), t32x8>>>(c0gw, 256, 0, Pc0 + 256LL * 24576, 0, 8192, 1);
    splitT_k<<<dim3(256, 8), t32x8>>>(c0iw, 256, 0, Pc0 + 512LL * 24576, 0, 8192, 1);
    splitT_k<<<dim3(8, 8), t32x8>>>(c1tw, 256, 0, Pc1, 0, 256, 1);
    splitT_k<<<dim3(8, 8), t32x8>>>(c1gw, 256, 0, Pc1 + 256LL * 768, 0, 256, 1);
    splitT_k<<<dim3(8, 8), t32x8>>>(c1iw, 256, 0, Pc1 + 512LL * 768, 0, 256, 1);

    // ---- attention ----
    rmsnorm_pack_k<<<SEQL, 256>>>(x, anw, Pxn);
    hgemm256<false><<<dim3(24, 16), 256, SMEM3>>>(Pxn, 6144, 0, Pqkv, 6144, 0, qkv, 6144, 0, nullptr, 0, 0, 6144, 1.f);
    spike_rope_k<<<SEQL * NHEADS * 64 / 256, 256>>>(qkv, 6144, 1);
    spike_rope_k<<<SEQL * NHEADS * 64 / 256, 256>>>(qkv + 2048, 6144, 1);
    spike_rope_k<<<SEQL * NHEADS * 64 / 256, 256>>>(qkv + 4096, 6144, 0);
    split_k<<<dim3(256, 1, 16), 256>>>(qkv, 128, 6144, Pq, 2048LL * 384, 128, 0);
    split_k<<<dim3(256, 1, 16), 256>>>(qkv + 2048, 128, 6144, Pk, 2048LL * 384, 128, 1);
    splitT_k<<<dim3(64, 4, 16), t32x8>>>(qkv + 4096, 6144, 128, Pvt, 128LL * 4096, 2048, 3);
    hgemm256<true><<<dim3(8, 16, 16), 256, SMEM3>>>(
        Pq, 384, 2048LL * 384, Pk, 384, 2048LL * 384,
        sc, 2048, (ll)SEQL * SEQL, nullptr, 0, 0, 384, att_scale);
    softmax_pack_k<<<dim3(SEQL, NHEADS), 256>>>(sc, Ppr);
    hgemm<<<dim3(1, 16, 16), 256>>>(
        Ppr, 4096, 2048LL * 4096, Pvt, 4096, 128LL * 4096,
        attn, 2048, 128, 4096, 1.f);
    split_k<<<2048 * 2048 / 1024, 256>>>(attn, 0, 2048, Pat, 0, 2048, 0);
    hgemm256<false><<<dim3(8, 16), 256, SMEM3>>>(Pat, 6144, 0, Pow, 6144, 0, h, 2048, 0, x, 2048, 0, 6144, 1.f);

    // ---- LTC feed-forward ----
    rmsnorm_pack_k<<<SEQL, 256>>>(h, fnw, Pxn);
    hgemm256<false><<<dim3(64, 16), 256, SMEM3>>>(Pxn, 6144, 0, Pgu, 6144, 0, gu, 16384, 0, nullptr, 0, 0, 6144, 1.f);
    silu_mul_pack_k<<<2048 * 8192 / 1024, 256>>>(gu, inter, Pin);
    // cell 0: split-K x8, N=768 combined
    hgemm256<false><<<dim3(3, 16, 8), 256, SMEM3>>>(
        Pin, 24576, 3072, Pc0, 24576, 3072,
        part, 768, 2048LL * 768, nullptr, 0, 0, 3072, 1.f);
    ltc_combine_k<<<2048, 256>>>(part, 8, 2048LL * 768, c0tb, c0gb, c0ib, c0hb, l0);
    split_k<<<2048 * 256 / 1024, 256>>>(l0, 0, 256, Pl0, 0, 256, 0);
    // cell 1
    hgemm256<false><<<dim3(3, 16), 256, SMEM3>>>(
        Pl0, 768, 0, Pc1, 768, 0, part, 768, 0, nullptr, 0, 0, 768, 1.f);
    ltc_combine_k<<<2048, 256>>>(part, 1, 0, c1tb, c1gb, c1ib, c1hb, l1);
    split_k<<<2048 * 256 / 1024, 256>>>(l1, 0, 256, Pl1, 0, 256, 0);
    // enhanced = inter + l1 @ proj
    hgemm256<false><<<dim3(32, 16), 256, SMEM3>>>(Pl1, 768, 0, Ppw, 768, 0, up, 8192, 0, inter, 8192, 0, 768, 1.f);
    split_k<<<2048 * 8192 / 1024, 256>>>(up, 0, 8192, Pin, 0, 8192, 0);
    // out = h + enhanced @ down_w
    hgemm256<false><<<dim3(8, 16), 256, SMEM3>>>(Pin, 24576, 0, Pdw, 24576, 0, out, 2048, 0, h, 2048, 0, 24576, 1.f);
}

// round 7
// speedup vs baseline: 4.9793x; 1.6734x over previous
#include <cuda_runtime.h>
#include <cuda_bf16.h>
#include <cuda_fp16.h>
#include <math.h>
#include <stdint.h>

#define SEQL 2048
#define DIMN 2048
#define NHEADS 16
#define HDIM 128
#define HIDDEN 8192
#define LTCN 256
#define RMS_EPS 1.1920929e-07f
typedef long long ll;

// ======================= fp32 scratch =======================
__align__(256) __device__ float g_qkv[2048LL * 6144];
__align__(256) __device__ float g_scores[(ll)NHEADS * SEQL * SEQL];
__align__(256) __device__ float g_attn[SEQL * DIMN];
__align__(256) __device__ float g_h[SEQL * DIMN];
__align__(256) __device__ float g_gu[2048LL * 16384];
__align__(256) __device__ float g_up[SEQL * HIDDEN];
__align__(256) __device__ float g_inter[SEQL * HIDDEN];
__align__(256) __device__ float g_part[8LL * 2048 * 768];
__align__(256) __device__ float g_l0[SEQL * LTCN];
__align__(256) __device__ float g_l1[SEQL * LTCN];

// ======================= packed bf16 operands (attention + c1, 3-term) ==========
__align__(256) __device__ __nv_bfloat16 p_xn[2048LL * 6144];
__align__(256) __device__ __nv_bfloat16 p_qkvw[6144LL * 6144];
__align__(256) __device__ __nv_bfloat16 p_ow[2048LL * 6144];
__align__(256) __device__ __nv_bfloat16 p_c1w[768LL * 768];
__align__(256) __device__ __nv_bfloat16 p_q[16LL * 2048 * 384];
__align__(256) __device__ __nv_bfloat16 p_k[16LL * 2048 * 384];
__align__(256) __device__ __nv_bfloat16 p_probs[16LL * 2048 * 4096];
__align__(256) __device__ __nv_bfloat16 p_vt[16LL * 128 * 4096];
__align__(256) __device__ __nv_bfloat16 p_attn[2048LL * 6144];
__align__(256) __device__ __nv_bfloat16 p_l0[2048LL * 768];

// ======================= packed fp16 operands (FFN, 1-term) =======================
__align__(256) __device__ __half h_xn[2048LL * 2048];
__align__(256) __device__ __half h_guw[16384LL * 2048];
__align__(256) __device__ __half h_dw[2048LL * 8192];
__align__(256) __device__ __half h_pw[8192LL * 256];
__align__(256) __device__ __half h_c0w[768LL * 8192];
__align__(256) __device__ __half h_in[2048LL * 8192];
__align__(256) __device__ __half h_l1[2048LL * 256];
__align__(256) __device__ __half h_en[2048LL * 8192];

// ======================= helpers =======================
__device__ __forceinline__ uint32_t smem_u32(const void* p) {
    uint32_t a;
    asm("{ .reg .u64 t; cvta.to.shared.u64 t, %1; cvt.u32.u64 %0, t; }" : "=r"(a) : "l"(p));
    return a;
}
__device__ __forceinline__ void cp16(uint32_t dst, const void* src) {
    asm volatile("cp.async.cg.shared.global [%0], [%1], 16;" :: "r"(dst), "l"(src));
}
#define CP_COMMIT()  asm volatile("cp.async.commit_group;" ::: "memory")
#define CP_WAIT1()   asm volatile("cp.async.wait_group 1;" ::: "memory")
#define CP_WAIT2()   asm volatile("cp.async.wait_group 2;" ::: "memory")

__device__ __forceinline__ void ldmx4(uint32_t* r, uint32_t addr) {
    asm volatile("ldmatrix.sync.aligned.m8n8.x4.shared.b16 {%0,%1,%2,%3}, [%4];"
                 : "=r"(r[0]), "=r"(r[1]), "=r"(r[2]), "=r"(r[3]) : "r"(addr));
}
__device__ __forceinline__ void mma16816(float* d, const uint32_t* a, uint32_t b0, uint32_t b1) {
    asm volatile(
        "mma.sync.aligned.m16n8k16.row.col.f32.bf16.bf16.f32 "
        "{%0,%1,%2,%3}, {%4,%5,%6,%7}, {%8,%9}, {%0,%1,%2,%3};"
        : "+f"(d[0]), "+f"(d[1]), "+f"(d[2]), "+f"(d[3])
        : "r"(a[0]), "r"(a[1]), "r"(a[2]), "r"(a[3]), "r"(b0), "r"(b1));
}
__device__ __forceinline__ void mma16816h(float* d, const uint32_t* a, uint32_t b0, uint32_t b1) {
    asm volatile(
        "mma.sync.aligned.m16n8k16.row.col.f32.f16.f16.f32 "
        "{%0,%1,%2,%3}, {%4,%5,%6,%7}, {%8,%9}, {%0,%1,%2,%3};"
        : "+f"(d[0]), "+f"(d[1]), "+f"(d[2]), "+f"(d[3])
        : "r"(a[0]), "r"(a[1]), "r"(a[2]), "r"(a[3]), "r"(b0), "r"(b1));
}

#define PITCH 80

// ======================= HMMA GEMM 128x256, 3-stage =======================
// C[M][N] = alpha * A[M][Kp] x B[N][Kp]^T (+ Dadd). A,B K-major 16-bit (bf16 or fp16).
template <bool CAUSAL, bool F16>
__global__ __launch_bounds__(256, 1) void hgemm256(
    const __nv_bfloat16* __restrict__ A, int lda, ll sA,
    const __nv_bfloat16* __restrict__ B, int ldb, ll sB,
    float* __restrict__ C, int ldc, ll sC,
    const float* __restrict__ Dadd, int ldd, ll sD,
    int Kp, float alpha)
{
    const int bm = blockIdx.y * 128;
    const int bn = blockIdx.x * 256;
    if (CAUSAL && bn > bm + 127) return;

    const int z = blockIdx.z;
    A += (ll)z * sA;
    B += (ll)z * sB;
    C += (ll)z * sC;
    if (Dadd) Dadd += (ll)z * sD;

    extern __shared__ char smem[];
    const uint32_t sb = smem_u32(smem);
    const int tid = threadIdx.x;
    const int lane = tid & 31;
    const int wid = tid >> 5;
    const int wm = wid & 1;
    const int wn = wid >> 1;

    float acc[4][8][4];
#pragma unroll
    for (int i = 0; i < 4; i++)
#pragma unroll
        for (int j = 0; j < 8; j++)
#pragma unroll
            for (int t = 0; t < 4; t++) acc[i][j][t] = 0.f;

    const int nK = Kp >> 5;

    auto load_stage = [&](int s, int b) {
        const uint32_t Ad = sb + b * 30720;
        const char* Ag = (const char*)A + (ll)s * 64;
#pragma unroll
        for (int j = 0; j < 2; j++) {
            int q = tid + j * 256;
            int r = q >> 2, c = q & 3;
            cp16(Ad + r * PITCH + c * 16, Ag + (ll)(bm + r) * lda * 2 + c * 16);
        }
        const uint32_t Bd = Ad + 10240;
        const char* Bg = (const char*)B + (ll)s * 64;
#pragma unroll
        for (int j = 0; j < 4; j++) {
            int q = tid + j * 256;
            int r = q >> 2, c = q & 3;
            cp16(Bd + r * PITCH + c * 16, Bg + (ll)(bn + r) * ldb * 2 + c * 16);
        }
    };

    load_stage(0, 0); CP_COMMIT();
    if (nK > 1) load_stage(1, 1);
    CP_COMMIT();
    if (nK > 2) load_stage(2, 2);
    CP_COMMIT();

    int buf = 0;
    for (int i = 0; i < nK; i++) {
        CP_WAIT2();
        __syncthreads();
        const uint32_t Ab = sb + buf * 30720;
        const uint32_t Bb = Ab + 10240;
#pragma unroll
        for (int ks = 0; ks < 2; ks++) {
            uint32_t a[4][4];
#pragma unroll
            for (int mt = 0; mt < 4; mt++) {
                const int row = wm * 64 + mt * 16 + (lane & 15);
                ldmx4(a[mt], Ab + row * PITCH + (ks * 2 + (lane >> 4)) * 16);
            }
            uint32_t bf[4][4];
#pragma unroll
            for (int p = 0; p < 4; p++) {
                const int nrow = wn * 64 + p * 16 + ((lane >> 4) << 3) + (lane & 7);
                ldmx4(bf[p], Bb + nrow * PITCH + (ks * 2 + ((lane >> 3) & 1)) * 16);
            }
#pragma unroll
            for (int mt = 0; mt < 4; mt++)
#pragma unroll
                for (int j = 0; j < 8; j++) {
                    if (F16) mma16816h(acc[mt][j], a[mt], bf[j >> 1][(j & 1) * 2], bf[j >> 1][(j & 1) * 2 + 1]);
                    else     mma16816(acc[mt][j], a[mt], bf[j >> 1][(j & 1) * 2], bf[j >> 1][(j & 1) * 2 + 1]);
                }
        }
        __syncthreads();
        if (i + 3 < nK) load_stage(i + 3, buf);
        CP_COMMIT();
        buf = (buf == 2) ? 0 : buf + 1;
    }

    const int r0 = lane >> 2;
    const int c0 = (lane & 3) * 2;
#pragma unroll
    for (int mt = 0; mt < 4; mt++) {
#pragma unroll
        for (int j = 0; j < 8; j++) {
            const int col = bn + wn * 64 + j * 8 + c0;
            const ll row0 = bm + wm * 64 + mt * 16 + r0;
            const ll row1 = row0 + 8;
            float2 v0 = {alpha * acc[mt][j][0], alpha * acc[mt][j][1]};
            float2 v1 = {alpha * acc[mt][j][2], alpha * acc[mt][j][3]};
            if (Dadd) {
                float2 d0 = *reinterpret_cast<const float2*>(Dadd + row0 * ldd + col);
                float2 d1 = *reinterpret_cast<const float2*>(Dadd + row1 * ldd + col);
                v0.x += d0.x; v0.y += d0.y; v1.x += d1.x; v1.y += d1.y;
            }
            *reinterpret_cast<float2*>(C + row0 * ldc + col) = v0;
            *reinterpret_cast<float2*>(C + row1 * ldc + col) = v1;
        }
    }
}

// ======================= HMMA GEMM 128x128, 2-stage (for AV) =======================
__global__ __launch_bounds__(256) void hgemm(
    const __nv_bfloat16* __restrict__ A, int lda, ll sA,
    const __nv_bfloat16* __restrict__ B, int ldb, ll sB,
    float* __restrict__ C, int ldc, ll sC,
    int Kp, float alpha)
{
    const int bm = blockIdx.y * 128;
    const int bn = blockIdx.x * 128;
    const int z = blockIdx.z;
    A += (ll)z * sA;
    B += (ll)z * sB;
    C += (ll)z * sC;

    __shared__ char smem[4 * 128 * PITCH];
    const uint32_t sb = smem_u32(smem);
    const uint32_t Abase[2] = {sb, sb + 128 * PITCH};
    const uint32_t Bbase[2] = {sb + 2 * 128 * PITCH, sb + 3 * 128 * PITCH};

    const int tid = threadIdx.x;
    const int lane = tid & 31;
    const int wid = tid >> 5;
    const int wm = wid & 3;
    const int wn = wid >> 2;

    float acc[2][8][4];
#pragma unroll
    for (int i = 0; i < 2; i++)
#pragma unroll
        for (int j = 0; j < 8; j++)
#pragma unroll
            for (int t = 0; t < 4; t++) acc[i][j][t] = 0.f;

    const int nK = Kp >> 5;

    auto load_stage = [&](int s, int b) {
        const char* Ag = (const char*)A + (ll)s * 64;
#pragma unroll
        for (int j = 0; j < 2; j++) {
            int q = tid + j * 256;
            int r = q >> 2, c = q & 3;
            cp16(Abase[b] + r * PITCH + c * 16, Ag + (ll)(bm + r) * lda * 2 + c * 16);
        }
        const char* Bg = (const char*)B + (ll)s * 64;
#pragma unroll
        for (int j = 0; j < 2; j++) {
            int q = tid + j * 256;
            int r = q >> 2, c = q & 3;
            cp16(Bbase[b] + r * PITCH + c * 16, Bg + (ll)(bn + r) * ldb * 2 + c * 16);
        }
    };

    load_stage(0, 0); CP_COMMIT();
    if (nK > 1) load_stage(1, 1);
    CP_COMMIT();

    for (int i = 0; i < nK; i++) {
        const int buf = i & 1;
        CP_WAIT1();
        __syncthreads();
        const uint32_t Ab = Abase[buf], Bb = Bbase[buf];
#pragma unroll
        for (int ks = 0; ks < 2; ks++) {
            uint32_t a[2][4];
#pragma unroll
            for (int mt = 0; mt < 2; mt++) {
                const int row = wm * 32 + mt * 16 + (lane & 15);
                ldmx4(a[mt], Ab + row * PITCH + (ks * 2 + (lane >> 4)) * 16);
            }
            uint32_t bf[4][4];
#pragma unroll
            for (int p = 0; p < 4; p++) {
                const int nrow = wn * 64 + p * 16 + ((lane >> 4) << 3) + (lane & 7);
                ldmx4(bf[p], Bb + nrow * PITCH + (ks * 2 + ((lane >> 3) & 1)) * 16);
            }
#pragma unroll
            for (int mt = 0; mt < 2; mt++)
#pragma unroll
                for (int j = 0; j < 8; j++)
                    mma16816(acc[mt][j], a[mt], bf[j >> 1][(j & 1) * 2], bf[j >> 1][(j & 1) * 2 + 1]);
        }
        __syncthreads();
        if (i + 2 < nK) load_stage(i + 2, buf);
        CP_COMMIT();
    }

    const int r0 = lane >> 2;
    const int c0 = (lane & 3) * 2;
#pragma unroll
    for (int mt = 0; mt < 2; mt++) {
#pragma unroll
        for (int j = 0; j < 8; j++) {
            const int col = bn + wn * 64 + j * 8 + c0;
            const ll row0 = bm + wm * 32 + mt * 16 + r0;
            const ll row1 = row0 + 8;
            float2 v0 = {alpha * acc[mt][j][0], alpha * acc[mt][j][1]};
            float2 v1 = {alpha * acc[mt][j][2], alpha * acc[mt][j][3]};
            *reinterpret_cast<float2*>(C + row0 * ldc + col) = v0;
            *reinterpret_cast<float2*>(C + row1 * ldc + col) = v1;
        }
    }
}

// ======================= split helpers =======================
__device__ __forceinline__ void split2f(float x, unsigned short& h, unsigned short& l) {
    __nv_bfloat16 hb = __float2bfloat16_rn(x);
    __nv_bfloat16 lb = __float2bfloat16_rn(x - __bfloat162float(hb));
    h = __bfloat16_as_ushort(hb);
    l = __bfloat16_as_ushort(lb);
}

// mode 0: [hi|hi|lo]   mode 1: [hi|lo|hi]   mode 2: [hi|lo]   mode 3: [x|x]
__global__ __launch_bounds__(256) void split_k(
    const float* __restrict__ in, ll inZ, int ldin,
    __nv_bfloat16* __restrict__ out, ll outZ, int C, int mode)
{
    const ll idx = (ll)blockIdx.x * 256 + threadIdx.x;
    const int c4n = C >> 2;
    const ll r = idx / c4n;
    const int c = (int)(idx % c4n) * 4;
    const float4 v = *reinterpret_cast<const float4*>(in + (ll)blockIdx.z * inZ + r * ldin + c);
    ushort4 hi, lo;
    split2f(v.x, hi.x, lo.x); split2f(v.y, hi.y, lo.y);
    split2f(v.z, hi.z, lo.z); split2f(v.w, hi.w, lo.w);
    const int terms = (mode < 2) ? 3 : 2;
    __nv_bfloat16* op = out + (ll)blockIdx.z * outZ + r * ((ll)terms * C) + c;
    ushort4* s0 = reinterpret_cast<ushort4*>(op);
    ushort4* s1 = reinterpret_cast<ushort4*>(op + C);
    ushort4* s2 = reinterpret_cast<ushort4*>(op + 2 * C);
    if (mode == 0)      { *s0 = hi; *s1 = hi; *s2 = lo; }
    else if (mode == 1) { *s0 = hi; *s1 = lo; *s2 = hi; }
    else if (mode == 2) { *s0 = hi; *s1 = lo; }
    else                { *s0 = hi; *s1 = hi; }
}

// transpose+split (bf16 3/2-term modes, as before)
__global__ void splitT_k(
    const float* __restrict__ in, int ldin, ll inZcols,
    __nv_bfloat16* __restrict__ out, ll outZ, int K, int mode)
{
    __shared__ float t[32][33];
    const int k0 = blockIdx.x * 32, n0 = blockIdx.y * 32;
    const int tx = threadIdx.x, ty = threadIdx.y;
    const float* ip = in + (ll)blockIdx.z * inZcols;
#pragma unroll
    for (int j = 0; j < 4; j++)
        t[ty + j * 8][tx] = ip[(ll)(k0 + ty + j * 8) * ldin + n0 + tx];
    __syncthreads();
    const int terms = (mode < 2) ? 3 : 2;
    __nv_bfloat16* op = out + (ll)blockIdx.z * outZ;
#pragma unroll
    for (int j = 0; j < 4; j++) {
        const int n = n0 + ty + j * 8, k = k0 + tx;
        const float x = t[tx][ty + j * 8];
        unsigned short h, l;
        split2f(x, h, l);
        __nv_bfloat16* base = op + (ll)n * ((ll)terms * K) + k;
        const __nv_bfloat16 hb = __ushort_as_bfloat16(h), lb = __ushort_as_bfloat16(l);
        if (mode == 0)      { base[0] = hb; base[K] = hb; base[2 * K] = lb; }
        else if (mode == 1) { base[0] = hb; base[K] = lb; base[2 * K] = hb; }
        else if (mode == 2) { base[0] = hb; base[K] = lb; }
        else                { base[0] = hb; base[K] = hb; }
    }
}

// transpose to fp16 1-term: out[n][k] = fp16(in[k][n])
__global__ void splitT_h16_k(
    const float* __restrict__ in, int ldin, __half* __restrict__ out, int K)
{
    __shared__ float t[32][33];
    const int k0 = blockIdx.x * 32, n0 = blockIdx.y * 32;
    const int tx = threadIdx.x, ty = threadIdx.y;
#pragma unroll
    for (int j = 0; j < 4; j++)
        t[ty + j * 8][tx] = in[(ll)(k0 + ty + j * 8) * ldin + n0 + tx];
    __syncthreads();
#pragma unroll
    for (int j = 0; j < 4; j++) {
        const int n = n0 + ty + j * 8, k = k0 + tx;
        out[(ll)n * K + k] = __float2half_rn(t[tx][ty + j * 8]);
    }
}

// fp32 -> fp16 elementwise pack
__global__ __launch_bounds__(256) void pack_h16_k(
    const float* __restrict__ in, __half* __restrict__ out)
{
    const ll i = ((ll)blockIdx.x * 256 + threadIdx.x) * 4;
    const float4 v = *reinterpret_cast<const float4*>(in + i);
    __half2 a = __floats2half2_rn(v.x, v.y);
    __half2 b = __floats2half2_rn(v.z, v.w);
    *reinterpret_cast<__half2*>(out + i) = a;
    *reinterpret_cast<__half2*>(out + i + 2) = b;
}

// ======================= fused elementwise kernels =======================
__global__ __launch_bounds__(256) void rmsnorm_pack_k(
    const float* __restrict__ x, const float* __restrict__ w, __nv_bfloat16* __restrict__ out)
{
    const int r = blockIdx.x, tid = threadIdx.x;
    const float* xr = x + (ll)r * DIMN;
    float ss = 0.f;
    for (int i = tid; i < DIMN; i += 256) { float v = xr[i]; ss += v * v; }
    __shared__ float red[256];
    red[tid] = ss; __syncthreads();
    for (int s = 128; s > 0; s >>= 1) { if (tid < s) red[tid] += red[tid + s]; __syncthreads(); }
    const float scale = rsqrtf(red[0] * (1.0f / DIMN) + RMS_EPS);
    __nv_bfloat16* orow = out + (ll)r * 6144;
    for (int i = tid; i < DIMN; i += 256) {
        const float v = xr[i] * scale * w[i];
        unsigned short h, l;
        split2f(v, h, l);
        orow[i] = __ushort_as_bfloat16(h);
        orow[2048 + i] = __ushort_as_bfloat16(h);
        orow[4096 + i] = __ushort_as_bfloat16(l);
    }
}

// rmsnorm -> fp16 1-term (row stride 2048)
__global__ __launch_bounds__(256) void rmsnorm_h16_k(
    const float* __restrict__ x, const float* __restrict__ w, __half* __restrict__ out)
{
    const int r = blockIdx.x, tid = threadIdx.x;
    const float* xr = x + (ll)r * DIMN;
    float ss = 0.f;
    for (int i = tid; i < DIMN; i += 256) { float v = xr[i]; ss += v * v; }
    __shared__ float red[256];
    red[tid] = ss; __syncthreads();
    for (int s = 128; s > 0; s >>= 1) { if (tid < s) red[tid] += red[tid + s]; __syncthreads(); }
    const float scale = rsqrtf(red[0] * (1.0f / DIMN) + RMS_EPS);
    __half* orow = out + (ll)r * DIMN;
    for (int i = tid; i < DIMN; i += 256)
        orow[i] = __float2half_rn(xr[i] * scale * w[i]);
}

__global__ __launch_bounds__(256) void spike_rope_k(float* __restrict__ q, int stride, int do_rope)
{
    const int idx = blockIdx.x * 256 + threadIdx.x;
    const int d = idx & 63;
    const int h = (idx >> 6) & (NHEADS - 1);
    const int s = idx >> 10;
    const ll base = (ll)s * stride + h * HDIM;
    const float a = q[base + d];
    const float b = q[base + d + 64];
    const float sa = a > 1.0f ? 1.f : 0.f;
    const float sb = b > 1.0f ? 1.f : 0.f;
    if (do_rope) {
        const float invf = powf(10000.0f, -(float)d * (1.0f / 64.0f));
        const float fr = (float)s * invf;
        double sd, cd;
        sincos((double)fr, &sd, &cd);
        const float c = (float)cd, si = (float)sd;
        q[base + d]      = sa * c - sb * si;
        q[base + d + 64] = sb * c + sa * si;
    } else {
        q[base + d] = sa;
        q[base + d + 64] = sb;
    }
}

__global__ __launch_bounds__(256) void softmax_pack_k(
    const float* __restrict__ sc, __nv_bfloat16* __restrict__ pr)
{
    const int q = blockIdx.x, h = blockIdx.y, tid = threadIdx.x;
    const float* row = sc + ((ll)h * SEQL + q) * SEQL;
    __nv_bfloat16* orow = pr + (ll)h * SEQL * 4096 + (ll)q * 4096;
    const int n = q + 1;
    __shared__ float red[256];
    float m = -1e30f;
    for (int i = tid; i < n; i += 256) m = fmaxf(m, row[i]);
    red[tid] = m; __syncthreads();
    for (int s = 128; s > 0; s >>= 1) { if (tid < s) red[tid] = fmaxf(red[tid], red[tid + s]); __syncthreads(); }
    m = red[0]; __syncthreads();
    float sum = 0.f;
    for (int i = tid; i < n; i += 256) sum += expf(row[i] - m);
    red[tid] = sum; __syncthreads();
    for (int s = 128; s > 0; s >>= 1) { if (tid < s) red[tid] += red[tid + s]; __syncthreads(); }
    const float inv = 1.0f / red[0];
    const __nv_bfloat16 z = __float2bfloat16_rn(0.f);
    for (int i = tid; i < n; i += 256) {
        const float p = expf(row[i] - m) * inv;
        unsigned short hb, lb;
        split2f(p, hb, lb);
        orow[i] = __ushort_as_bfloat16(hb);
        orow[2048 + i] = __ushort_as_bfloat16(lb);
    }
    for (int i = n + tid; i < SEQL; i += 256) { orow[i] = z; orow[2048 + i] = z; }
}

// silu(gate)*up; writes inter fp32 + fp16 1-term pack
__global__ __launch_bounds__(256) void silu_mul_pack_k(
    const float* __restrict__ gu, float* __restrict__ inter, __half* __restrict__ pin)
{
    const ll idx = (ll)blockIdx.x * 256 + threadIdx.x;
    const ll r = idx / 2048;
    const int c = (int)(idx % 2048) * 4;
    const float4 g = *reinterpret_cast<const float4*>(gu + r * 16384 + c);
    const float4 u = *reinterpret_cast<const float4*>(gu + r * 16384 + 8192 + c);
    float4 v;
    v.x = (g.x / (1.f + expf(-g.x))) * u.x;
    v.y = (g.y / (1.f + expf(-g.y))) * u.y;
    v.z = (g.z / (1.f + expf(-g.z))) * u.z;
    v.w = (g.w / (1.f + expf(-g.w))) * u.w;
    *reinterpret_cast<float4*>(inter + r * 8192 + c) = v;
    __half* op = pin + r * 8192 + c;
    *reinterpret_cast<__half2*>(op) = __floats2half2_rn(v.x, v.y);
    *reinterpret_cast<__half2*>(op + 2) = __floats2half2_rn(v.z, v.w);
}

__global__ __launch_bounds__(256) void ltc_combine_k(
    const float* __restrict__ t, int nz, ll zstride,
    const float* __restrict__ tb, const float* __restrict__ gb,
    const float* __restrict__ ib, const float* __restrict__ hb,
    float* __restrict__ out)
{
    const int i = blockIdx.x * 256 + threadIdx.x;
    const int r = i >> 8;
    const int n = i & (LTCN - 1);
    float tv = 0.f, gv = 0.f, iv = 0.f;
    for (int z = 0; z < nz; z++) {
        const float* base = t + (ll)z * zstride + (ll)r * 768;
        tv += base[n]; gv += base[256 + n]; iv += base[512 + n];
    }
    const float tau = 0.1f + 9.9f / (1.f + expf(-(tv + tb[n])));
    const float gt  = 1.f / (1.f + expf(-(gv + gb[n])));
    const float ic  = tanhf(iv + ib[n]);
    const float hc  = tanhf(hb[n]);
    const float target = gt * ic + (1.f - gt) * hc;
    out[i] = tanhf(target / (tau + 1e-8f));
}

// ======================= launcher =======================
static inline float* SYMF(const void* s) { void* p; cudaGetSymbolAddress(&p, s); return (float*)p; }
static inline __nv_bfloat16* SYMB(const void* s) { void* p; cudaGetSymbolAddress(&p, s); return (__nv_bfloat16*)p; }
static inline __half* SYMH(const void* s) { void* p; cudaGetSymbolAddress(&p, s); return (__half*)p; }

extern "C" void kernel_launch(void* const* d_in, const int* in_sizes, int n_in,
                              void* d_out, int out_size)
{
    (void)in_sizes; (void)n_in; (void)out_size;
    const float* x     = (const float*)d_in[0];
    const float* anw   = (const float*)d_in[1];
    const float* fnw   = (const float*)d_in[2];
    const float* qw    = (const float*)d_in[3];
    const float* kw    = (const float*)d_in[4];
    const float* vw    = (const float*)d_in[5];
    const float* ow    = (const float*)d_in[6];
    const float* gatew = (const float*)d_in[7];
    const float* upw   = (const float*)d_in[8];
    const float* downw = (const float*)d_in[9];
    const float* projw = (const float*)d_in[10];
    const float* c0tw  = (const float*)d_in[11];
    const float* c0tb  = (const float*)d_in[12];
    const float* c0gw  = (const float*)d_in[13];
    const float* c0gb  = (const float*)d_in[14];
    const float* c0iw  = (const float*)d_in[15];
    const float* c0ib  = (const float*)d_in[16];
    const float* c0hb  = (const float*)d_in[18];
    const float* c1tw  = (const float*)d_in[19];
    const float* c1tb  = (const float*)d_in[20];
    const float* c1gw  = (const float*)d_in[21];
    const float* c1gb  = (const float*)d_in[22];
    const float* c1iw  = (const float*)d_in[23];
    const float* c1ib  = (const float*)d_in[24];
    const float* c1hb  = (const float*)d_in[26];
    float* out = (float*)d_out;

    float* qkv   = SYMF(g_qkv);   float* sc    = SYMF(g_scores);
    float* attn  = SYMF(g_attn);  float* h     = SYMF(g_h);
    float* gu    = SYMF(g_gu);    float* up    = SYMF(g_up);
    float* inter = SYMF(g_inter); float* part  = SYMF(g_part);
    float* l0    = SYMF(g_l0);    float* l1    = SYMF(g_l1);

    __nv_bfloat16* Pxn  = SYMB(p_xn);    __nv_bfloat16* Pqkv = SYMB(p_qkvw);
    __nv_bfloat16* Pow  = SYMB(p_ow);    __nv_bfloat16* Pc1  = SYMB(p_c1w);
    __nv_bfloat16* Pq   = SYMB(p_q);     __nv_bfloat16* Pk   = SYMB(p_k);
    __nv_bfloat16* Ppr  = SYMB(p_probs); __nv_bfloat16* Pvt  = SYMB(p_vt);
    __nv_bfloat16* Pat  = SYMB(p_attn);  __nv_bfloat16* Pl0  = SYMB(p_l0);

    __half* Hxn  = SYMH(h_xn);   __half* Hguw = SYMH(h_guw);
    __half* Hdw  = SYMH(h_dw);   __half* Hpw  = SYMH(h_pw);
    __half* Hc0w = SYMH(h_c0w);  __half* Hin  = SYMH(h_in);
    __half* Hl1  = SYMH(h_l1);   __half* Hen  = SYMH(h_en);

    const int SMEM3 = 3 * 30720;
    cudaFuncSetAttribute((const void*)hgemm256<false, false>, cudaFuncAttributeMaxDynamicSharedMemorySize, SMEM3);
    cudaFuncSetAttribute((const void*)hgemm256<true, false>,  cudaFuncAttributeMaxDynamicSharedMemorySize, SMEM3);
    cudaFuncSetAttribute((const void*)hgemm256<false, true>,  cudaFuncAttributeMaxDynamicSharedMemorySize, SMEM3);

    const dim3 t32x8(32, 8);
    const float att_scale = 0.08838834764831845f;

    // ---- pack weights: attention 3-term bf16 ----
    splitT_k<<<dim3(64, 64), t32x8>>>(qw, 2048, 0, Pqkv, 0, 2048, 1);
    splitT_k<<<dim3(64, 64), t32x8>>>(kw, 2048, 0, Pqkv + 2048LL * 6144, 0, 2048, 1);
    splitT_k<<<dim3(64, 64), t32x8>>>(vw, 2048, 0, Pqkv + 4096LL * 6144, 0, 2048, 1);
    splitT_k<<<dim3(64, 64), t32x8>>>(ow, 2048, 0, Pow, 0, 2048, 1);
    splitT_k<<<dim3(8, 8), t32x8>>>(c1tw, 256, 0, Pc1, 0, 256, 1);
    splitT_k<<<dim3(8, 8), t32x8>>>(c1gw, 256, 0, Pc1 + 256LL * 768, 0, 256, 1);
    splitT_k<<<dim3(8, 8), t32x8>>>(c1iw, 256, 0, Pc1 + 512LL * 768, 0, 256, 1);
    // ---- pack weights: FFN fp16 1-term ----
    splitT_h16_k<<<dim3(64, 256), t32x8>>>(gatew, 8192, Hguw, 2048);
    splitT_h16_k<<<dim3(64, 256), t32x8>>>(upw, 8192, Hguw + 8192LL * 2048, 2048);
    splitT_h16_k<<<dim3(256, 64), t32x8>>>(downw, 2048, Hdw, 8192);
    splitT_h16_k<<<dim3(8, 256), t32x8>>>(projw, 8192, Hpw, 256);
    splitT_h16_k<<<dim3(256, 8), t32x8>>>(c0tw, 256, Hc0w, 8192);
    splitT_h16_k<<<dim3(256, 8), t32x8>>>(c0gw, 256, Hc0w + 256LL * 8192, 8192);
    splitT_h16_k<<<dim3(256, 8), t32x8>>>(c0iw, 256, Hc0w + 512LL * 8192, 8192);

    // ---- attention (unchanged: 3-term bf16) ----
    rmsnorm_pack_k<<<SEQL, 256>>>(x, anw, Pxn);
    hgemm256<false, false><<<dim3(24, 16), 256, SMEM3>>>(Pxn, 6144, 0, Pqkv, 6144, 0, qkv, 6144, 0, nullptr, 0, 0, 6144, 1.f);
    spike_rope_k<<<SEQL * NHEADS * 64 / 256, 256>>>(qkv, 6144, 1);
    spike_rope_k<<<SEQL * NHEADS * 64 / 256, 256>>>(qkv + 2048, 6144, 1);
    spike_rope_k<<<SEQL * NHEADS * 64 / 256, 256>>>(qkv + 4096, 6144, 0);
    split_k<<<dim3(256, 1, 16), 256>>>(qkv, 128, 6144, Pq, 2048LL * 384, 128, 0);
    split_k<<<dim3(256, 1, 16), 256>>>(qkv + 2048, 128, 6144, Pk, 2048LL * 384, 128, 1);
    splitT_k<<<dim3(64, 4, 16), t32x8>>>(qkv + 4096, 6144, 128, Pvt, 128LL * 4096, 2048, 3);
    hgemm256<true, false><<<dim3(8, 16, 16), 256, SMEM3>>>(
        Pq, 384, 2048LL * 384, Pk, 384, 2048LL * 384,
        sc, 2048, (ll)SEQL * SEQL, nullptr, 0, 0, 384, att_scale);
    softmax_pack_k<<<dim3(SEQL, NHEADS), 256>>>(sc, Ppr);
    hgemm<<<dim3(1, 16, 16), 256>>>(
        Ppr, 4096, 2048LL * 4096, Pvt, 4096, 128LL * 4096,
        attn, 2048, 128, 4096, 1.f);
    split_k<<<2048 * 2048 / 1024, 256>>>(attn, 0, 2048, Pat, 0, 2048, 0);
    hgemm256<false, false><<<dim3(8, 16), 256, SMEM3>>>(Pat, 6144, 0, Pow, 6144, 0, h, 2048, 0, x, 2048, 0, 6144, 1.f);

    // ---- LTC feed-forward (fp16 1-term GEMMs) ----
    rmsnorm_h16_k<<<SEQL, 256>>>(h, fnw, Hxn);
    hgemm256<false, true><<<dim3(64, 16), 256, SMEM3>>>(
        (const __nv_bfloat16*)Hxn, 2048, 0, (const __nv_bfloat16*)Hguw, 2048, 0,
        gu, 16384, 0, nullptr, 0, 0, 2048, 1.f);
    silu_mul_pack_k<<<2048 * 8192 / 1024, 256>>>(gu, inter, Hin);
    // cell 0: split-K x8 over K=8192, N=768 combined
    hgemm256<false, true><<<dim3(3, 16, 8), 256, SMEM3>>>(
        (const __nv_bfloat16*)Hin, 8192, 1024, (const __nv_bfloat16*)Hc0w, 8192, 1024,
        part, 768, 2048LL * 768, nullptr, 0, 0, 1024, 1.f);
    ltc_combine_k<<<2048, 256>>>(part, 8, 2048LL * 768, c0tb, c0gb, c0ib, c0hb, l0);
    split_k<<<2048 * 256 / 1024, 256>>>(l0, 0, 256, Pl0, 0, 256, 0);
    // cell 1 (3-term bf16, tiny)
    hgemm256<false, false><<<dim3(3, 16), 256, SMEM3>>>(
        Pl0, 768, 0, Pc1, 768, 0, part, 768, 0, nullptr, 0, 0, 768, 1.f);
    ltc_combine_k<<<2048, 256>>>(part, 1, 0, c1tb, c1gb, c1ib, c1hb, l1);
    pack_h16_k<<<2048 * 256 / 1024, 256>>>(l1, Hl1);
    // enhanced = inter + l1 @ proj  (fp16)
    hgemm256<false, true><<<dim3(32, 16), 256, SMEM3>>>(
        (const __nv_bfloat16*)Hl1, 256, 0, (const __nv_bfloat16*)Hpw, 256, 0,
        up, 8192, 0, inter, 8192, 0, 256, 1.f);
    pack_h16_k<<<2048 * 8192 / 1024, 256>>>(up, Hen);
    // out = h + enhanced @ down_w  (fp16)
    hgemm256<false, true><<<dim3(8, 16), 256, SMEM3>>>(
        (const __nv_bfloat16*)Hen, 8192, 0, (const __nv_bfloat16*)Hdw, 8192, 0,
        out, 2048, 0, h, 2048, 0, 8192, 1.f);
}

// round 9
// speedup vs baseline: 5.5359x; 1.1118x over previous
#include <cuda_runtime.h>
#include <cuda_bf16.h>
#include <cuda_fp16.h>
#include <math.h>
#include <stdint.h>

#define SEQL 2048
#define DIMN 2048
#define NHEADS 16
#define HDIM 128
#define HIDDEN 8192
#define LTCN 256
#define RMS_EPS 1.1920929e-07f
typedef long long ll;

// ======================= fp32 scratch =======================
__align__(256) __device__ float g_qkv[2048LL * 6144];
__align__(256) __device__ float g_scores[(ll)NHEADS * SEQL * SEQL];
__align__(256) __device__ float g_attn[SEQL * DIMN];
__align__(256) __device__ float g_h[SEQL * DIMN];
__align__(256) __device__ float g_gu[2048LL * 16384];
__align__(256) __device__ float g_up[SEQL * HIDDEN];
__align__(256) __device__ float g_inter[SEQL * HIDDEN];
__align__(256) __device__ float g_part[8LL * 2048 * 768];
__align__(256) __device__ float g_l0[SEQL * LTCN];
__align__(256) __device__ float g_l1[SEQL * LTCN];

// ======================= packed bf16 (3-term paths: QKV, c1) =======================
__align__(256) __device__ __nv_bfloat16 p_xn[2048LL * 6144];
__align__(256) __device__ __nv_bfloat16 p_qkvw[6144LL * 6144];
__align__(256) __device__ __nv_bfloat16 p_c1w[768LL * 768];
__align__(256) __device__ __nv_bfloat16 p_l0[2048LL * 768];

// ======================= packed fp16 (1-term paths) =======================
__align__(256) __device__ __half h_q[16LL * 2048 * 128];
__align__(256) __device__ __half h_k[16LL * 2048 * 128];
__align__(256) __device__ __half h_pr[16LL * 2048 * 2048];
__align__(256) __device__ __half h_vt[16LL * 128 * 2048];
__align__(256) __device__ __half h_at[2048LL * 2048];
__align__(256) __device__ __half h_ow[2048LL * 2048];
__align__(256) __device__ __half h_xn[2048LL * 2048];
__align__(256) __device__ __half h_guw[16384LL * 2048];
__align__(256) __device__ __half h_dw[2048LL * 8192];
__align__(256) __device__ __half h_pw[8192LL * 256];
__align__(256) __device__ __half h_c0w[768LL * 8192];
__align__(256) __device__ __half h_in[2048LL * 8192];
__align__(256) __device__ __half h_l1[2048LL * 256];
__align__(256) __device__ __half h_en[2048LL * 8192];

// ======================= helpers =======================
__device__ __forceinline__ uint32_t smem_u32(const void* p) {
    uint32_t a;
    asm("{ .reg .u64 t; cvta.to.shared.u64 t, %1; cvt.u32.u64 %0, t; }" : "=r"(a) : "l"(p));
    return a;
}
__device__ __forceinline__ void cp16(uint32_t dst, const void* src) {
    asm volatile("cp.async.cg.shared.global [%0], [%1], 16;" :: "r"(dst), "l"(src));
}
#define CP_COMMIT()  asm volatile("cp.async.commit_group;" ::: "memory")
#define CP_WAIT1()   asm volatile("cp.async.wait_group 1;" ::: "memory")
#define CP_WAIT2()   asm volatile("cp.async.wait_group 2;" ::: "memory")

__device__ __forceinline__ void ldmx4(uint32_t* r, uint32_t addr) {
    asm volatile("ldmatrix.sync.aligned.m8n8.x4.shared.b16 {%0,%1,%2,%3}, [%4];"
                 : "=r"(r[0]), "=r"(r[1]), "=r"(r[2]), "=r"(r[3]) : "r"(addr));
}
__device__ __forceinline__ void mma_bf(float* d, const uint32_t* a, uint32_t b0, uint32_t b1) {
    asm volatile(
        "mma.sync.aligned.m16n8k16.row.col.f32.bf16.bf16.f32 "
        "{%0,%1,%2,%3}, {%4,%5,%6,%7}, {%8,%9}, {%0,%1,%2,%3};"
        : "+f"(d[0]), "+f"(d[1]), "+f"(d[2]), "+f"(d[3])
        : "r"(a[0]), "r"(a[1]), "r"(a[2]), "r"(a[3]), "r"(b0), "r"(b1));
}
__device__ __forceinline__ void mma_fp(float* d, const uint32_t* a, uint32_t b0, uint32_t b1) {
    asm volatile(
        "mma.sync.aligned.m16n8k16.row.col.f32.f16.f16.f32 "
        "{%0,%1,%2,%3}, {%4,%5,%6,%7}, {%8,%9}, {%0,%1,%2,%3};"
        : "+f"(d[0]), "+f"(d[1]), "+f"(d[2]), "+f"(d[3])
        : "r"(a[0]), "r"(a[1]), "r"(a[2]), "r"(a[3]), "r"(b0), "r"(b1));
}

#define PITCH 80

// ======================= HMMA GEMM 128x256, 3-stage =======================
template <bool CAUSAL, bool F16>
__global__ __launch_bounds__(256, 1) void hgemm256(
    const __nv_bfloat16* __restrict__ A, int lda, ll sA,
    const __nv_bfloat16* __restrict__ B, int ldb, ll sB,
    float* __restrict__ C, int ldc, ll sC,
    const float* __restrict__ Dadd, int ldd, ll sD,
    int Kp, float alpha)
{
    const int bm = blockIdx.y * 128;
    const int bn = blockIdx.x * 256;
    if (CAUSAL && bn > bm + 127) return;

    const int z = blockIdx.z;
    A += (ll)z * sA;
    B += (ll)z * sB;
    C += (ll)z * sC;
    if (Dadd) Dadd += (ll)z * sD;

    extern __shared__ char smem[];
    const uint32_t sb = smem_u32(smem);
    const int tid = threadIdx.x;
    const int lane = tid & 31;
    const int wid = tid >> 5;
    const int wm = wid & 1;
    const int wn = wid >> 1;

    float acc[4][8][4];
#pragma unroll
    for (int i = 0; i < 4; i++)
#pragma unroll
        for (int j = 0; j < 8; j++)
#pragma unroll
            for (int t = 0; t < 4; t++) acc[i][j][t] = 0.f;

    const int nK = Kp >> 5;

    auto load_stage = [&](int s, int b) {
        const uint32_t Ad = sb + b * 30720;
        const char* Ag = (const char*)A + (ll)s * 64;
#pragma unroll
        for (int j = 0; j < 2; j++) {
            int q = tid + j * 256;
            int r = q >> 2, c = q & 3;
            cp16(Ad + r * PITCH + c * 16, Ag + (ll)(bm + r) * lda * 2 + c * 16);
        }
        const uint32_t Bd = Ad + 10240;
        const char* Bg = (const char*)B + (ll)s * 64;
#pragma unroll
        for (int j = 0; j < 4; j++) {
            int q = tid + j * 256;
            int r = q >> 2, c = q & 3;
            cp16(Bd + r * PITCH + c * 16, Bg + (ll)(bn + r) * ldb * 2 + c * 16);
        }
    };

    load_stage(0, 0); CP_COMMIT();
    if (nK > 1) load_stage(1, 1);
    CP_COMMIT();
    if (nK > 2) load_stage(2, 2);
    CP_COMMIT();

    int buf = 0;
    for (int i = 0; i < nK; i++) {
        CP_WAIT2();
        __syncthreads();
        const uint32_t Ab = sb + buf * 30720;
        const uint32_t Bb = Ab + 10240;
#pragma unroll
        for (int ks = 0; ks < 2; ks++) {
            uint32_t a[4][4];
#pragma unroll
            for (int mt = 0; mt < 4; mt++) {
                const int row = wm * 64 + mt * 16 + (lane & 15);
                ldmx4(a[mt], Ab + row * PITCH + (ks * 2 + (lane >> 4)) * 16);
            }
            uint32_t bf[4][4];
#pragma unroll
            for (int p = 0; p < 4; p++) {
                const int nrow = wn * 64 + p * 16 + ((lane >> 4) << 3) + (lane & 7);
                ldmx4(bf[p], Bb + nrow * PITCH + (ks * 2 + ((lane >> 3) & 1)) * 16);
            }
#pragma unroll
            for (int mt = 0; mt < 4; mt++)
#pragma unroll
                for (int j = 0; j < 8; j++) {
                    if (F16) mma_fp(acc[mt][j], a[mt], bf[j >> 1][(j & 1) * 2], bf[j >> 1][(j & 1) * 2 + 1]);
                    else     mma_bf(acc[mt][j], a[mt], bf[j >> 1][(j & 1) * 2], bf[j >> 1][(j & 1) * 2 + 1]);
                }
        }
        __syncthreads();
        if (i + 3 < nK) load_stage(i + 3, buf);
        CP_COMMIT();
        buf = (buf == 2) ? 0 : buf + 1;
    }

    const int r0 = lane >> 2;
    const int c0 = (lane & 3) * 2;
#pragma unroll
    for (int mt = 0; mt < 4; mt++) {
#pragma unroll
        for (int j = 0; j < 8; j++) {
            const int col = bn + wn * 64 + j * 8 + c0;
            const ll row0 = bm + wm * 64 + mt * 16 + r0;
            const ll row1 = row0 + 8;
            float2 v0 = {alpha * acc[mt][j][0], alpha * acc[mt][j][1]};
            float2 v1 = {alpha * acc[mt][j][2], alpha * acc[mt][j][3]};
            if (Dadd) {
                float2 d0 = *reinterpret_cast<const float2*>(Dadd + row0 * ldd + col);
                float2 d1 = *reinterpret_cast<const float2*>(Dadd + row1 * ldd + col);
                v0.x += d0.x; v0.y += d0.y; v1.x += d1.x; v1.y += d1.y;
            }
            *reinterpret_cast<float2*>(C + row0 * ldc + col) = v0;
            *reinterpret_cast<float2*>(C + row1 * ldc + col) = v1;
        }
    }
}

// ======================= HMMA GEMM 128x128, 2-stage (AV) =======================
template <bool F16>
__global__ __launch_bounds__(256) void hgemm(
    const __nv_bfloat16* __restrict__ A, int lda, ll sA,
    const __nv_bfloat16* __restrict__ B, int ldb, ll sB,
    float* __restrict__ C, int ldc, ll sC,
    int Kp, float alpha)
{
    const int bm = blockIdx.y * 128;
    const int bn = blockIdx.x * 128;
    const int z = blockIdx.z;
    A += (ll)z * sA;
    B += (ll)z * sB;
    C += (ll)z * sC;

    __shared__ char smem[4 * 128 * PITCH];
    const uint32_t sb = smem_u32(smem);
    const uint32_t Abase[2] = {sb, sb + 128 * PITCH};
    const uint32_t Bbase[2] = {sb + 2 * 128 * PITCH, sb + 3 * 128 * PITCH};

    const int tid = threadIdx.x;
    const int lane = tid & 31;
    const int wid = tid >> 5;
    const int wm = wid & 3;
    const int wn = wid >> 2;

    float acc[2][8][4];
#pragma unroll
    for (int i = 0; i < 2; i++)
#pragma unroll
        for (int j = 0; j < 8; j++)
#pragma unroll
            for (int t = 0; t < 4; t++) acc[i][j][t] = 0.f;

    const int nK = Kp >> 5;

    auto load_stage = [&](int s, int b) {
        const char* Ag = (const char*)A + (ll)s * 64;
#pragma unroll
        for (int j = 0; j < 2; j++) {
            int q = tid + j * 256;
            int r = q >> 2, c = q & 3;
            cp16(Abase[b] + r * PITCH + c * 16, Ag + (ll)(bm + r) * lda * 2 + c * 16);
        }
        const char* Bg = (const char*)B + (ll)s * 64;
#pragma unroll
        for (int j = 0; j < 2; j++) {
            int q = tid + j * 256;
            int r = q >> 2, c = q & 3;
            cp16(Bbase[b] + r * PITCH + c * 16, Bg + (ll)(bn + r) * ldb * 2 + c * 16);
        }
    };

    load_stage(0, 0); CP_COMMIT();
    if (nK > 1) load_stage(1, 1);
    CP_COMMIT();

    for (int i = 0; i < nK; i++) {
        const int buf = i & 1;
        CP_WAIT1();
        __syncthreads();
        const uint32_t Ab = Abase[buf], Bb = Bbase[buf];
#pragma unroll
        for (int ks = 0; ks < 2; ks++) {
            uint32_t a[2][4];
#pragma unroll
            for (int mt = 0; mt < 2; mt++) {
                const int row = wm * 32 + mt * 16 + (lane & 15);
                ldmx4(a[mt], Ab + row * PITCH + (ks * 2 + (lane >> 4)) * 16);
            }
            uint32_t bf[4][4];
#pragma unroll
            for (int p = 0; p < 4; p++) {
                const int nrow = wn * 64 + p * 16 + ((lane >> 4) << 3) + (lane & 7);
                ldmx4(bf[p], Bb + nrow * PITCH + (ks * 2 + ((lane >> 3) & 1)) * 16);
            }
#pragma unroll
            for (int mt = 0; mt < 2; mt++)
#pragma unroll
                for (int j = 0; j < 8; j++) {
                    if (F16) mma_fp(acc[mt][j], a[mt], bf[j >> 1][(j & 1) * 2], bf[j >> 1][(j & 1) * 2 + 1]);
                    else     mma_bf(acc[mt][j], a[mt], bf[j >> 1][(j & 1) * 2], bf[j >> 1][(j & 1) * 2 + 1]);
                }
        }
        __syncthreads();
        if (i + 2 < nK) load_stage(i + 2, buf);
        CP_COMMIT();
    }

    const int r0 = lane >> 2;
    const int c0 = (lane & 3) * 2;
#pragma unroll
    for (int mt = 0; mt < 2; mt++) {
#pragma unroll
        for (int j = 0; j < 8; j++) {
            const int col = bn + wn * 64 + j * 8 + c0;
            const ll row0 = bm + wm * 32 + mt * 16 + r0;
            const ll row1 = row0 + 8;
            float2 v0 = {alpha * acc[mt][j][0], alpha * acc[mt][j][1]};
            float2 v1 = {alpha * acc[mt][j][2], alpha * acc[mt][j][3]};
            *reinterpret_cast<float2*>(C + row0 * ldc + col) = v0;
            *reinterpret_cast<float2*>(C + row1 * ldc + col) = v1;
        }
    }
}

// ======================= split/pack helpers =======================
__device__ __forceinline__ void split2f(float x, unsigned short& h, unsigned short& l) {
    __nv_bfloat16 hb = __float2bfloat16_rn(x);
    __nv_bfloat16 lb = __float2bfloat16_rn(x - __bfloat162float(hb));
    h = __bfloat16_as_ushort(hb);
    l = __bfloat16_as_ushort(lb);
}

// mode 0: [hi|hi|lo] 3-term bf16 pack (for l0)
__global__ __launch_bounds__(256) void split_k(
    const float* __restrict__ in, int ldin,
    __nv_bfloat16* __restrict__ out, int C)
{
    const ll idx = (ll)blockIdx.x * 256 + threadIdx.x;
    const int c4n = C >> 2;
    const ll r = idx / c4n;
    const int c = (int)(idx % c4n) * 4;
    const float4 v = *reinterpret_cast<const float4*>(in + r * ldin + c);
    ushort4 hi, lo;
    split2f(v.x, hi.x, lo.x); split2f(v.y, hi.y, lo.y);
    split2f(v.z, hi.z, lo.z); split2f(v.w, hi.w, lo.w);
    __nv_bfloat16* op = out + r * ((ll)3 * C) + c;
    *reinterpret_cast<ushort4*>(op) = hi;
    *reinterpret_cast<ushort4*>(op + C) = hi;
    *reinterpret_cast<ushort4*>(op + 2 * C) = lo;
}

// transpose+split bf16 (mode 1 [hi|lo|hi] for weights)
__global__ void splitT_k(
    const float* __restrict__ in, int ldin,
    __nv_bfloat16* __restrict__ out, int K)
{
    __shared__ float t[32][33];
    const int k0 = blockIdx.x * 32, n0 = blockIdx.y * 32;
    const int tx = threadIdx.x, ty = threadIdx.y;
#pragma unroll
    for (int j = 0; j < 4; j++)
        t[ty + j * 8][tx] = in[(ll)(k0 + ty + j * 8) * ldin + n0 + tx];
    __syncthreads();
#pragma unroll
    for (int j = 0; j < 4; j++) {
        const int n = n0 + ty + j * 8, k = k0 + tx;
        const float x = t[tx][ty + j * 8];
        unsigned short h, l;
        split2f(x, h, l);
        __nv_bfloat16* base = out + (ll)n * ((ll)3 * K) + k;
        base[0] = __ushort_as_bfloat16(h);
        base[K] = __ushort_as_bfloat16(l);
        base[2 * K] = __ushort_as_bfloat16(h);
    }
}

// transpose to fp16 1-term with z batching: out[z][n][k] = fp16(in[k][zcol + n])
__global__ void splitT_h16_k(
    const float* __restrict__ in, int ldin, ll inZcols,
    __half* __restrict__ out, ll outZ, int K)
{
    __shared__ float t[32][33];
    const int k0 = blockIdx.x * 32, n0 = blockIdx.y * 32;
    const int tx = threadIdx.x, ty = threadIdx.y;
    const float* ip = in + (ll)blockIdx.z * inZcols;
#pragma unroll
    for (int j = 0; j < 4; j++)
        t[ty + j * 8][tx] = ip[(ll)(k0 + ty + j * 8) * ldin + n0 + tx];
    __syncthreads();
    __half* op = out + (ll)blockIdx.z * outZ;
#pragma unroll
    for (int j = 0; j < 4; j++) {
        const int n = n0 + ty + j * 8, k = k0 + tx;
        op[(ll)n * K + k] = __float2half_rn(t[tx][ty + j * 8]);
    }
}

// fp32 -> fp16 elementwise pack
__global__ __launch_bounds__(256) void pack_h16_k(
    const float* __restrict__ in, __half* __restrict__ out)
{
    const ll i = ((ll)blockIdx.x * 256 + threadIdx.x) * 4;
    const float4 v = *reinterpret_cast<const float4*>(in + i);
    *reinterpret_cast<__half2*>(out + i) = __floats2half2_rn(v.x, v.y);
    *reinterpret_cast<__half2*>(out + i + 2) = __floats2half2_rn(v.z, v.w);
}

// ======================= fused elementwise kernels =======================
__global__ __launch_bounds__(256) void rmsnorm_pack_k(
    const float* __restrict__ x, const float* __restrict__ w, __nv_bfloat16* __restrict__ out)
{
    const int r = blockIdx.x, tid = threadIdx.x;
    const float* xr = x + (ll)r * DIMN;
    float ss = 0.f;
    for (int i = tid; i < DIMN; i += 256) { float v = xr[i]; ss += v * v; }
    __shared__ float red[256];
    red[tid] = ss; __syncthreads();
    for (int s = 128; s > 0; s >>= 1) { if (tid < s) red[tid] += red[tid + s]; __syncthreads(); }
    const float scale = rsqrtf(red[0] * (1.0f / DIMN) + RMS_EPS);
    __nv_bfloat16* orow = out + (ll)r * 6144;
    for (int i = tid; i < DIMN; i += 256) {
        const float v = xr[i] * scale * w[i];
        unsigned short h, l;
        split2f(v, h, l);
        orow[i] = __ushort_as_bfloat16(h);
        orow[2048 + i] = __ushort_as_bfloat16(h);
        orow[4096 + i] = __ushort_as_bfloat16(l);
    }
}

__global__ __launch_bounds__(256) void rmsnorm_h16_k(
    const float* __restrict__ x, const float* __restrict__ w, __half* __restrict__ out)
{
    const int r = blockIdx.x, tid = threadIdx.x;
    const float* xr = x + (ll)r * DIMN;
    float ss = 0.f;
    for (int i = tid; i < DIMN; i += 256) { float v = xr[i]; ss += v * v; }
    __shared__ float red[256];
    red[tid] = ss; __syncthreads();
    for (int s = 128; s > 0; s >>= 1) { if (tid < s) red[tid] += red[tid + s]; __syncthreads(); }
    const float scale = rsqrtf(red[0] * (1.0f / DIMN) + RMS_EPS);
    __half* orow = out + (ll)r * DIMN;
    for (int i = tid; i < DIMN; i += 256)
        orow[i] = __float2half_rn(xr[i] * scale * w[i]);
}

// spike + rope, writing per-head fp16 layout out[h][s][d]
__global__ __launch_bounds__(256) void spike_rope_h16_k(
    const float* __restrict__ q, int stride, __half* __restrict__ out)
{
    const int idx = blockIdx.x * 256 + threadIdx.x;
    const int d = idx & 63;
    const int h = (idx >> 6) & (NHEADS - 1);
    const int s = idx >> 10;
    const ll base = (ll)s * stride + h * HDIM;
    const float a = q[base + d];
    const float b = q[base + d + 64];
    const float sa = a > 1.0f ? 1.f : 0.f;
    const float sb = b > 1.0f ? 1.f : 0.f;
    const float invf = powf(10000.0f, -(float)d * (1.0f / 64.0f));
    const float fr = (float)s * invf;
    double sd, cd;
    sincos((double)fr, &sd, &cd);
    const float c = (float)cd, si = (float)sd;
    __half* op = out + (ll)h * (SEQL * HDIM) + (ll)s * HDIM;
    op[d]      = __float2half_rn(sa * c - sb * si);
    op[d + 64] = __float2half_rn(sb * c + sa * si);
}

// spike only (V), in place fp32
__global__ __launch_bounds__(256) void spike_k(float* __restrict__ q, int stride)
{
    const int idx = blockIdx.x * 256 + threadIdx.x;
    const int d = idx & 127;
    const int h = (idx >> 7) & (NHEADS - 1);
    const int s = idx >> 11;
    const ll base = (ll)s * stride + h * HDIM;
    q[base + d] = q[base + d] > 1.0f ? 1.f : 0.f;
}

// causal softmax -> fp16 probs (row stride 2048)
__global__ __launch_bounds__(256) void softmax_h16_k(
    const float* __restrict__ sc, __half* __restrict__ pr)
{
    const int q = blockIdx.x, h = blockIdx.y, tid = threadIdx.x;
    const float* row = sc + ((ll)h * SEQL + q) * SEQL;
    __half* orow = pr + ((ll)h * SEQL + q) * SEQL;
    const int n = q + 1;
    __shared__ float red[256];
    float m = -1e30f;
    for (int i = tid; i < n; i += 256) m = fmaxf(m, row[i]);
    red[tid] = m; __syncthreads();
    for (int s = 128; s > 0; s >>= 1) { if (tid < s) red[tid] = fmaxf(red[tid], red[tid + s]); __syncthreads(); }
    m = red[0]; __syncthreads();
    float sum = 0.f;
    for (int i = tid; i < n; i += 256) sum += expf(row[i] - m);
    red[tid] = sum; __syncthreads();
    for (int s = 128; s > 0; s >>= 1) { if (tid < s) red[tid] += red[tid + s]; __syncthreads(); }
    const float inv = 1.0f / red[0];
    const __half z = __float2half_rn(0.f);
    for (int i = tid; i < n; i += 256)
        orow[i] = __float2half_rn(expf(row[i] - m) * inv);
    for (int i = n + tid; i < SEQL; i += 256) orow[i] = z;
}

__global__ __launch_bounds__(256) void silu_mul_pack_k(
    const float* __restrict__ gu, float* __restrict__ inter, __half* __restrict__ pin)
{
    const ll idx = (ll)blockIdx.x * 256 + threadIdx.x;
    const ll r = idx / 2048;
    const int c = (int)(idx % 2048) * 4;
    const float4 g = *reinterpret_cast<const float4*>(gu + r * 16384 + c);
    const float4 u = *reinterpret_cast<const float4*>(gu + r * 16384 + 8192 + c);
    float4 v;
    v.x = (g.x / (1.f + expf(-g.x))) * u.x;
    v.y = (g.y / (1.f + expf(-g.y))) * u.y;
    v.z = (g.z / (1.f + expf(-g.z))) * u.z;
    v.w = (g.w / (1.f + expf(-g.w))) * u.w;
    *reinterpret_cast<float4*>(inter + r * 8192 + c) = v;
    __half* op = pin + r * 8192 + c;
    *reinterpret_cast<__half2*>(op) = __floats2half2_rn(v.x, v.y);
    *reinterpret_cast<__half2*>(op + 2) = __floats2half2_rn(v.z, v.w);
}

__global__ __launch_bounds__(256) void ltc_combine_k(
    const float* __restrict__ t, int nz, ll zstride,
    const float* __restrict__ tb, const float* __restrict__ gb,
    const float* __restrict__ ib, const float* __restrict__ hb,
    float* __restrict__ out)
{
    const int i = blockIdx.x * 256 + threadIdx.x;
    const int r = i >> 8;
    const int n = i & (LTCN - 1);
    float tv = 0.f, gv = 0.f, iv = 0.f;
    for (int z = 0; z < nz; z++) {
        const float* base = t + (ll)z * zstride + (ll)r * 768;
        tv += base[n]; gv += base[256 + n]; iv += base[512 + n];
    }
    const float tau = 0.1f + 9.9f / (1.f + expf(-(tv + tb[n])));
    const float gt  = 1.f / (1.f + expf(-(gv + gb[n])));
    const float ic  = tanhf(iv + ib[n]);
    const float hc  = tanhf(hb[n]);
    const float target = gt * ic + (1.f - gt) * hc;
    out[i] = tanhf(target / (tau + 1e-8f));
}

// ======================= launcher =======================
static inline float* SYMF(const void* s) { void* p; cudaGetSymbolAddress(&p, s); return (float*)p; }
static inline __nv_bfloat16* SYMB(const void* s) { void* p; cudaGetSymbolAddress(&p, s); return (__nv_bfloat16*)p; }
static inline __half* SYMH(const void* s) { void* p; cudaGetSymbolAddress(&p, s); return (__half*)p; }

extern "C" void kernel_launch(void* const* d_in, const int* in_sizes, int n_in,
                              void* d_out, int out_size)
{
    (void)in_sizes; (void)n_in; (void)out_size;
    const float* x     = (const float*)d_in[0];
    const float* anw   = (const float*)d_in[1];
    const float* fnw   = (const float*)d_in[2];
    const float* qw    = (const float*)d_in[3];
    const float* kw    = (const float*)d_in[4];
    const float* vw    = (const float*)d_in[5];
    const float* ow    = (const float*)d_in[6];
    const float* gatew = (const float*)d_in[7];
    const float* upw   = (const float*)d_in[8];
    const float* downw = (const float*)d_in[9];
    const float* projw = (const float*)d_in[10];
    const float* c0tw  = (const float*)d_in[11];
    const float* c0tb  = (const float*)d_in[12];
    const float* c0gw  = (const float*)d_in[13];
    const float* c0gb  = (const float*)d_in[14];
    const float* c0iw  = (const float*)d_in[15];
    const float* c0ib  = (const float*)d_in[16];
    const float* c0hb  = (const float*)d_in[18];
    const float* c1tw  = (const float*)d_in[19];
    const float* c1tb  = (const float*)d_in[20];
    const float* c1gw  = (const float*)d_in[21];
    const float* c1gb  = (const float*)d_in[22];
    const float* c1iw  = (const float*)d_in[23];
    const float* c1ib  = (const float*)d_in[24];
    const float* c1hb  = (const float*)d_in[26];
    float* out = (float*)d_out;

    float* qkv   = SYMF(g_qkv);   float* sc    = SYMF(g_scores);
    float* attn  = SYMF(g_attn);  float* h     = SYMF(g_h);
    float* gu    = SYMF(g_gu);    float* up    = SYMF(g_up);
    float* inter = SYMF(g_inter); float* part  = SYMF(g_part);
    float* l0    = SYMF(g_l0);    float* l1    = SYMF(g_l1);

    __nv_bfloat16* Pxn  = SYMB(p_xn);   __nv_bfloat16* Pqkv = SYMB(p_qkvw);
    __nv_bfloat16* Pc1  = SYMB(p_c1w);  __nv_bfloat16* Pl0  = SYMB(p_l0);

    __half* Hq   = SYMH(h_q);    __half* Hk   = SYMH(h_k);
    __half* Hpr  = SYMH(h_pr);   __half* Hvt  = SYMH(h_vt);
    __half* Hat  = SYMH(h_at);   __half* How  = SYMH(h_ow);
    __half* Hxn  = SYMH(h_xn);   __half* Hguw = SYMH(h_guw);
    __half* Hdw  = SYMH(h_dw);   __half* Hpw  = SYMH(h_pw);
    __half* Hc0w = SYMH(h_c0w);  __half* Hin  = SYMH(h_in);
    __half* Hl1  = SYMH(h_l1);   __half* Hen  = SYMH(h_en);

    const int SMEM3 = 3 * 30720;
    cudaFuncSetAttribute((const void*)hgemm256<false, false>, cudaFuncAttributeMaxDynamicSharedMemorySize, SMEM3);
    cudaFuncSetAttribute((const void*)hgemm256<true, true>,   cudaFuncAttributeMaxDynamicSharedMemorySize, SMEM3);
    cudaFuncSetAttribute((const void*)hgemm256<false, true>,  cudaFuncAttributeMaxDynamicSharedMemorySize, SMEM3);

    const dim3 t32x8(32, 8);
    const float att_scale = 0.08838834764831845f;

    // ---- pack weights ----
    splitT_k<<<dim3(64, 64), t32x8>>>(qw, 2048, Pqkv, 2048);
    splitT_k<<<dim3(64, 64), t32x8>>>(kw, 2048, Pqkv + 2048LL * 6144, 2048);
    splitT_k<<<dim3(64, 64), t32x8>>>(vw, 2048, Pqkv + 4096LL * 6144, 2048);
    splitT_k<<<dim3(8, 8), t32x8>>>(c1tw, 256, Pc1, 256);
    splitT_k<<<dim3(8, 8), t32x8>>>(c1gw, 256, Pc1 + 256LL * 768, 256);
    splitT_k<<<dim3(8, 8), t32x8>>>(c1iw, 256, Pc1 + 512LL * 768, 256);
    splitT_h16_k<<<dim3(64, 64), t32x8>>>(ow, 2048, 0, How, 0, 2048);
    splitT_h16_k<<<dim3(64, 256), t32x8>>>(gatew, 8192, 0, Hguw, 0, 2048);
    splitT_h16_k<<<dim3(64, 256), t32x8>>>(upw, 8192, 0, Hguw + 8192LL * 2048, 0, 2048);
    splitT_h16_k<<<dim3(256, 64), t32x8>>>(downw, 2048, 0, Hdw, 0, 8192);
    splitT_h16_k<<<dim3(8, 256), t32x8>>>(projw, 8192, 0, Hpw, 0, 256);
    splitT_h16_k<<<dim3(256, 8), t32x8>>>(c0tw, 256, 0, Hc0w, 0, 8192);
    splitT_h16_k<<<dim3(256, 8), t32x8>>>(c0gw, 256, 0, Hc0w + 256LL * 8192, 0, 8192);
    splitT_h16_k<<<dim3(256, 8), t32x8>>>(c0iw, 256, 0, Hc0w + 512LL * 8192, 0, 8192);

    // ---- attention ----
    rmsnorm_pack_k<<<SEQL, 256>>>(x, anw, Pxn);
    hgemm256<false, false><<<dim3(24, 16), 256, SMEM3>>>(Pxn, 6144, 0, Pqkv, 6144, 0, qkv, 6144, 0, nullptr, 0, 0, 6144, 1.f);
    spike_rope_h16_k<<<SEQL * NHEADS * 64 / 256, 256>>>(qkv, 6144, Hq);
    spike_rope_h16_k<<<SEQL * NHEADS * 64 / 256, 256>>>(qkv + 2048, 6144, Hk);
    spike_k<<<SEQL * NHEADS * 128 / 256, 256>>>(qkv + 4096, 6144);
    splitT_h16_k<<<dim3(64, 4, 16), t32x8>>>(qkv + 4096, 6144, 128, Hvt, 128LL * 2048, 2048);
    // scores: fp16 1-term, per head, causal tile skip
    hgemm256<true, true><<<dim3(8, 16, 16), 256, SMEM3>>>(
        (const __nv_bfloat16*)Hq, 128, 2048LL * 128, (const __nv_bfloat16*)Hk, 128, 2048LL * 128,
        sc, 2048, (ll)SEQL * SEQL, nullptr, 0, 0, 128, att_scale);
    softmax_h16_k<<<dim3(SEQL, NHEADS), 256>>>(sc, Hpr);
    // AV: fp16 1-term
    hgemm<true><<<dim3(1, 16, 16), 256>>>(
        (const __nv_bfloat16*)Hpr, 2048, 2048LL * 2048, (const __nv_bfloat16*)Hvt, 2048, 128LL * 2048,
        attn, 2048, 128, 2048, 1.f);
    pack_h16_k<<<2048 * 2048 / 1024, 256>>>(attn, Hat);
    // O projection: fp16 1-term + residual
    hgemm256<false, true><<<dim3(8, 16), 256, SMEM3>>>(
        (const __nv_bfloat16*)Hat, 2048, 0, (const __nv_bfloat16*)How, 2048, 0,
        h, 2048, 0, x, 2048, 0, 2048, 1.f);

    // ---- LTC feed-forward (fp16 1-term) ----
    rmsnorm_h16_k<<<SEQL, 256>>>(h, fnw, Hxn);
    hgemm256<false, true><<<dim3(64, 16), 256, SMEM3>>>(
        (const __nv_bfloat16*)Hxn, 2048, 0, (const __nv_bfloat16*)Hguw, 2048, 0,
        gu, 16384, 0, nullptr, 0, 0, 2048, 1.f);
    silu_mul_pack_k<<<2048 * 8192 / 1024, 256>>>(gu, inter, Hin);
    hgemm256<false, true><<<dim3(3, 16, 8), 256, SMEM3>>>(
        (const __nv_bfloat16*)Hin, 8192, 1024, (const __nv_bfloat16*)Hc0w, 8192, 1024,
        part, 768, 2048LL * 768, nullptr, 0, 0, 1024, 1.f);
    ltc_combine_k<<<2048, 256>>>(part, 8, 2048LL * 768, c0tb, c0gb, c0ib, c0hb, l0);
    split_k<<<2048 * 256 / 1024, 256>>>(l0, 256, Pl0, 256);
    hgemm256<false, false><<<dim3(3, 16), 256, SMEM3>>>(
        Pl0, 768, 0, Pc1, 768, 0, part, 768, 0, nullptr, 0, 0, 768, 1.f);
    ltc_combine_k<<<2048, 256>>>(part, 1, 0, c1tb, c1gb, c1ib, c1hb, l1);
    pack_h16_k<<<2048 * 256 / 1024, 256>>>(l1, Hl1);
    hgemm256<false, true><<<dim3(32, 16), 256, SMEM3>>>(
        (const __nv_bfloat16*)Hl1, 256, 0, (const __nv_bfloat16*)Hpw, 256, 0,
        up, 8192, 0, inter, 8192, 0, 256, 1.f);
    pack_h16_k<<<2048 * 8192 / 1024, 256>>>(up, Hen);
    hgemm256<false, true><<<dim3(8, 16), 256, SMEM3>>>(
        (const __nv_bfloat16*)Hen, 8192, 0, (const __nv_bfloat16*)Hdw, 8192, 0,
        out, 2048, 0, h, 2048, 0, 8192, 1.f);
}

// round 13
// speedup vs baseline: 5.6821x; 1.0264x over previous
#include <cuda_runtime.h>
#include <cuda_bf16.h>
#include <cuda_fp16.h>
#include <math.h>
#include <stdint.h>

#define SEQL 2048
#define DIMN 2048
#define NHEADS 16
#define HDIM 128
#define HIDDEN 8192
#define LTCN 256
#define RMS_EPS 1.1920929e-07f
typedef long long ll;

// ======================= fp32 scratch =======================
__align__(256) __device__ float g_qkv[2048LL * 6144];
__align__(256) __device__ float g_scores[(ll)NHEADS * SEQL * SEQL];
__align__(256) __device__ float g_h[SEQL * DIMN];
__align__(256) __device__ float g_inter[SEQL * HIDDEN];
__align__(256) __device__ float g_part[8LL * 2048 * 768];
__align__(256) __device__ float g_l0[SEQL * LTCN];
__align__(256) __device__ float g_l1[SEQL * LTCN];

// ======================= packed bf16 (3-term paths: QKV, c1) =======================
__align__(256) __device__ __nv_bfloat16 p_xn[2048LL * 6144];
__align__(256) __device__ __nv_bfloat16 p_qkvw[6144LL * 6144];
__align__(256) __device__ __nv_bfloat16 p_c1w[768LL * 768];
__align__(256) __device__ __nv_bfloat16 p_l0[2048LL * 768];

// ======================= packed fp16 (1-term paths) =======================
__align__(256) __device__ __half h_q[16LL * 2048 * 128];
__align__(256) __device__ __half h_k[16LL * 2048 * 128];
__align__(256) __device__ __half h_pr[16LL * 2048 * 2048];
__align__(256) __device__ __half h_vt[16LL * 128 * 2048];
__align__(256) __device__ __half h_at[2048LL * 2048];
__align__(256) __device__ __half h_ow[2048LL * 2048];
__align__(256) __device__ __half h_xn[2048LL * 2048];
__align__(256) __device__ __half h_guw[16384LL * 2048];   // interleaved gate/up
__align__(256) __device__ __half h_dw[2048LL * 8192];
__align__(256) __device__ __half h_pw[8192LL * 256];
__align__(256) __device__ __half h_c0w[768LL * 8192];
__align__(256) __device__ __half h_in[2048LL * 8192];
__align__(256) __device__ __half h_l1[2048LL * 256];
__align__(256) __device__ __half h_en[2048LL * 8192];

// ======================= helpers =======================
__device__ __forceinline__ uint32_t smem_u32(const void* p) {
    uint32_t a;
    asm("{ .reg .u64 t; cvta.to.shared.u64 t, %1; cvt.u32.u64 %0, t; }" : "=r"(a) : "l"(p));
    return a;
}
__device__ __forceinline__ void cp16(uint32_t dst, const void* src) {
    asm volatile("cp.async.cg.shared.global [%0], [%1], 16;" :: "r"(dst), "l"(src));
}
#define CP_COMMIT()  asm volatile("cp.async.commit_group;" ::: "memory")
#define CP_WAIT1()   asm volatile("cp.async.wait_group 1;" ::: "memory")
#define CP_WAIT2()   asm volatile("cp.async.wait_group 2;" ::: "memory")

__device__ __forceinline__ void ldmx4(uint32_t* r, uint32_t addr) {
    asm volatile("ldmatrix.sync.aligned.m8n8.x4.shared.b16 {%0,%1,%2,%3}, [%4];"
                 : "=r"(r[0]), "=r"(r[1]), "=r"(r[2]), "=r"(r[3]) : "r"(addr));
}
__device__ __forceinline__ void mma_bf(float* d, const uint32_t* a, uint32_t b0, uint32_t b1) {
    asm volatile(
        "mma.sync.aligned.m16n8k16.row.col.f32.bf16.bf16.f32 "
        "{%0,%1,%2,%3}, {%4,%5,%6,%7}, {%8,%9}, {%0,%1,%2,%3};"
        : "+f"(d[0]), "+f"(d[1]), "+f"(d[2]), "+f"(d[3])
        : "r"(a[0]), "r"(a[1]), "r"(a[2]), "r"(a[3]), "r"(b0), "r"(b1));
}
__device__ __forceinline__ void mma_fp(float* d, const uint32_t* a, uint32_t b0, uint32_t b1) {
    asm volatile(
        "mma.sync.aligned.m16n8k16.row.col.f32.f16.f16.f32 "
        "{%0,%1,%2,%3}, {%4,%5,%6,%7}, {%8,%9}, {%0,%1,%2,%3};"
        : "+f"(d[0]), "+f"(d[1]), "+f"(d[2]), "+f"(d[3])
        : "r"(a[0]), "r"(a[1]), "r"(a[2]), "r"(a[3]), "r"(b0), "r"(b1));
}

#define PITCH 80

// ======================= HMMA GEMM 128x256, 3-stage =======================
// OUT16: C is __half* (ldc/sC in half elements); Dadd stays fp32.
template <bool CAUSAL, bool F16, bool OUT16>
__global__ __launch_bounds__(256, 1) void hgemm256(
    const __nv_bfloat16* __restrict__ A, int lda, ll sA,
    const __nv_bfloat16* __restrict__ B, int ldb, ll sB,
    float* __restrict__ C, int ldc, ll sC,
    const float* __restrict__ Dadd, int ldd, ll sD,
    int Kp, float alpha)
{
    const int bm = blockIdx.y * 128;
    const int bn = blockIdx.x * 256;
    if (CAUSAL && bn > bm + 127) return;

    const int z = blockIdx.z;
    A += (ll)z * sA;
    B += (ll)z * sB;
    __half* Ch = nullptr;
    if (OUT16) Ch = (__half*)C + (ll)z * sC;
    else C += (ll)z * sC;
    if (Dadd) Dadd += (ll)z * sD;

    extern __shared__ char smem[];
    const uint32_t sb = smem_u32(smem);
    const int tid = threadIdx.x;
    const int lane = tid & 31;
    const int wid = tid >> 5;
    const int wm = wid & 1;
    const int wn = wid >> 1;

    float acc[4][8][4];
#pragma unroll
    for (int i = 0; i < 4; i++)
#pragma unroll
        for (int j = 0; j < 8; j++)
#pragma unroll
            for (int t = 0; t < 4; t++) acc[i][j][t] = 0.f;

    const int nK = Kp >> 5;

    auto load_stage = [&](int s, int b) {
        const uint32_t Ad = sb + b * 30720;
        const char* Ag = (const char*)A + (ll)s * 64;
#pragma unroll
        for (int j = 0; j < 2; j++) {
            int q = tid + j * 256;
            int r = q >> 2, c = q & 3;
            cp16(Ad + r * PITCH + c * 16, Ag + (ll)(bm + r) * lda * 2 + c * 16);
        }
        const uint32_t Bd = Ad + 10240;
        const char* Bg = (const char*)B + (ll)s * 64;
#pragma unroll
        for (int j = 0; j < 4; j++) {
            int q = tid + j * 256;
            int r = q >> 2, c = q & 3;
            cp16(Bd + r * PITCH + c * 16, Bg + (ll)(bn + r) * ldb * 2 + c * 16);
        }
    };

    load_stage(0, 0); CP_COMMIT();
    if (nK > 1) load_stage(1, 1);
    CP_COMMIT();
    if (nK > 2) load_stage(2, 2);
    CP_COMMIT();

    int buf = 0;
    for (int i = 0; i < nK; i++) {
        CP_WAIT2();
        __syncthreads();
        const uint32_t Ab = sb + buf * 30720;
        const uint32_t Bb = Ab + 10240;
#pragma unroll
        for (int ks = 0; ks < 2; ks++) {
            uint32_t a[4][4];
#pragma unroll
            for (int mt = 0; mt < 4; mt++) {
                const int row = wm * 64 + mt * 16 + (lane & 15);
                ldmx4(a[mt], Ab + row * PITCH + (ks * 2 + (lane >> 4)) * 16);
            }
            uint32_t bf[4][4];
#pragma unroll
            for (int p = 0; p < 4; p++) {
                const int nrow = wn * 64 + p * 16 + ((lane >> 4) << 3) + (lane & 7);
                ldmx4(bf[p], Bb + nrow * PITCH + (ks * 2 + ((lane >> 3) & 1)) * 16);
            }
#pragma unroll
            for (int mt = 0; mt < 4; mt++)
#pragma unroll
                for (int j = 0; j < 8; j++) {
                    if (F16) mma_fp(acc[mt][j], a[mt], bf[j >> 1][(j & 1) * 2], bf[j >> 1][(j & 1) * 2 + 1]);
                    else     mma_bf(acc[mt][j], a[mt], bf[j >> 1][(j & 1) * 2], bf[j >> 1][(j & 1) * 2 + 1]);
                }
        }
        __syncthreads();
        if (i + 3 < nK) load_stage(i + 3, buf);
        CP_COMMIT();
        buf = (buf == 2) ? 0 : buf + 1;
    }

    const int r0 = lane >> 2;
    const int c0 = (lane & 3) * 2;
#pragma unroll
    for (int mt = 0; mt < 4; mt++) {
#pragma unroll
        for (int j = 0; j < 8; j++) {
            const int col = bn + wn * 64 + j * 8 + c0;
            const ll row0 = bm + wm * 64 + mt * 16 + r0;
            const ll row1 = row0 + 8;
            float2 v0 = {alpha * acc[mt][j][0], alpha * acc[mt][j][1]};
            float2 v1 = {alpha * acc[mt][j][2], alpha * acc[mt][j][3]};
            if (Dadd) {
                float2 d0 = *reinterpret_cast<const float2*>(Dadd + row0 * ldd + col);
                float2 d1 = *reinterpret_cast<const float2*>(Dadd + row1 * ldd + col);
                v0.x += d0.x; v0.y += d0.y; v1.x += d1.x; v1.y += d1.y;
            }
            if (OUT16) {
                *reinterpret_cast<__half2*>(Ch + row0 * ldc + col) = __floats2half2_rn(v0.x, v0.y);
                *reinterpret_cast<__half2*>(Ch + row1 * ldc + col) = __floats2half2_rn(v1.x, v1.y);
            } else {
                *reinterpret_cast<float2*>(C + row0 * ldc + col) = v0;
                *reinterpret_cast<float2*>(C + row1 * ldc + col) = v1;
            }
        }
    }
}

// ======================= gate/up fused GEMM (fp16, interleaved weights) ============
// B packed: 16-row groups: rows 0-7 = gate cols g*8..+7, rows 8-15 = up same cols.
// Epilogue: inter = silu(gate)*up (fp32) + fp16 copy.
__global__ __launch_bounds__(256, 1) void hgemm_gu(
    const __half* __restrict__ A, const __half* __restrict__ B,
    float* __restrict__ inter, __half* __restrict__ hin)
{
    const int bm = blockIdx.y * 128;
    const int bn = blockIdx.x * 256;
    extern __shared__ char smem[];
    const uint32_t sb = smem_u32(smem);
    const int tid = threadIdx.x;
    const int lane = tid & 31;
    const int wid = tid >> 5;
    const int wm = wid & 1;
    const int wn = wid >> 1;

    float acc[4][8][4];
#pragma unroll
    for (int i = 0; i < 4; i++)
#pragma unroll
        for (int j = 0; j < 8; j++)
#pragma unroll
            for (int t = 0; t < 4; t++) acc[i][j][t] = 0.f;

    const int nK = 2048 >> 5;

    auto load_stage = [&](int s, int b) {
        const uint32_t Ad = sb + b * 30720;
        const char* Ag = (const char*)A + (ll)s * 64;
#pragma unroll
        for (int j = 0; j < 2; j++) {
            int q = tid + j * 256;
            int r = q >> 2, c = q & 3;
            cp16(Ad + r * PITCH + c * 16, Ag + (ll)(bm + r) * 2048 * 2 + c * 16);
        }
        const uint32_t Bd = Ad + 10240;
        const char* Bg = (const char*)B + (ll)s * 64;
#pragma unroll
        for (int j = 0; j < 4; j++) {
            int q = tid + j * 256;
            int r = q >> 2, c = q & 3;
            cp16(Bd + r * PITCH + c * 16, Bg + (ll)(bn + r) * 2048 * 2 + c * 16);
        }
    };

    load_stage(0, 0); CP_COMMIT();
    load_stage(1, 1); CP_COMMIT();
    load_stage(2, 2); CP_COMMIT();

    int buf = 0;
    for (int i = 0; i < nK; i++) {
        CP_WAIT2();
        __syncthreads();
        const uint32_t Ab = sb + buf * 30720;
        const uint32_t Bb = Ab + 10240;
#pragma unroll
        for (int ks = 0; ks < 2; ks++) {
            uint32_t a[4][4];
#pragma unroll
            for (int mt = 0; mt < 4; mt++) {
                const int row = wm * 64 + mt * 16 + (lane & 15);
                ldmx4(a[mt], Ab + row * PITCH + (ks * 2 + (lane >> 4)) * 16);
            }
            uint32_t bf[4][4];
#pragma unroll
            for (int p = 0; p < 4; p++) {
                const int nrow = wn * 64 + p * 16 + ((lane >> 4) << 3) + (lane & 7);
                ldmx4(bf[p], Bb + nrow * PITCH + (ks * 2 + ((lane >> 3) & 1)) * 16);
            }
#pragma unroll
            for (int mt = 0; mt < 4; mt++)
#pragma unroll
                for (int j = 0; j < 8; j++)
                    mma_fp(acc[mt][j], a[mt], bf[j >> 1][(j & 1) * 2], bf[j >> 1][(j & 1) * 2 + 1]);
        }
        __syncthreads();
        if (i + 3 < nK) load_stage(i + 3, buf);
        CP_COMMIT();
        buf = (buf == 2) ? 0 : buf + 1;
    }

    const int r0 = lane >> 2;
    const int c0 = (lane & 3) * 2;
#pragma unroll
    for (int mt = 0; mt < 4; mt++) {
#pragma unroll
        for (int p = 0; p < 4; p++) {
            // j=2p: gate tile; j=2p+1: up tile; both map to same output cols
            const int ob = ((bn + wn * 64) >> 1) + p * 8 + c0;
            const ll row0 = bm + wm * 64 + mt * 16 + r0;
            const ll row1 = row0 + 8;
            const float* ga = acc[mt][2 * p];
            const float* ua = acc[mt][2 * p + 1];
            float v0x = (ga[0] / (1.f + expf(-ga[0]))) * ua[0];
            float v0y = (ga[1] / (1.f + expf(-ga[1]))) * ua[1];
            float v1x = (ga[2] / (1.f + expf(-ga[2]))) * ua[2];
            float v1y = (ga[3] / (1.f + expf(-ga[3]))) * ua[3];
            *reinterpret_cast<float2*>(inter + row0 * 8192 + ob) = make_float2(v0x, v0y);
            *reinterpret_cast<float2*>(inter + row1 * 8192 + ob) = make_float2(v1x, v1y);
            *reinterpret_cast<__half2*>(hin + row0 * 8192 + ob) = __floats2half2_rn(v0x, v0y);
            *reinterpret_cast<__half2*>(hin + row1 * 8192 + ob) = __floats2half2_rn(v1x, v1y);
        }
    }
}

// ======================= HMMA GEMM 128x128, 2-stage (AV) =======================
// CK: causal K truncation (keys <= query block top). OUT16: fp16 C.
template <bool CK, bool OUT16>
__global__ __launch_bounds__(256) void hgemm(
    const __nv_bfloat16* __restrict__ A, int lda, ll sA,
    const __nv_bfloat16* __restrict__ B, int ldb, ll sB,
    float* __restrict__ C, int ldc, ll sC,
    int Kp, float alpha)
{
    const int bm = blockIdx.y * 128;
    const int bn = blockIdx.x * 128;
    const int z = blockIdx.z;
    A += (ll)z * sA;
    B += (ll)z * sB;
    __half* Ch = nullptr;
    if (OUT16) Ch = (__half*)C + (ll)z * sC;
    else C += (ll)z * sC;

    __shared__ char smem[4 * 128 * PITCH];
    const uint32_t sb = smem_u32(smem);
    const uint32_t Abase[2] = {sb, sb + 128 * PITCH};
    const uint32_t Bbase[2] = {sb + 2 * 128 * PITCH, sb + 3 * 128 * PITCH};

    const int tid = threadIdx.x;
    const int lane = tid & 31;
    const int wid = tid >> 5;
    const int wm = wid & 3;
    const int wn = wid >> 2;

    float acc[2][8][4];
#pragma unroll
    for (int i = 0; i < 2; i++)
#pragma unroll
        for (int j = 0; j < 8; j++)
#pragma unroll
            for (int t = 0; t < 4; t++) acc[i][j][t] = 0.f;

    const int KpEff = CK ? (bm + 128 < Kp ? bm + 128 : Kp) : Kp;
    const int nK = KpEff >> 5;

    auto load_stage = [&](int s, int b) {
        const char* Ag = (const char*)A + (ll)s * 64;
#pragma unroll
        for (int j = 0; j < 2; j++) {
            int q = tid + j * 256;
            int r = q >> 2, c = q & 3;
            cp16(Abase[b] + r * PITCH + c * 16, Ag + (ll)(bm + r) * lda * 2 + c * 16);
        }
        const char* Bg = (const char*)B + (ll)s * 64;
#pragma unroll
        for (int j = 0; j < 2; j++) {
            int q = tid + j * 256;
            int r = q >> 2, c = q & 3;
            cp16(Bbase[b] + r * PITCH + c * 16, Bg + (ll)(bn + r) * ldb * 2 + c * 16);
        }
    };

    load_stage(0, 0); CP_COMMIT();
    if (nK > 1) load_stage(1, 1);
    CP_COMMIT();

    for (int i = 0; i < nK; i++) {
        const int buf = i & 1;
        CP_WAIT1();
        __syncthreads();
        const uint32_t Ab = Abase[buf], Bb = Bbase[buf];
#pragma unroll
        for (int ks = 0; ks < 2; ks++) {
            uint32_t a[2][4];
#pragma unroll
            for (int mt = 0; mt < 2; mt++) {
                const int row = wm * 32 + mt * 16 + (lane & 15);
                ldmx4(a[mt], Ab + row * PITCH + (ks * 2 + (lane >> 4)) * 16);
            }
            uint32_t bf[4][4];
#pragma unroll
            for (int p = 0; p < 4; p++) {
                const int nrow = wn * 64 + p * 16 + ((lane >> 4) << 3) + (lane & 7);
                ldmx4(bf[p], Bb + nrow * PITCH + (ks * 2 + ((lane >> 3) & 1)) * 16);
            }
#pragma unroll
            for (int mt = 0; mt < 2; mt++)
#pragma unroll
                for (int j = 0; j < 8; j++)
                    mma_fp(acc[mt][j], a[mt], bf[j >> 1][(j & 1) * 2], bf[j >> 1][(j & 1) * 2 + 1]);
        }
        __syncthreads();
        if (i + 2 < nK) load_stage(i + 2, buf);
        CP_COMMIT();
    }

    const int r0 = lane >> 2;
    const int c0 = (lane & 3) * 2;
#pragma unroll
    for (int mt = 0; mt < 2; mt++) {
#pragma unroll
        for (int j = 0; j < 8; j++) {
            const int col = bn + wn * 64 + j * 8 + c0;
            const ll row0 = bm + wm * 32 + mt * 16 + r0;
            const ll row1 = row0 + 8;
            float2 v0 = {alpha * acc[mt][j][0], alpha * acc[mt][j][1]};
            float2 v1 = {alpha * acc[mt][j][2], alpha * acc[mt][j][3]};
            if (OUT16) {
                *reinterpret_cast<__half2*>(Ch + row0 * ldc + col) = __floats2half2_rn(v0.x, v0.y);
                *reinterpret_cast<__half2*>(Ch + row1 * ldc + col) = __floats2half2_rn(v1.x, v1.y);
            } else {
                *reinterpret_cast<float2*>(C + row0 * ldc + col) = v0;
                *reinterpret_cast<float2*>(C + row1 * ldc + col) = v1;
            }
        }
    }
}

// ======================= split/pack helpers =======================
__device__ __forceinline__ void split2f(float x, unsigned short& h, unsigned short& l) {
    __nv_bfloat16 hb = __float2bfloat16_rn(x);
    __nv_bfloat16 lb = __float2bfloat16_rn(x - __bfloat162float(hb));
    h = __bfloat16_as_ushort(hb);
    l = __bfloat16_as_ushort(lb);
}

// [hi|hi|lo] 3-term bf16 pack (for l0)
__global__ __launch_bounds__(256) void split_k(
    const float* __restrict__ in, int ldin,
    __nv_bfloat16* __restrict__ out, int C)
{
    const ll idx = (ll)blockIdx.x * 256 + threadIdx.x;
    const int c4n = C >> 2;
    const ll r = idx / c4n;
    const int c = (int)(idx % c4n) * 4;
    const float4 v = *reinterpret_cast<const float4*>(in + r * ldin + c);
    ushort4 hi, lo;
    split2f(v.x, hi.x, lo.x); split2f(v.y, hi.y, lo.y);
    split2f(v.z, hi.z, lo.z); split2f(v.w, hi.w, lo.w);
    __nv_bfloat16* op = out + r * ((ll)3 * C) + c;
    *reinterpret_cast<ushort4*>(op) = hi;
    *reinterpret_cast<ushort4*>(op + C) = hi;
    *reinterpret_cast<ushort4*>(op + 2 * C) = lo;
}

// transpose+split bf16 ([hi|lo|hi] weights)
__global__ void splitT_k(
    const float* __restrict__ in, int ldin,
    __nv_bfloat16* __restrict__ out, int K)
{
    __shared__ float t[32][33];
    const int k0 = blockIdx.x * 32, n0 = blockIdx.y * 32;
    const int tx = threadIdx.x, ty = threadIdx.y;
#pragma unroll
    for (int j = 0; j < 4; j++)
        t[ty + j * 8][tx] = in[(ll)(k0 + ty + j * 8) * ldin + n0 + tx];
    __syncthreads();
#pragma unroll
    for (int j = 0; j < 4; j++) {
        const int n = n0 + ty + j * 8, k = k0 + tx;
        const float x = t[tx][ty + j * 8];
        unsigned short h, l;
        split2f(x, h, l);
        __nv_bfloat16* base = out + (ll)n * ((ll)3 * K) + k;
        base[0] = __ushort_as_bfloat16(h);
        base[K] = __ushort_as_bfloat16(l);
        base[2 * K] = __ushort_as_bfloat16(h);
    }
}

// transpose to fp16 1-term with z batching
__global__ void splitT_h16_k(
    const float* __restrict__ in, int ldin, ll inZcols,
    __half* __restrict__ out, ll outZ, int K)
{
    __shared__ float t[32][33];
    const int k0 = blockIdx.x * 32, n0 = blockIdx.y * 32;
    const int tx = threadIdx.x, ty = threadIdx.y;
    const float* ip = in + (ll)blockIdx.z * inZcols;
#pragma unroll
    for (int j = 0; j < 4; j++)
        t[ty + j * 8][tx] = ip[(ll)(k0 + ty + j * 8) * ldin + n0 + tx];
    __syncthreads();
    __half* op = out + (ll)blockIdx.z * outZ;
#pragma unroll
    for (int j = 0; j < 4; j++) {
        const int n = n0 + ty + j * 8, k = k0 + tx;
        op[(ll)n * K + k] = __float2half_rn(t[tx][ty + j * 8]);
    }
}

// interleaved gate/up fp16 transpose pack:
// packed row n: g=n>>4, half=(n>>3)&1, off=n&7 -> src col g*8+off of (half? up : gate)
__global__ void splitT_gu_k(
    const float* __restrict__ gatew, const float* __restrict__ upw,
    __half* __restrict__ out)
{
    __shared__ float t[32][33];
    const int k0 = blockIdx.x * 32, n0 = blockIdx.y * 32;
    const int tx = threadIdx.x, ty = threadIdx.y;
    const int base = n0 >> 1;
    const float* src = (tx < 16) ? gatew : upw;
    const int scol = base + (tx & 15);
#pragma unroll
    for (int j = 0; j < 4; j++)
        t[ty + j * 8][tx] = src[(ll)(k0 + ty + j * 8) * 8192 + scol];
    __syncthreads();
#pragma unroll
    for (int j = 0; j < 4; j++) {
        const int nl = ty + j * 8;
        const int grp = nl >> 4, w16 = nl & 15;
        const int half = w16 >> 3, col = grp * 8 + (w16 & 7);
        const int s = half * 16 + col;
        out[(ll)(n0 + nl) * 2048 + k0 + tx] = __float2half_rn(t[tx][s]);
    }
}

// fp32 -> fp16 elementwise pack
__global__ __launch_bounds__(256) void pack_h16_k(
    const float* __restrict__ in, __half* __restrict__ out)
{
    const ll i = ((ll)blockIdx.x * 256 + threadIdx.x) * 4;
    const float4 v = *reinterpret_cast<const float4*>(in + i);
    *reinterpret_cast<__half2*>(out + i) = __floats2half2_rn(v.x, v.y);
    *reinterpret_cast<__half2*>(out + i + 2) = __floats2half2_rn(v.z, v.w);
}

// ======================= fused elementwise kernels =======================
__global__ __launch_bounds__(256) void rmsnorm_pack_k(
    const float* __restrict__ x, const float* __restrict__ w, __nv_bfloat16* __restrict__ out)
{
    const int r = blockIdx.x, tid = threadIdx.x;
    const float* xr = x + (ll)r * DIMN;
    float ss = 0.f;
    for (int i = tid; i < DIMN; i += 256) { float v = xr[i]; ss += v * v; }
    __shared__ float red[256];
    red[tid] = ss; __syncthreads();
    for (int s = 128; s > 0; s >>= 1) { if (tid < s) red[tid] += red[tid + s]; __syncthreads(); }
    const float scale = rsqrtf(red[0] * (1.0f / DIMN) + RMS_EPS);
    __nv_bfloat16* orow = out + (ll)r * 6144;
    for (int i = tid; i < DIMN; i += 256) {
        const float v = xr[i] * scale * w[i];
        unsigned short h, l;
        split2f(v, h, l);
        orow[i] = __ushort_as_bfloat16(h);
        orow[2048 + i] = __ushort_as_bfloat16(h);
        orow[4096 + i] = __ushort_as_bfloat16(l);
    }
}

__global__ __launch_bounds__(256) void rmsnorm_h16_k(
    const float* __restrict__ x, const float* __restrict__ w, __half* __restrict__ out)
{
    const int r = blockIdx.x, tid = threadIdx.x;
    const float* xr = x + (ll)r * DIMN;
    float ss = 0.f;
    for (int i = tid; i < DIMN; i += 256) { float v = xr[i]; ss += v * v; }
    __shared__ float red[256];
    red[tid] = ss; __syncthreads();
    for (int s = 128; s > 0; s >>= 1) { if (tid < s) red[tid] += red[tid + s]; __syncthreads(); }
    const float scale = rsqrtf(red[0] * (1.0f / DIMN) + RMS_EPS);
    __half* orow = out + (ll)r * DIMN;
    for (int i = tid; i < DIMN; i += 256)
        orow[i] = __float2half_rn(xr[i] * scale * w[i]);
}

__global__ __launch_bounds__(256) void spike_rope_h16_k(
    const float* __restrict__ q, int stride, __half* __restrict__ out)
{
    const int idx = blockIdx.x * 256 + threadIdx.x;
    const int d = idx & 63;
    const int h = (idx >> 6) & (NHEADS - 1);
    const int s = idx >> 10;
    const ll base = (ll)s * stride + h * HDIM;
    const float a = q[base + d];
    const float b = q[base + d + 64];
    const float sa = a > 1.0f ? 1.f : 0.f;
    const float sb = b > 1.0f ? 1.f : 0.f;
    const float invf = powf(10000.0f, -(float)d * (1.0f / 64.0f));
    const float fr = (float)s * invf;
    double sd, cd;
    sincos((double)fr, &sd, &cd);
    const float c = (float)cd, si = (float)sd;
    __half* op = out + (ll)h * (SEQL * HDIM) + (ll)s * HDIM;
    op[d]      = __float2half_rn(sa * c - sb * si);
    op[d + 64] = __float2half_rn(sb * c + sa * si);
}

__global__ __launch_bounds__(256) void spike_k(float* __restrict__ q, int stride)
{
    const int idx = blockIdx.x * 256 + threadIdx.x;
    const int d = idx & 127;
    const int h = (idx >> 7) & (NHEADS - 1);
    const int s = idx >> 11;
    const ll base = (ll)s * stride + h * HDIM;
    q[base + d] = q[base + d] > 1.0f ? 1.f : 0.f;
}

__global__ __launch_bounds__(256) void softmax_h16_k(
    const float* __restrict__ sc, __half* __restrict__ pr)
{
    const int q = blockIdx.x, h = blockIdx.y, tid = threadIdx.x;
    const float* row = sc + ((ll)h * SEQL + q) * SEQL;
    __half* orow = pr + ((ll)h * SEQL + q) * SEQL;
    const int n = q + 1;
    __shared__ float red[256];
    float m = -1e30f;
    for (int i = tid; i < n; i += 256) m = fmaxf(m, row[i]);
    red[tid] = m; __syncthreads();
    for (int s = 128; s > 0; s >>= 1) { if (tid < s) red[tid] = fmaxf(red[tid], red[tid + s]); __syncthreads(); }
    m = red[0]; __syncthreads();
    float sum = 0.f;
    for (int i = tid; i < n; i += 256) sum += expf(row[i] - m);
    red[tid] = sum; __syncthreads();
    for (int s = 128; s > 0; s >>= 1) { if (tid < s) red[tid] += red[tid + s]; __syncthreads(); }
    const float inv = 1.0f / red[0];
    const __half z = __float2half_rn(0.f);
    for (int i = tid; i < n; i += 256)
        orow[i] = __float2half_rn(expf(row[i] - m) * inv);
    for (int i = n + tid; i < SEQL; i += 256) orow[i] = z;
}

__global__ __launch_bounds__(256) void ltc_combine_k(
    const float* __restrict__ t, int nz, ll zstride,
    const float* __restrict__ tb, const float* __restrict__ gb,
    const float* __restrict__ ib, const float* __restrict__ hb,
    float* __restrict__ out)
{
    const int i = blockIdx.x * 256 + threadIdx.x;
    const int r = i >> 8;
    const int n = i & (LTCN - 1);
    float tv = 0.f, gv = 0.f, iv = 0.f;
    for (int z = 0; z < nz; z++) {
        const float* base = t + (ll)z * zstride + (ll)r * 768;
        tv += base[n]; gv += base[256 + n]; iv += base[512 + n];
    }
    const float tau = 0.1f + 9.9f / (1.f + expf(-(tv + tb[n])));
    const float gt  = 1.f / (1.f + expf(-(gv + gb[n])));
    const float ic  = tanhf(iv + ib[n]);
    const float hc  = tanhf(hb[n]);
    const float target = gt * ic + (1.f - gt) * hc;
    out[i] = tanhf(target / (tau + 1e-8f));
}

// ======================= launcher =======================
static inline float* SYMF(const void* s) { void* p; cudaGetSymbolAddress(&p, s); return (float*)p; }
static inline __nv_bfloat16* SYMB(const void* s) { void* p; cudaGetSymbolAddress(&p, s); return (__nv_bfloat16*)p; }
static inline __half* SYMH(const void* s) { void* p; cudaGetSymbolAddress(&p, s); return (__half*)p; }

extern "C" void kernel_launch(void* const* d_in, const int* in_sizes, int n_in,
                              void* d_out, int out_size)
{
    (void)in_sizes; (void)n_in; (void)out_size;
    const float* x     = (const float*)d_in[0];
    const float* anw   = (const float*)d_in[1];
    const float* fnw   = (const float*)d_in[2];
    const float* qw    = (const float*)d_in[3];
    const float* kw    = (const float*)d_in[4];
    const float* vw    = (const float*)d_in[5];
    const float* ow    = (const float*)d_in[6];
    const float* gatew = (const float*)d_in[7];
    const float* upw   = (const float*)d_in[8];
    const float* downw = (const float*)d_in[9];
    const float* projw = (const float*)d_in[10];
    const float* c0tw  = (const float*)d_in[11];
    const float* c0tb  = (const float*)d_in[12];
    const float* c0gw  = (const float*)d_in[13];
    const float* c0gb  = (const float*)d_in[14];
    const float* c0iw  = (const float*)d_in[15];
    const float* c0ib  = (const float*)d_in[16];
    const float* c0hb  = (const float*)d_in[18];
    const float* c1tw  = (const float*)d_in[19];
    const float* c1tb  = (const float*)d_in[20];
    const float* c1gw  = (const float*)d_in[21];
    const float* c1gb  = (const float*)d_in[22];
    const float* c1iw  = (const float*)d_in[23];
    const float* c1ib  = (const float*)d_in[24];
    const float* c1hb  = (const float*)d_in[26];
    float* out = (float*)d_out;

    float* qkv   = SYMF(g_qkv);   float* sc    = SYMF(g_scores);
    float* h     = SYMF(g_h);     float* inter = SYMF(g_inter);
    float* part  = SYMF(g_part);
    float* l0    = SYMF(g_l0);    float* l1    = SYMF(g_l1);

    __nv_bfloat16* Pxn  = SYMB(p_xn);   __nv_bfloat16* Pqkv = SYMB(p_qkvw);
    __nv_bfloat16* Pc1  = SYMB(p_c1w);  __nv_bfloat16* Pl0  = SYMB(p_l0);

    __half* Hq   = SYMH(h_q);    __half* Hk   = SYMH(h_k);
    __half* Hpr  = SYMH(h_pr);   __half* Hvt  = SYMH(h_vt);
    __half* Hat  = SYMH(h_at);   __half* How  = SYMH(h_ow);
    __half* Hxn  = SYMH(h_xn);   __half* Hguw = SYMH(h_guw);
    __half* Hdw  = SYMH(h_dw);   __half* Hpw  = SYMH(h_pw);
    __half* Hc0w = SYMH(h_c0w);  __half* Hin  = SYMH(h_in);
    __half* Hl1  = SYMH(h_l1);   __half* Hen  = SYMH(h_en);

    const int SMEM3 = 3 * 30720;
    cudaFuncSetAttribute((const void*)hgemm256<false, false, false>, cudaFuncAttributeMaxDynamicSharedMemorySize, SMEM3);
    cudaFuncSetAttribute((const void*)hgemm256<true, true, false>,   cudaFuncAttributeMaxDynamicSharedMemorySize, SMEM3);
    cudaFuncSetAttribute((const void*)hgemm256<false, true, false>,  cudaFuncAttributeMaxDynamicSharedMemorySize, SMEM3);
    cudaFuncSetAttribute((const void*)hgemm256<false, true, true>,   cudaFuncAttributeMaxDynamicSharedMemorySize, SMEM3);
    cudaFuncSetAttribute((const void*)hgemm_gu,                      cudaFuncAttributeMaxDynamicSharedMemorySize, SMEM3);

    const dim3 t32x8(32, 8);
    const float att_scale = 0.08838834764831845f;

    // ---- pack weights ----
    splitT_k<<<dim3(64, 64), t32x8>>>(qw, 2048, Pqkv, 2048);
    splitT_k<<<dim3(64, 64), t32x8>>>(kw, 2048, Pqkv + 2048LL * 6144, 2048);
    splitT_k<<<dim3(64, 64), t32x8>>>(vw, 2048, Pqkv + 4096LL * 6144, 2048);
    splitT_k<<<dim3(8, 8), t32x8>>>(c1tw, 256, Pc1, 256);
    splitT_k<<<dim3(8, 8), t32x8>>>(c1gw, 256, Pc1 + 256LL * 768, 256);
    splitT_k<<<dim3(8, 8), t32x8>>>(c1iw, 256, Pc1 + 512LL * 768, 256);
    splitT_h16_k<<<dim3(64, 64), t32x8>>>(ow, 2048, 0, How, 0, 2048);
    splitT_gu_k<<<dim3(64, 512), t32x8>>>(gatew, upw, Hguw);
    splitT_h16_k<<<dim3(256, 64), t32x8>>>(downw, 2048, 0, Hdw, 0, 8192);
    splitT_h16_k<<<dim3(8, 256), t32x8>>>(projw, 8192, 0, Hpw, 0, 256);
    splitT_h16_k<<<dim3(256, 8), t32x8>>>(c0tw, 256, 0, Hc0w, 0, 8192);
    splitT_h16_k<<<dim3(256, 8), t32x8>>>(c0gw, 256, 0, Hc0w + 256LL * 8192, 0, 8192);
    splitT_h16_k<<<dim3(256, 8), t32x8>>>(c0iw, 256, 0, Hc0w + 512LL * 8192, 0, 8192);

    // ---- attention ----
    rmsnorm_pack_k<<<SEQL, 256>>>(x, anw, Pxn);
    hgemm256<false, false, false><<<dim3(24, 16), 256, SMEM3>>>(Pxn, 6144, 0, Pqkv, 6144, 0, qkv, 6144, 0, nullptr, 0, 0, 6144, 1.f);
    spike_rope_h16_k<<<SEQL * NHEADS * 64 / 256, 256>>>(qkv, 6144, Hq);
    spike_rope_h16_k<<<SEQL * NHEADS * 64 / 256, 256>>>(qkv + 2048, 6144, Hk);
    spike_k<<<SEQL * NHEADS * 128 / 256, 256>>>(qkv + 4096, 6144);
    splitT_h16_k<<<dim3(64, 4, 16), t32x8>>>(qkv + 4096, 6144, 128, Hvt, 128LL * 2048, 2048);
    // scores: fp16, causal tile skip
    hgemm256<true, true, false><<<dim3(8, 16, 16), 256, SMEM3>>>(
        (const __nv_bfloat16*)Hq, 128, 2048LL * 128, (const __nv_bfloat16*)Hk, 128, 2048LL * 128,
        sc, 2048, (ll)SEQL * SEQL, nullptr, 0, 0, 128, att_scale);
    softmax_h16_k<<<dim3(SEQL, NHEADS), 256>>>(sc, Hpr);
    // AV: fp16, causal K-truncation, fp16 output
    hgemm<true, true><<<dim3(1, 16, 16), 256>>>(
        (const __nv_bfloat16*)Hpr, 2048, 2048LL * 2048, (const __nv_bfloat16*)Hvt, 2048, 128LL * 2048,
        (float*)Hat, 2048, 128, 2048, 1.f);
    // O projection: fp16 + residual
    hgemm256<false, true, false><<<dim3(8, 16), 256, SMEM3>>>(
        (const __nv_bfloat16*)Hat, 2048, 0, (const __nv_bfloat16*)How, 2048, 0,
        h, 2048, 0, x, 2048, 0, 2048, 1.f);

    // ---- LTC feed-forward ----
    rmsnorm_h16_k<<<SEQL, 256>>>(h, fnw, Hxn);
    // gate/up fused GEMM with silu epilogue
    hgemm_gu<<<dim3(64, 16), 256, SMEM3>>>(Hxn, Hguw, inter, Hin);
    // cell 0: split-K x8
    hgemm256<false, true, false><<<dim3(3, 16, 8), 256, SMEM3>>>(
        (const __nv_bfloat16*)Hin, 8192, 1024, (const __nv_bfloat16*)Hc0w, 8192, 1024,
        part, 768, 2048LL * 768, nullptr, 0, 0, 1024, 1.f);
    ltc_combine_k<<<2048, 256>>>(part, 8, 2048LL * 768, c0tb, c0gb, c0ib, c0hb, l0);
    split_k<<<2048 * 256 / 1024, 256>>>(l0, 256, Pl0, 256);
    // cell 1 (3-term bf16)
    hgemm256<false, false, false><<<dim3(3, 16), 256, SMEM3>>>(
        Pl0, 768, 0, Pc1, 768, 0, part, 768, 0, nullptr, 0, 0, 768, 1.f);
    ltc_combine_k<<<2048, 256>>>(part, 1, 0, c1tb, c1gb, c1ib, c1hb, l1);
    pack_h16_k<<<2048 * 256 / 1024, 256>>>(l1, Hl1);
    // enhanced = inter + l1 @ proj -> fp16 directly
    hgemm256<false, true, true><<<dim3(32, 16), 256, SMEM3>>>(
        (const __nv_bfloat16*)Hl1, 256, 0, (const __nv_bfloat16*)Hpw, 256, 0,
        (float*)Hen, 8192, 0, inter, 8192, 0, 256, 1.f);
    // out = h + enhanced @ down_w
    hgemm256<false, true, false><<<dim3(8, 16), 256, SMEM3>>>(
        (const __nv_bfloat16*)Hen, 8192, 0, (const __nv_bfloat16*)Hdw, 8192, 0,
        out, 2048, 0, h, 2048, 0, 8192, 1.f);
}

// round 14
// speedup vs baseline: 5.8231x; 1.0248x over previous
#include <cuda_runtime.h>
#include <cuda_bf16.h>
#include <cuda_fp16.h>
#include <math.h>
#include <stdint.h>

#define SEQL 2048
#define DIMN 2048
#define NHEADS 16
#define HDIM 128
#define HIDDEN 8192
#define LTCN 256
#define RMS_EPS 1.1920929e-07f
typedef long long ll;

// ======================= fp32 scratch =======================
__align__(256) __device__ float g_qkv[2048LL * 6144];
__align__(256) __device__ __half g_sc16[(ll)NHEADS * SEQL * SEQL];   // fp16 scores
__align__(256) __device__ float g_h[SEQL * DIMN];
__align__(256) __device__ float g_part[8LL * 2048 * 768];
__align__(256) __device__ float g_l0[SEQL * LTCN];
__align__(256) __device__ float g_l1[SEQL * LTCN];

// ======================= packed bf16 (3-term paths: QKV, c1) =======================
__align__(256) __device__ __nv_bfloat16 p_xn[2048LL * 6144];
__align__(256) __device__ __nv_bfloat16 p_qkvw[6144LL * 6144];
__align__(256) __device__ __nv_bfloat16 p_c1w[768LL * 768];
__align__(256) __device__ __nv_bfloat16 p_l0[2048LL * 768];

// ======================= packed fp16 (1-term paths) =======================
__align__(256) __device__ __half h_q[16LL * 2048 * 128];
__align__(256) __device__ __half h_k[16LL * 2048 * 128];
__align__(256) __device__ __half h_pr[16LL * 2048 * 2048];
__align__(256) __device__ __half h_vt[16LL * 128 * 2048];
__align__(256) __device__ __half h_at[2048LL * 2048];
__align__(256) __device__ __half h_ow[2048LL * 2048];
__align__(256) __device__ __half h_xn[2048LL * 2048];
__align__(256) __device__ __half h_guw[16384LL * 2048];   // interleaved gate/up
__align__(256) __device__ __half h_dw[2048LL * 8192];
__align__(256) __device__ __half h_pw[8192LL * 256];
__align__(256) __device__ __half h_c0w[768LL * 8192];
__align__(256) __device__ __half h_in[2048LL * 8192];
__align__(256) __device__ __half h_l1[2048LL * 256];
__align__(256) __device__ __half h_en[2048LL * 8192];

// ======================= helpers =======================
__device__ __forceinline__ uint32_t smem_u32(const void* p) {
    uint32_t a;
    asm("{ .reg .u64 t; cvta.to.shared.u64 t, %1; cvt.u32.u64 %0, t; }" : "=r"(a) : "l"(p));
    return a;
}
__device__ __forceinline__ void cp16(uint32_t dst, const void* src) {
    asm volatile("cp.async.cg.shared.global [%0], [%1], 16;" :: "r"(dst), "l"(src));
}
#define CP_COMMIT()  asm volatile("cp.async.commit_group;" ::: "memory")
#define CP_WAIT1()   asm volatile("cp.async.wait_group 1;" ::: "memory")
#define CP_WAIT2()   asm volatile("cp.async.wait_group 2;" ::: "memory")

__device__ __forceinline__ void ldmx4(uint32_t* r, uint32_t addr) {
    asm volatile("ldmatrix.sync.aligned.m8n8.x4.shared.b16 {%0,%1,%2,%3}, [%4];"
                 : "=r"(r[0]), "=r"(r[1]), "=r"(r[2]), "=r"(r[3]) : "r"(addr));
}
__device__ __forceinline__ void mma_bf(float* d, const uint32_t* a, uint32_t b0, uint32_t b1) {
    asm volatile(
        "mma.sync.aligned.m16n8k16.row.col.f32.bf16.bf16.f32 "
        "{%0,%1,%2,%3}, {%4,%5,%6,%7}, {%8,%9}, {%0,%1,%2,%3};"
        : "+f"(d[0]), "+f"(d[1]), "+f"(d[2]), "+f"(d[3])
        : "r"(a[0]), "r"(a[1]), "r"(a[2]), "r"(a[3]), "r"(b0), "r"(b1));
}
__device__ __forceinline__ void mma_fp(float* d, const uint32_t* a, uint32_t b0, uint32_t b1) {
    asm volatile(
        "mma.sync.aligned.m16n8k16.row.col.f32.f16.f16.f32 "
        "{%0,%1,%2,%3}, {%4,%5,%6,%7}, {%8,%9}, {%0,%1,%2,%3};"
        : "+f"(d[0]), "+f"(d[1]), "+f"(d[2]), "+f"(d[3])
        : "r"(a[0]), "r"(a[1]), "r"(a[2]), "r"(a[3]), "r"(b0), "r"(b1));
}

#define PITCH 80

// ======================= HMMA GEMM 128x256, 3-stage =======================
// OUT16: C is __half* (ldc/sC halves). D16: Dadd is __half* (ldd/sD halves).
template <bool CAUSAL, bool F16, bool OUT16, bool D16>
__global__ __launch_bounds__(256, 1) void hgemm256(
    const __nv_bfloat16* __restrict__ A, int lda, ll sA,
    const __nv_bfloat16* __restrict__ B, int ldb, ll sB,
    float* __restrict__ C, int ldc, ll sC,
    const float* __restrict__ Dadd, int ldd, ll sD,
    int Kp, float alpha)
{
    const int bm = blockIdx.y * 128;
    const int bn = blockIdx.x * 256;
    if (CAUSAL && bn > bm + 127) return;

    const int z = blockIdx.z;
    A += (ll)z * sA;
    B += (ll)z * sB;
    __half* Ch = nullptr;
    if (OUT16) Ch = (__half*)C + (ll)z * sC;
    else C += (ll)z * sC;
    const __half* Dh = nullptr;
    if (Dadd) {
        if (D16) Dh = (const __half*)Dadd + (ll)z * sD;
        else Dadd += (ll)z * sD;
    }

    extern __shared__ char smem[];
    const uint32_t sb = smem_u32(smem);
    const int tid = threadIdx.x;
    const int lane = tid & 31;
    const int wid = tid >> 5;
    const int wm = wid & 1;
    const int wn = wid >> 1;

    float acc[4][8][4];
#pragma unroll
    for (int i = 0; i < 4; i++)
#pragma unroll
        for (int j = 0; j < 8; j++)
#pragma unroll
            for (int t = 0; t < 4; t++) acc[i][j][t] = 0.f;

    const int nK = Kp >> 5;

    auto load_stage = [&](int s, int b) {
        const uint32_t Ad = sb + b * 30720;
        const char* Ag = (const char*)A + (ll)s * 64;
#pragma unroll
        for (int j = 0; j < 2; j++) {
            int q = tid + j * 256;
            int r = q >> 2, c = q & 3;
            cp16(Ad + r * PITCH + c * 16, Ag + (ll)(bm + r) * lda * 2 + c * 16);
        }
        const uint32_t Bd = Ad + 10240;
        const char* Bg = (const char*)B + (ll)s * 64;
#pragma unroll
        for (int j = 0; j < 4; j++) {
            int q = tid + j * 256;
            int r = q >> 2, c = q & 3;
            cp16(Bd + r * PITCH + c * 16, Bg + (ll)(bn + r) * ldb * 2 + c * 16);
        }
    };

    load_stage(0, 0); CP_COMMIT();
    if (nK > 1) load_stage(1, 1);
    CP_COMMIT();
    if (nK > 2) load_stage(2, 2);
    CP_COMMIT();

    int buf = 0;
    for (int i = 0; i < nK; i++) {
        CP_WAIT2();
        __syncthreads();
        const uint32_t Ab = sb + buf * 30720;
        const uint32_t Bb = Ab + 10240;
#pragma unroll
        for (int ks = 0; ks < 2; ks++) {
            uint32_t a[4][4];
#pragma unroll
            for (int mt = 0; mt < 4; mt++) {
                const int row = wm * 64 + mt * 16 + (lane & 15);
                ldmx4(a[mt], Ab + row * PITCH + (ks * 2 + (lane >> 4)) * 16);
            }
            uint32_t bf[4][4];
#pragma unroll
            for (int p = 0; p < 4; p++) {
                const int nrow = wn * 64 + p * 16 + ((lane >> 4) << 3) + (lane & 7);
                ldmx4(bf[p], Bb + nrow * PITCH + (ks * 2 + ((lane >> 3) & 1)) * 16);
            }
#pragma unroll
            for (int mt = 0; mt < 4; mt++)
#pragma unroll
                for (int j = 0; j < 8; j++) {
                    if (F16) mma_fp(acc[mt][j], a[mt], bf[j >> 1][(j & 1) * 2], bf[j >> 1][(j & 1) * 2 + 1]);
                    else     mma_bf(acc[mt][j], a[mt], bf[j >> 1][(j & 1) * 2], bf[j >> 1][(j & 1) * 2 + 1]);
                }
        }
        __syncthreads();
        if (i + 3 < nK) load_stage(i + 3, buf);
        CP_COMMIT();
        buf = (buf == 2) ? 0 : buf + 1;
    }

    const int r0 = lane >> 2;
    const int c0 = (lane & 3) * 2;
#pragma unroll
    for (int mt = 0; mt < 4; mt++) {
#pragma unroll
        for (int j = 0; j < 8; j++) {
            const int col = bn + wn * 64 + j * 8 + c0;
            const ll row0 = bm + wm * 64 + mt * 16 + r0;
            const ll row1 = row0 + 8;
            float2 v0 = {alpha * acc[mt][j][0], alpha * acc[mt][j][1]};
            float2 v1 = {alpha * acc[mt][j][2], alpha * acc[mt][j][3]};
            if (Dadd) {
                if (D16) {
                    float2 d0 = __half22float2(*reinterpret_cast<const __half2*>(Dh + row0 * ldd + col));
                    float2 d1 = __half22float2(*reinterpret_cast<const __half2*>(Dh + row1 * ldd + col));
                    v0.x += d0.x; v0.y += d0.y; v1.x += d1.x; v1.y += d1.y;
                } else {
                    float2 d0 = *reinterpret_cast<const float2*>(Dadd + row0 * ldd + col);
                    float2 d1 = *reinterpret_cast<const float2*>(Dadd + row1 * ldd + col);
                    v0.x += d0.x; v0.y += d0.y; v1.x += d1.x; v1.y += d1.y;
                }
            }
            if (OUT16) {
                *reinterpret_cast<__half2*>(Ch + row0 * ldc + col) = __floats2half2_rn(v0.x, v0.y);
                *reinterpret_cast<__half2*>(Ch + row1 * ldc + col) = __floats2half2_rn(v1.x, v1.y);
            } else {
                *reinterpret_cast<float2*>(C + row0 * ldc + col) = v0;
                *reinterpret_cast<float2*>(C + row1 * ldc + col) = v1;
            }
        }
    }
}

// ======================= gate/up fused GEMM (fp16, interleaved weights) ============
// Epilogue: hin = fp16(silu(gate)*up) only.
__global__ __launch_bounds__(256, 1) void hgemm_gu(
    const __half* __restrict__ A, const __half* __restrict__ B,
    __half* __restrict__ hin)
{
    const int bm = blockIdx.y * 128;
    const int bn = blockIdx.x * 256;
    extern __shared__ char smem[];
    const uint32_t sb = smem_u32(smem);
    const int tid = threadIdx.x;
    const int lane = tid & 31;
    const int wid = tid >> 5;
    const int wm = wid & 1;
    const int wn = wid >> 1;

    float acc[4][8][4];
#pragma unroll
    for (int i = 0; i < 4; i++)
#pragma unroll
        for (int j = 0; j < 8; j++)
#pragma unroll
            for (int t = 0; t < 4; t++) acc[i][j][t] = 0.f;

    const int nK = 2048 >> 5;

    auto load_stage = [&](int s, int b) {
        const uint32_t Ad = sb + b * 30720;
        const char* Ag = (const char*)A + (ll)s * 64;
#pragma unroll
        for (int j = 0; j < 2; j++) {
            int q = tid + j * 256;
            int r = q >> 2, c = q & 3;
            cp16(Ad + r * PITCH + c * 16, Ag + (ll)(bm + r) * 2048 * 2 + c * 16);
        }
        const uint32_t Bd = Ad + 10240;
        const char* Bg = (const char*)B + (ll)s * 64;
#pragma unroll
        for (int j = 0; j < 4; j++) {
            int q = tid + j * 256;
            int r = q >> 2, c = q & 3;
            cp16(Bd + r * PITCH + c * 16, Bg + (ll)(bn + r) * 2048 * 2 + c * 16);
        }
    };

    load_stage(0, 0); CP_COMMIT();
    load_stage(1, 1); CP_COMMIT();
    load_stage(2, 2); CP_COMMIT();

    int buf = 0;
    for (int i = 0; i < nK; i++) {
        CP_WAIT2();
        __syncthreads();
        const uint32_t Ab = sb + buf * 30720;
        const uint32_t Bb = Ab + 10240;
#pragma unroll
        for (int ks = 0; ks < 2; ks++) {
            uint32_t a[4][4];
#pragma unroll
            for (int mt = 0; mt < 4; mt++) {
                const int row = wm * 64 + mt * 16 + (lane & 15);
                ldmx4(a[mt], Ab + row * PITCH + (ks * 2 + (lane >> 4)) * 16);
            }
            uint32_t bf[4][4];
#pragma unroll
            for (int p = 0; p < 4; p++) {
                const int nrow = wn * 64 + p * 16 + ((lane >> 4) << 3) + (lane & 7);
                ldmx4(bf[p], Bb + nrow * PITCH + (ks * 2 + ((lane >> 3) & 1)) * 16);
            }
#pragma unroll
            for (int mt = 0; mt < 4; mt++)
#pragma unroll
                for (int j = 0; j < 8; j++)
                    mma_fp(acc[mt][j], a[mt], bf[j >> 1][(j & 1) * 2], bf[j >> 1][(j & 1) * 2 + 1]);
        }
        __syncthreads();
        if (i + 3 < nK) load_stage(i + 3, buf);
        CP_COMMIT();
        buf = (buf == 2) ? 0 : buf + 1;
    }

    const int r0 = lane >> 2;
    const int c0 = (lane & 3) * 2;
#pragma unroll
    for (int mt = 0; mt < 4; mt++) {
#pragma unroll
        for (int p = 0; p < 4; p++) {
            const int ob = ((bn + wn * 64) >> 1) + p * 8 + c0;
            const ll row0 = bm + wm * 64 + mt * 16 + r0;
            const ll row1 = row0 + 8;
            const float* ga = acc[mt][2 * p];
            const float* ua = acc[mt][2 * p + 1];
            float v0x = (ga[0] / (1.f + expf(-ga[0]))) * ua[0];
            float v0y = (ga[1] / (1.f + expf(-ga[1]))) * ua[1];
            float v1x = (ga[2] / (1.f + expf(-ga[2]))) * ua[2];
            float v1y = (ga[3] / (1.f + expf(-ga[3]))) * ua[3];
            *reinterpret_cast<__half2*>(hin + row0 * 8192 + ob) = __floats2half2_rn(v0x, v0y);
            *reinterpret_cast<__half2*>(hin + row1 * 8192 + ob) = __floats2half2_rn(v1x, v1y);
        }
    }
}

// ======================= HMMA GEMM 128x128, 2-stage (AV) =======================
template <bool CK, bool OUT16>
__global__ __launch_bounds__(256) void hgemm(
    const __nv_bfloat16* __restrict__ A, int lda, ll sA,
    const __nv_bfloat16* __restrict__ B, int ldb, ll sB,
    float* __restrict__ C, int ldc, ll sC,
    int Kp, float alpha)
{
    const int bm = blockIdx.y * 128;
    const int bn = blockIdx.x * 128;
    const int z = blockIdx.z;
    A += (ll)z * sA;
    B += (ll)z * sB;
    __half* Ch = nullptr;
    if (OUT16) Ch = (__half*)C + (ll)z * sC;
    else C += (ll)z * sC;

    __shared__ char smem[4 * 128 * PITCH];
    const uint32_t sb = smem_u32(smem);
    const uint32_t Abase[2] = {sb, sb + 128 * PITCH};
    const uint32_t Bbase[2] = {sb + 2 * 128 * PITCH, sb + 3 * 128 * PITCH};

    const int tid = threadIdx.x;
    const int lane = tid & 31;
    const int wid = tid >> 5;
    const int wm = wid & 3;
    const int wn = wid >> 2;

    float acc[2][8][4];
#pragma unroll
    for (int i = 0; i < 2; i++)
#pragma unroll
        for (int j = 0; j < 8; j++)
#pragma unroll
            for (int t = 0; t < 4; t++) acc[i][j][t] = 0.f;

    const int KpEff = CK ? (bm + 128 < Kp ? bm + 128 : Kp) : Kp;
    const int nK = KpEff >> 5;

    auto load_stage = [&](int s, int b) {
        const char* Ag = (const char*)A + (ll)s * 64;
#pragma unroll
        for (int j = 0; j < 2; j++) {
            int q = tid + j * 256;
            int r = q >> 2, c = q & 3;
            cp16(Abase[b] + r * PITCH + c * 16, Ag + (ll)(bm + r) * lda * 2 + c * 16);
        }
        const char* Bg = (const char*)B + (ll)s * 64;
#pragma unroll
        for (int j = 0; j < 2; j++) {
            int q = tid + j * 256;
            int r = q >> 2, c = q & 3;
            cp16(Bbase[b] + r * PITCH + c * 16, Bg + (ll)(bn + r) * ldb * 2 + c * 16);
        }
    };

    load_stage(0, 0); CP_COMMIT();
    if (nK > 1) load_stage(1, 1);
    CP_COMMIT();

    for (int i = 0; i < nK; i++) {
        const int buf = i & 1;
        CP_WAIT1();
        __syncthreads();
        const uint32_t Ab = Abase[buf], Bb = Bbase[buf];
#pragma unroll
        for (int ks = 0; ks < 2; ks++) {
            uint32_t a[2][4];
#pragma unroll
            for (int mt = 0; mt < 2; mt++) {
                const int row = wm * 32 + mt * 16 + (lane & 15);
                ldmx4(a[mt], Ab + row * PITCH + (ks * 2 + (lane >> 4)) * 16);
            }
            uint32_t bf[4][4];
#pragma unroll
            for (int p = 0; p < 4; p++) {
                const int nrow = wn * 64 + p * 16 + ((lane >> 4) << 3) + (lane & 7);
                ldmx4(bf[p], Bb + nrow * PITCH + (ks * 2 + ((lane >> 3) & 1)) * 16);
            }
#pragma unroll
            for (int mt = 0; mt < 2; mt++)
#pragma unroll
                for (int j = 0; j < 8; j++)
                    mma_fp(acc[mt][j], a[mt], bf[j >> 1][(j & 1) * 2], bf[j >> 1][(j & 1) * 2 + 1]);
        }
        __syncthreads();
        if (i + 2 < nK) load_stage(i + 2, buf);
        CP_COMMIT();
    }

    const int r0 = lane >> 2;
    const int c0 = (lane & 3) * 2;
#pragma unroll
    for (int mt = 0; mt < 2; mt++) {
#pragma unroll
        for (int j = 0; j < 8; j++) {
            const int col = bn + wn * 64 + j * 8 + c0;
            const ll row0 = bm + wm * 32 + mt * 16 + r0;
            const ll row1 = row0 + 8;
            float2 v0 = {alpha * acc[mt][j][0], alpha * acc[mt][j][1]};
            float2 v1 = {alpha * acc[mt][j][2], alpha * acc[mt][j][3]};
            if (OUT16) {
                *reinterpret_cast<__half2*>(Ch + row0 * ldc + col) = __floats2half2_rn(v0.x, v0.y);
                *reinterpret_cast<__half2*>(Ch + row1 * ldc + col) = __floats2half2_rn(v1.x, v1.y);
            } else {
                *reinterpret_cast<float2*>(C + row0 * ldc + col) = v0;
                *reinterpret_cast<float2*>(C + row1 * ldc + col) = v1;
            }
        }
    }
}

// ======================= split/pack helpers =======================
__device__ __forceinline__ void split2f(float x, unsigned short& h, unsigned short& l) {
    __nv_bfloat16 hb = __float2bfloat16_rn(x);
    __nv_bfloat16 lb = __float2bfloat16_rn(x - __bfloat162float(hb));
    h = __bfloat16_as_ushort(hb);
    l = __bfloat16_as_ushort(lb);
}

// transpose+split bf16 ([hi|lo|hi] weights)
__global__ void splitT_k(
    const float* __restrict__ in, int ldin,
    __nv_bfloat16* __restrict__ out, int K)
{
    __shared__ float t[32][33];
    const int k0 = blockIdx.x * 32, n0 = blockIdx.y * 32;
    const int tx = threadIdx.x, ty = threadIdx.y;
#pragma unroll
    for (int j = 0; j < 4; j++)
        t[ty + j * 8][tx] = in[(ll)(k0 + ty + j * 8) * ldin + n0 + tx];
    __syncthreads();
#pragma unroll
    for (int j = 0; j < 4; j++) {
        const int n = n0 + ty + j * 8, k = k0 + tx;
        const float x = t[tx][ty + j * 8];
        unsigned short h, l;
        split2f(x, h, l);
        __nv_bfloat16* base = out + (ll)n * ((ll)3 * K) + k;
        base[0] = __ushort_as_bfloat16(h);
        base[K] = __ushort_as_bfloat16(l);
        base[2 * K] = __ushort_as_bfloat16(h);
    }
}

// transpose to fp16 1-term with z batching
__global__ void splitT_h16_k(
    const float* __restrict__ in, int ldin, ll inZcols,
    __half* __restrict__ out, ll outZ, int K)
{
    __shared__ float t[32][33];
    const int k0 = blockIdx.x * 32, n0 = blockIdx.y * 32;
    const int tx = threadIdx.x, ty = threadIdx.y;
    const float* ip = in + (ll)blockIdx.z * inZcols;
#pragma unroll
    for (int j = 0; j < 4; j++)
        t[ty + j * 8][tx] = ip[(ll)(k0 + ty + j * 8) * ldin + n0 + tx];
    __syncthreads();
    __half* op = out + (ll)blockIdx.z * outZ;
#pragma unroll
    for (int j = 0; j < 4; j++) {
        const int n = n0 + ty + j * 8, k = k0 + tx;
        op[(ll)n * K + k] = __float2half_rn(t[tx][ty + j * 8]);
    }
}

// interleaved gate/up fp16 transpose pack
__global__ void splitT_gu_k(
    const float* __restrict__ gatew, const float* __restrict__ upw,
    __half* __restrict__ out)
{
    __shared__ float t[32][33];
    const int k0 = blockIdx.x * 32, n0 = blockIdx.y * 32;
    const int tx = threadIdx.x, ty = threadIdx.y;
    const int base = n0 >> 1;
    const float* src = (tx < 16) ? gatew : upw;
    const int scol = base + (tx & 15);
#pragma unroll
    for (int j = 0; j < 4; j++)
        t[ty + j * 8][tx] = src[(ll)(k0 + ty + j * 8) * 8192 + scol];
    __syncthreads();
#pragma unroll
    for (int j = 0; j < 4; j++) {
        const int nl = ty + j * 8;
        const int grp = nl >> 4, w16 = nl & 15;
        const int half = w16 >> 3, col = grp * 8 + (w16 & 7);
        const int s = half * 16 + col;
        out[(ll)(n0 + nl) * 2048 + k0 + tx] = __float2half_rn(t[tx][s]);
    }
}

// ======================= fused elementwise kernels =======================
__global__ __launch_bounds__(256) void rmsnorm_pack_k(
    const float* __restrict__ x, const float* __restrict__ w, __nv_bfloat16* __restrict__ out)
{
    const int r = blockIdx.x, tid = threadIdx.x;
    const float* xr = x + (ll)r * DIMN;
    float ss = 0.f;
    for (int i = tid; i < DIMN; i += 256) { float v = xr[i]; ss += v * v; }
    __shared__ float red[256];
    red[tid] = ss; __syncthreads();
    for (int s = 128; s > 0; s >>= 1) { if (tid < s) red[tid] += red[tid + s]; __syncthreads(); }
    const float scale = rsqrtf(red[0] * (1.0f / DIMN) + RMS_EPS);
    __nv_bfloat16* orow = out + (ll)r * 6144;
    for (int i = tid; i < DIMN; i += 256) {
        const float v = xr[i] * scale * w[i];
        unsigned short h, l;
        split2f(v, h, l);
        orow[i] = __ushort_as_bfloat16(h);
        orow[2048 + i] = __ushort_as_bfloat16(h);
        orow[4096 + i] = __ushort_as_bfloat16(l);
    }
}

__global__ __launch_bounds__(256) void rmsnorm_h16_k(
    const float* __restrict__ x, const float* __restrict__ w, __half* __restrict__ out)
{
    const int r = blockIdx.x, tid = threadIdx.x;
    const float* xr = x + (ll)r * DIMN;
    float ss = 0.f;
    for (int i = tid; i < DIMN; i += 256) { float v = xr[i]; ss += v * v; }
    __shared__ float red[256];
    red[tid] = ss; __syncthreads();
    for (int s = 128; s > 0; s >>= 1) { if (tid < s) red[tid] += red[tid + s]; __syncthreads(); }
    const float scale = rsqrtf(red[0] * (1.0f / DIMN) + RMS_EPS);
    __half* orow = out + (ll)r * DIMN;
    for (int i = tid; i < DIMN; i += 256)
        orow[i] = __float2half_rn(xr[i] * scale * w[i]);
}

__global__ __launch_bounds__(256) void spike_rope_h16_k(
    const float* __restrict__ q, int stride, __half* __restrict__ out)
{
    const int idx = blockIdx.x * 256 + threadIdx.x;
    const int d = idx & 63;
    const int h = (idx >> 6) & (NHEADS - 1);
    const int s = idx >> 10;
    const ll base = (ll)s * stride + h * HDIM;
    const float a = q[base + d];
    const float b = q[base + d + 64];
    const float sa = a > 1.0f ? 1.f : 0.f;
    const float sb = b > 1.0f ? 1.f : 0.f;
    const float invf = powf(10000.0f, -(float)d * (1.0f / 64.0f));
    const float fr = (float)s * invf;
    double sd, cd;
    sincos((double)fr, &sd, &cd);
    const float c = (float)cd, si = (float)sd;
    __half* op = out + (ll)h * (SEQL * HDIM) + (ll)s * HDIM;
    op[d]      = __float2half_rn(sa * c - sb * si);
    op[d + 64] = __float2half_rn(sb * c + sa * si);
}

__global__ __launch_bounds__(256) void spike_k(float* __restrict__ q, int stride)
{
    const int idx = blockIdx.x * 256 + threadIdx.x;
    const int d = idx & 127;
    const int h = (idx >> 7) & (NHEADS - 1);
    const int s = idx >> 11;
    const ll base = (ll)s * stride + h * HDIM;
    q[base + d] = q[base + d] > 1.0f ? 1.f : 0.f;
}

// causal softmax: fp16 scores in, fp16 probs out; 2-pass, no max shift
// (|s| <= 22.7 so exp is safely within fp32 range)
__global__ __launch_bounds__(256) void softmax_h16_k(
    const __half* __restrict__ sc, __half* __restrict__ pr)
{
    const int q = blockIdx.x, h = blockIdx.y, tid = threadIdx.x;
    const __half* row = sc + ((ll)h * SEQL + q) * SEQL;
    __half* orow = pr + ((ll)h * SEQL + q) * SEQL;
    const int n = q + 1;
    __shared__ float red[256];
    float sum = 0.f;
    for (int i = tid; i < n; i += 256) sum += expf(__half2float(row[i]));
    red[tid] = sum; __syncthreads();
    for (int s = 128; s > 0; s >>= 1) { if (tid < s) red[tid] += red[tid + s]; __syncthreads(); }
    const float inv = 1.0f / red[0];
    for (int i = tid; i < n; i += 256)
        orow[i] = __float2half_rn(expf(__half2float(row[i])) * inv);
    // zero-fill only to the 128-boundary the AV kernel actually reads
    const int nz = (n + 127) & ~127;
    const __half z = __float2half_rn(0.f);
    for (int i = n + tid; i < nz; i += 256) orow[i] = z;
}

// LTC combine + fused output packs (bf16 3-term and/or fp16)
__global__ __launch_bounds__(256) void ltc_combine_k(
    const float* __restrict__ t, int nz, ll zstride,
    const float* __restrict__ tb, const float* __restrict__ gb,
    const float* __restrict__ ib, const float* __restrict__ hb,
    float* __restrict__ out, __nv_bfloat16* __restrict__ bf3, __half* __restrict__ h16)
{
    const int i = blockIdx.x * 256 + threadIdx.x;
    const int r = i >> 8;
    const int n = i & (LTCN - 1);
    float tv = 0.f, gv = 0.f, iv = 0.f;
    for (int z = 0; z < nz; z++) {
        const float* base = t + (ll)z * zstride + (ll)r * 768;
        tv += base[n]; gv += base[256 + n]; iv += base[512 + n];
    }
    const float tau = 0.1f + 9.9f / (1.f + expf(-(tv + tb[n])));
    const float gt  = 1.f / (1.f + expf(-(gv + gb[n])));
    const float ic  = tanhf(iv + ib[n]);
    const float hc  = tanhf(hb[n]);
    const float target = gt * ic + (1.f - gt) * hc;
    const float o = tanhf(target / (tau + 1e-8f));
    out[i] = o;
    if (bf3) {
        unsigned short hsh, lsh;
        split2f(o, hsh, lsh);
        __nv_bfloat16* bp = bf3 + (ll)r * 768 + n;
        bp[0] = __ushort_as_bfloat16(hsh);
        bp[256] = __ushort_as_bfloat16(hsh);
        bp[512] = __ushort_as_bfloat16(lsh);
    }
    if (h16) h16[i] = __float2half_rn(o);
}

// ======================= launcher =======================
static inline float* SYMF(const void* s) { void* p; cudaGetSymbolAddress(&p, s); return (float*)p; }
static inline __nv_bfloat16* SYMB(const void* s) { void* p; cudaGetSymbolAddress(&p, s); return (__nv_bfloat16*)p; }
static inline __half* SYMH(const void* s) { void* p; cudaGetSymbolAddress(&p, s); return (__half*)p; }

extern "C" void kernel_launch(void* const* d_in, const int* in_sizes, int n_in,
                              void* d_out, int out_size)
{
    (void)in_sizes; (void)n_in; (void)out_size;
    const float* x     = (const float*)d_in[0];
    const float* anw   = (const float*)d_in[1];
    const float* fnw   = (const float*)d_in[2];
    const float* qw    = (const float*)d_in[3];
    const float* kw    = (const float*)d_in[4];
    const float* vw    = (const float*)d_in[5];
    const float* ow    = (const float*)d_in[6];
    const float* gatew = (const float*)d_in[7];
    const float* upw   = (const float*)d_in[8];
    const float* downw = (const float*)d_in[9];
    const float* projw = (const float*)d_in[10];
    const float* c0tw  = (const float*)d_in[11];
    const float* c0tb  = (const float*)d_in[12];
    const float* c0gw  = (const float*)d_in[13];
    const float* c0gb  = (const float*)d_in[14];
    const float* c0iw  = (const float*)d_in[15];
    const float* c0ib  = (const float*)d_in[16];
    const float* c0hb  = (const float*)d_in[18];
    const float* c1tw  = (const float*)d_in[19];
    const float* c1tb  = (const float*)d_in[20];
    const float* c1gw  = (const float*)d_in[21];
    const float* c1gb  = (const float*)d_in[22];
    const float* c1iw  = (const float*)d_in[23];
    const float* c1ib  = (const float*)d_in[24];
    const float* c1hb  = (const float*)d_in[26];
    float* out = (float*)d_out;

    float* qkv   = SYMF(g_qkv);
    __half* Hsc  = SYMH(g_sc16);
    float* h     = SYMF(g_h);
    float* part  = SYMF(g_part);
    float* l0    = SYMF(g_l0);    float* l1    = SYMF(g_l1);

    __nv_bfloat16* Pxn  = SYMB(p_xn);   __nv_bfloat16* Pqkv = SYMB(p_qkvw);
    __nv_bfloat16* Pc1  = SYMB(p_c1w);  __nv_bfloat16* Pl0  = SYMB(p_l0);

    __half* Hq   = SYMH(h_q);    __half* Hk   = SYMH(h_k);
    __half* Hpr  = SYMH(h_pr);   __half* Hvt  = SYMH(h_vt);
    __half* Hat  = SYMH(h_at);   __half* How  = SYMH(h_ow);
    __half* Hxn  = SYMH(h_xn);   __half* Hguw = SYMH(h_guw);
    __half* Hdw  = SYMH(h_dw);   __half* Hpw  = SYMH(h_pw);
    __half* Hc0w = SYMH(h_c0w);  __half* Hin  = SYMH(h_in);
    __half* Hl1  = SYMH(h_l1);   __half* Hen  = SYMH(h_en);

    const int SMEM3 = 3 * 30720;
    cudaFuncSetAttribute((const void*)hgemm256<false, false, false, false>, cudaFuncAttributeMaxDynamicSharedMemorySize, SMEM3);
    cudaFuncSetAttribute((const void*)hgemm256<true, true, true, false>,    cudaFuncAttributeMaxDynamicSharedMemorySize, SMEM3);
    cudaFuncSetAttribute((const void*)hgemm256<false, true, false, false>,  cudaFuncAttributeMaxDynamicSharedMemorySize, SMEM3);
    cudaFuncSetAttribute((const void*)hgemm256<false, true, true, true>,    cudaFuncAttributeMaxDynamicSharedMemorySize, SMEM3);
    cudaFuncSetAttribute((const void*)hgemm_gu,                             cudaFuncAttributeMaxDynamicSharedMemorySize, SMEM3);

    const dim3 t32x8(32, 8);
    const float att_scale = 0.08838834764831845f;

    // ---- pack weights ----
    splitT_k<<<dim3(64, 64), t32x8>>>(qw, 2048, Pqkv, 2048);
    splitT_k<<<dim3(64, 64), t32x8>>>(kw, 2048, Pqkv + 2048LL * 6144, 2048);
    splitT_k<<<dim3(64, 64), t32x8>>>(vw, 2048, Pqkv + 4096LL * 6144, 2048);
    splitT_k<<<dim3(8, 8), t32x8>>>(c1tw, 256, Pc1, 256);
    splitT_k<<<dim3(8, 8), t32x8>>>(c1gw, 256, Pc1 + 256LL * 768, 256);
    splitT_k<<<dim3(8, 8), t32x8>>>(c1iw, 256, Pc1 + 512LL * 768, 256);
    splitT_h16_k<<<dim3(64, 64), t32x8>>>(ow, 2048, 0, How, 0, 2048);
    splitT_gu_k<<<dim3(64, 512), t32x8>>>(gatew, upw, Hguw);
    splitT_h16_k<<<dim3(256, 64), t32x8>>>(downw, 2048, 0, Hdw, 0, 8192);
    splitT_h16_k<<<dim3(8, 256), t32x8>>>(projw, 8192, 0, Hpw, 0, 256);
    splitT_h16_k<<<dim3(256, 8), t32x8>>>(c0tw, 256, 0, Hc0w, 0, 8192);
    splitT_h16_k<<<dim3(256, 8), t32x8>>>(c0gw, 256, 0, Hc0w + 256LL * 8192, 0, 8192);
    splitT_h16_k<<<dim3(256, 8), t32x8>>>(c0iw, 256, 0, Hc0w + 512LL * 8192, 0, 8192);

    // ---- attention ----
    rmsnorm_pack_k<<<SEQL, 256>>>(x, anw, Pxn);
    hgemm256<false, false, false, false><<<dim3(24, 16), 256, SMEM3>>>(
        Pxn, 6144, 0, Pqkv, 6144, 0, qkv, 6144, 0, nullptr, 0, 0, 6144, 1.f);
    spike_rope_h16_k<<<SEQL * NHEADS * 64 / 256, 256>>>(qkv, 6144, Hq);
    spike_rope_h16_k<<<SEQL * NHEADS * 64 / 256, 256>>>(qkv + 2048, 6144, Hk);
    spike_k<<<SEQL * NHEADS * 128 / 256, 256>>>(qkv + 4096, 6144);
    splitT_h16_k<<<dim3(64, 4, 16), t32x8>>>(qkv + 4096, 6144, 128, Hvt, 128LL * 2048, 2048);
    // scores: fp16 in/out, causal tile skip
    hgemm256<true, true, true, false><<<dim3(8, 16, 16), 256, SMEM3>>>(
        (const __nv_bfloat16*)Hq, 128, 2048LL * 128, (const __nv_bfloat16*)Hk, 128, 2048LL * 128,
        (float*)Hsc, 2048, (ll)SEQL * SEQL, nullptr, 0, 0, 128, att_scale);
    softmax_h16_k<<<dim3(SEQL, NHEADS), 256>>>(Hsc, Hpr);
    // AV: fp16, causal K-truncation, fp16 output
    hgemm<true, true><<<dim3(1, 16, 16), 256>>>(
        (const __nv_bfloat16*)Hpr, 2048, 2048LL * 2048, (const __nv_bfloat16*)Hvt, 2048, 128LL * 2048,
        (float*)Hat, 2048, 128, 2048, 1.f);
    // O projection: fp16 + fp32 residual
    hgemm256<false, true, false, false><<<dim3(8, 16), 256, SMEM3>>>(
        (const __nv_bfloat16*)Hat, 2048, 0, (const __nv_bfloat16*)How, 2048, 0,
        h, 2048, 0, x, 2048, 0, 2048, 1.f);

    // ---- LTC feed-forward ----
    rmsnorm_h16_k<<<SEQL, 256>>>(h, fnw, Hxn);
    hgemm_gu<<<dim3(64, 16), 256, SMEM3>>>(Hxn, Hguw, Hin);
    // cell 0: split-K x8
    hgemm256<false, true, false, false><<<dim3(3, 16, 8), 256, SMEM3>>>(
        (const __nv_bfloat16*)Hin, 8192, 1024, (const __nv_bfloat16*)Hc0w, 8192, 1024,
        part, 768, 2048LL * 768, nullptr, 0, 0, 1024, 1.f);
    ltc_combine_k<<<2048, 256>>>(part, 8, 2048LL * 768, c0tb, c0gb, c0ib, c0hb, l0, Pl0, nullptr);
    // cell 1 (3-term bf16)
    hgemm256<false, false, false, false><<<dim3(3, 16), 256, SMEM3>>>(
        Pl0, 768, 0, Pc1, 768, 0, part, 768, 0, nullptr, 0, 0, 768, 1.f);
    ltc_combine_k<<<2048, 256>>>(part, 1, 0, c1tb, c1gb, c1ib, c1hb, l1, nullptr, Hl1);
    // enhanced = inter(fp16) + l1 @ proj -> fp16
    hgemm256<false, true, true, true><<<dim3(32, 16), 256, SMEM3>>>(
        (const __nv_bfloat16*)Hl1, 256, 0, (const __nv_bfloat16*)Hpw, 256, 0,
        (float*)Hen, 8192, 0, (const float*)Hin, 8192, 0, 256, 1.f);
    // out = h + enhanced @ down_w
    hgemm256<false, true, false, false><<<dim3(8, 16), 256, SMEM3>>>(
        (const __nv_bfloat16*)Hen, 8192, 0, (const __nv_bfloat16*)Hdw, 8192, 0,
        out, 2048, 0, h, 2048, 0, 8192, 1.f);
}

// round 15
// speedup vs baseline: 6.3932x; 1.0979x over previous
#include <cuda_runtime.h>
#include <cuda_bf16.h>
#include <cuda_fp16.h>
#include <math.h>
#include <stdint.h>

#define SEQL 2048
#define DIMN 2048
#define NHEADS 16
#define HDIM 128
#define HIDDEN 8192
#define LTCN 256
#define RMS_EPS 1.1920929e-07f
typedef long long ll;

// ======================= scratch =======================
__align__(256) __device__ float g_qkv[2048LL * 6144];
__align__(256) __device__ __half g_sc16[(ll)NHEADS * SEQL * SEQL];
__align__(256) __device__ float g_h[SEQL * DIMN];
__align__(256) __device__ float g_part[8LL * 2048 * 768];
__align__(256) __device__ float g_l0[SEQL * LTCN];
__align__(256) __device__ float g_l1[SEQL * LTCN];

// ======================= packed bf16 (3-term path: c1) =======================
__align__(256) __device__ __nv_bfloat16 p_c1w[768LL * 768];
__align__(256) __device__ __nv_bfloat16 p_l0[2048LL * 768];

// ======================= packed fp16 =======================
__align__(256) __device__ __half h_xn2[2048LL * 4096];    // [hi|lo] 2-term
__align__(256) __device__ __half h_qkvw[6144LL * 4096];   // [hi|hi] 2-term
__align__(256) __device__ __half h_q[16LL * 2048 * 128];
__align__(256) __device__ __half h_k[16LL * 2048 * 128];
__align__(256) __device__ __half h_pr[16LL * 2048 * 2048];
__align__(256) __device__ __half h_vt[16LL * 128 * 2048];
__align__(256) __device__ __half h_at[2048LL * 2048];
__align__(256) __device__ __half h_ow[2048LL * 2048];
__align__(256) __device__ __half h_xn[2048LL * 2048];
__align__(256) __device__ __half h_guw[16384LL * 2048];   // interleaved gate/up
__align__(256) __device__ __half h_dw[2048LL * 8192];
__align__(256) __device__ __half h_pw[8192LL * 256];
__align__(256) __device__ __half h_c0w[768LL * 8192];
__align__(256) __device__ __half h_in[2048LL * 8192];
__align__(256) __device__ __half h_l1[2048LL * 256];
__align__(256) __device__ __half h_en[2048LL * 8192];

// ======================= helpers =======================
__device__ __forceinline__ uint32_t smem_u32(const void* p) {
    uint32_t a;
    asm("{ .reg .u64 t; cvta.to.shared.u64 t, %1; cvt.u32.u64 %0, t; }" : "=r"(a) : "l"(p));
    return a;
}
__device__ __forceinline__ void cp16(uint32_t dst, const void* src) {
    asm volatile("cp.async.cg.shared.global [%0], [%1], 16;" :: "r"(dst), "l"(src));
}
#define CP_COMMIT()  asm volatile("cp.async.commit_group;" ::: "memory")
#define CP_WAIT1()   asm volatile("cp.async.wait_group 1;" ::: "memory")
#define CP_WAIT2()   asm volatile("cp.async.wait_group 2;" ::: "memory")

__device__ __forceinline__ void ldmx4(uint32_t* r, uint32_t addr) {
    asm volatile("ldmatrix.sync.aligned.m8n8.x4.shared.b16 {%0,%1,%2,%3}, [%4];"
                 : "=r"(r[0]), "=r"(r[1]), "=r"(r[2]), "=r"(r[3]) : "r"(addr));
}
__device__ __forceinline__ void mma_bf(float* d, const uint32_t* a, uint32_t b0, uint32_t b1) {
    asm volatile(
        "mma.sync.aligned.m16n8k16.row.col.f32.bf16.bf16.f32 "
        "{%0,%1,%2,%3}, {%4,%5,%6,%7}, {%8,%9}, {%0,%1,%2,%3};"
        : "+f"(d[0]), "+f"(d[1]), "+f"(d[2]), "+f"(d[3])
        : "r"(a[0]), "r"(a[1]), "r"(a[2]), "r"(a[3]), "r"(b0), "r"(b1));
}
__device__ __forceinline__ void mma_fp(float* d, const uint32_t* a, uint32_t b0, uint32_t b1) {
    asm volatile(
        "mma.sync.aligned.m16n8k16.row.col.f32.f16.f16.f32 "
        "{%0,%1,%2,%3}, {%4,%5,%6,%7}, {%8,%9}, {%0,%1,%2,%3};"
        : "+f"(d[0]), "+f"(d[1]), "+f"(d[2]), "+f"(d[3])
        : "r"(a[0]), "r"(a[1]), "r"(a[2]), "r"(a[3]), "r"(b0), "r"(b1));
}

#define PITCH 80

// ======================= HMMA GEMM 128x256, 3-stage =======================
template <bool CAUSAL, bool F16, bool OUT16, bool D16>
__global__ __launch_bounds__(256, 1) void hgemm256(
    const __nv_bfloat16* __restrict__ A, int lda, ll sA,
    const __nv_bfloat16* __restrict__ B, int ldb, ll sB,
    float* __restrict__ C, int ldc, ll sC,
    const float* __restrict__ Dadd, int ldd, ll sD,
    int Kp, float alpha)
{
    const int bm = blockIdx.y * 128;
    const int bn = blockIdx.x * 256;
    if (CAUSAL && bn > bm + 127) return;

    const int z = blockIdx.z;
    A += (ll)z * sA;
    B += (ll)z * sB;
    __half* Ch = nullptr;
    if (OUT16) Ch = (__half*)C + (ll)z * sC;
    else C += (ll)z * sC;
    const __half* Dh = nullptr;
    if (Dadd) {
        if (D16) Dh = (const __half*)Dadd + (ll)z * sD;
        else Dadd += (ll)z * sD;
    }

    extern __shared__ char smem[];
    const uint32_t sb = smem_u32(smem);
    const int tid = threadIdx.x;
    const int lane = tid & 31;
    const int wid = tid >> 5;
    const int wm = wid & 1;
    const int wn = wid >> 1;

    float acc[4][8][4];
#pragma unroll
    for (int i = 0; i < 4; i++)
#pragma unroll
        for (int j = 0; j < 8; j++)
#pragma unroll
            for (int t = 0; t < 4; t++) acc[i][j][t] = 0.f;

    const int nK = Kp >> 5;

    auto load_stage = [&](int s, int b) {
        const uint32_t Ad = sb + b * 30720;
        const char* Ag = (const char*)A + (ll)s * 64;
#pragma unroll
        for (int j = 0; j < 2; j++) {
            int q = tid + j * 256;
            int r = q >> 2, c = q & 3;
            cp16(Ad + r * PITCH + c * 16, Ag + (ll)(bm + r) * lda * 2 + c * 16);
        }
        const uint32_t Bd = Ad + 10240;
        const char* Bg = (const char*)B + (ll)s * 64;
#pragma unroll
        for (int j = 0; j < 4; j++) {
            int q = tid + j * 256;
            int r = q >> 2, c = q & 3;
            cp16(Bd + r * PITCH + c * 16, Bg + (ll)(bn + r) * ldb * 2 + c * 16);
        }
    };

    load_stage(0, 0); CP_COMMIT();
    if (nK > 1) load_stage(1, 1);
    CP_COMMIT();
    if (nK > 2) load_stage(2, 2);
    CP_COMMIT();

    int buf = 0;
    for (int i = 0; i < nK; i++) {
        CP_WAIT2();
        __syncthreads();
        const uint32_t Ab = sb + buf * 30720;
        const uint32_t Bb = Ab + 10240;
#pragma unroll
        for (int ks = 0; ks < 2; ks++) {
            uint32_t a[4][4];
#pragma unroll
            for (int mt = 0; mt < 4; mt++) {
                const int row = wm * 64 + mt * 16 + (lane & 15);
                ldmx4(a[mt], Ab + row * PITCH + (ks * 2 + (lane >> 4)) * 16);
            }
            uint32_t bf[4][4];
#pragma unroll
            for (int p = 0; p < 4; p++) {
                const int nrow = wn * 64 + p * 16 + ((lane >> 4) << 3) + (lane & 7);
                ldmx4(bf[p], Bb + nrow * PITCH + (ks * 2 + ((lane >> 3) & 1)) * 16);
            }
#pragma unroll
            for (int mt = 0; mt < 4; mt++)
#pragma unroll
                for (int j = 0; j < 8; j++) {
                    if (F16) mma_fp(acc[mt][j], a[mt], bf[j >> 1][(j & 1) * 2], bf[j >> 1][(j & 1) * 2 + 1]);
                    else     mma_bf(acc[mt][j], a[mt], bf[j >> 1][(j & 1) * 2], bf[j >> 1][(j & 1) * 2 + 1]);
                }
        }
        __syncthreads();
        if (i + 3 < nK) load_stage(i + 3, buf);
        CP_COMMIT();
        buf = (buf == 2) ? 0 : buf + 1;
    }

    const int r0 = lane >> 2;
    const int c0 = (lane & 3) * 2;
#pragma unroll
    for (int mt = 0; mt < 4; mt++) {
#pragma unroll
        for (int j = 0; j < 8; j++) {
            const int col = bn + wn * 64 + j * 8 + c0;
            const ll row0 = bm + wm * 64 + mt * 16 + r0;
            const ll row1 = row0 + 8;
            float2 v0 = {alpha * acc[mt][j][0], alpha * acc[mt][j][1]};
            float2 v1 = {alpha * acc[mt][j][2], alpha * acc[mt][j][3]};
            if (Dadd) {
                if (D16) {
                    float2 d0 = __half22float2(*reinterpret_cast<const __half2*>(Dh + row0 * ldd + col));
                    float2 d1 = __half22float2(*reinterpret_cast<const __half2*>(Dh + row1 * ldd + col));
                    v0.x += d0.x; v0.y += d0.y; v1.x += d1.x; v1.y += d1.y;
                } else {
                    float2 d0 = *reinterpret_cast<const float2*>(Dadd + row0 * ldd + col);
                    float2 d1 = *reinterpret_cast<const float2*>(Dadd + row1 * ldd + col);
                    v0.x += d0.x; v0.y += d0.y; v1.x += d1.x; v1.y += d1.y;
                }
            }
            if (OUT16) {
                *reinterpret_cast<__half2*>(Ch + row0 * ldc + col) = __floats2half2_rn(v0.x, v0.y);
                *reinterpret_cast<__half2*>(Ch + row1 * ldc + col) = __floats2half2_rn(v1.x, v1.y);
            } else {
                *reinterpret_cast<float2*>(C + row0 * ldc + col) = v0;
                *reinterpret_cast<float2*>(C + row1 * ldc + col) = v1;
            }
        }
    }
}

// ======================= gate/up fused GEMM (fp16, interleaved weights) ============
__global__ __launch_bounds__(256, 1) void hgemm_gu(
    const __half* __restrict__ A, const __half* __restrict__ B,
    __half* __restrict__ hin)
{
    const int bm = blockIdx.y * 128;
    const int bn = blockIdx.x * 256;
    extern __shared__ char smem[];
    const uint32_t sb = smem_u32(smem);
    const int tid = threadIdx.x;
    const int lane = tid & 31;
    const int wid = tid >> 5;
    const int wm = wid & 1;
    const int wn = wid >> 1;

    float acc[4][8][4];
#pragma unroll
    for (int i = 0; i < 4; i++)
#pragma unroll
        for (int j = 0; j < 8; j++)
#pragma unroll
            for (int t = 0; t < 4; t++) acc[i][j][t] = 0.f;

    const int nK = 2048 >> 5;

    auto load_stage = [&](int s, int b) {
        const uint32_t Ad = sb + b * 30720;
        const char* Ag = (const char*)A + (ll)s * 64;
#pragma unroll
        for (int j = 0; j < 2; j++) {
            int q = tid + j * 256;
            int r = q >> 2, c = q & 3;
            cp16(Ad + r * PITCH + c * 16, Ag + (ll)(bm + r) * 2048 * 2 + c * 16);
        }
        const uint32_t Bd = Ad + 10240;
        const char* Bg = (const char*)B + (ll)s * 64;
#pragma unroll
        for (int j = 0; j < 4; j++) {
            int q = tid + j * 256;
            int r = q >> 2, c = q & 3;
            cp16(Bd + r * PITCH + c * 16, Bg + (ll)(bn + r) * 2048 * 2 + c * 16);
        }
    };

    load_stage(0, 0); CP_COMMIT();
    load_stage(1, 1); CP_COMMIT();
    load_stage(2, 2); CP_COMMIT();

    int buf = 0;
    for (int i = 0; i < nK; i++) {
        CP_WAIT2();
        __syncthreads();
        const uint32_t Ab = sb + buf * 30720;
        const uint32_t Bb = Ab + 10240;
#pragma unroll
        for (int ks = 0; ks < 2; ks++) {
            uint32_t a[4][4];
#pragma unroll
            for (int mt = 0; mt < 4; mt++) {
                const int row = wm * 64 + mt * 16 + (lane & 15);
                ldmx4(a[mt], Ab + row * PITCH + (ks * 2 + (lane >> 4)) * 16);
            }
            uint32_t bf[4][4];
#pragma unroll
            for (int p = 0; p < 4; p++) {
                const int nrow = wn * 64 + p * 16 + ((lane >> 4) << 3) + (lane & 7);
                ldmx4(bf[p], Bb + nrow * PITCH + (ks * 2 + ((lane >> 3) & 1)) * 16);
            }
#pragma unroll
            for (int mt = 0; mt < 4; mt++)
#pragma unroll
                for (int j = 0; j < 8; j++)
                    mma_fp(acc[mt][j], a[mt], bf[j >> 1][(j & 1) * 2], bf[j >> 1][(j & 1) * 2 + 1]);
        }
        __syncthreads();
        if (i + 3 < nK) load_stage(i + 3, buf);
        CP_COMMIT();
        buf = (buf == 2) ? 0 : buf + 1;
    }

    const int r0 = lane >> 2;
    const int c0 = (lane & 3) * 2;
#pragma unroll
    for (int mt = 0; mt < 4; mt++) {
#pragma unroll
        for (int p = 0; p < 4; p++) {
            const int ob = ((bn + wn * 64) >> 1) + p * 8 + c0;
            const ll row0 = bm + wm * 64 + mt * 16 + r0;
            const ll row1 = row0 + 8;
            const float* ga = acc[mt][2 * p];
            const float* ua = acc[mt][2 * p + 1];
            float v0x = (ga[0] / (1.f + expf(-ga[0]))) * ua[0];
            float v0y = (ga[1] / (1.f + expf(-ga[1]))) * ua[1];
            float v1x = (ga[2] / (1.f + expf(-ga[2]))) * ua[2];
            float v1y = (ga[3] / (1.f + expf(-ga[3]))) * ua[3];
            *reinterpret_cast<__half2*>(hin + row0 * 8192 + ob) = __floats2half2_rn(v0x, v0y);
            *reinterpret_cast<__half2*>(hin + row1 * 8192 + ob) = __floats2half2_rn(v1x, v1y);
        }
    }
}

// ======================= HMMA GEMM 128x128, 2-stage (AV) =======================
template <bool CK, bool OUT16>
__global__ __launch_bounds__(256) void hgemm(
    const __nv_bfloat16* __restrict__ A, int lda, ll sA,
    const __nv_bfloat16* __restrict__ B, int ldb, ll sB,
    float* __restrict__ C, int ldc, ll sC,
    int Kp, float alpha)
{
    const int bm = blockIdx.y * 128;
    const int bn = blockIdx.x * 128;
    const int z = blockIdx.z;
    A += (ll)z * sA;
    B += (ll)z * sB;
    __half* Ch = nullptr;
    if (OUT16) Ch = (__half*)C + (ll)z * sC;
    else C += (ll)z * sC;

    __shared__ char smem[4 * 128 * PITCH];
    const uint32_t sb = smem_u32(smem);
    const uint32_t Abase[2] = {sb, sb + 128 * PITCH};
    const uint32_t Bbase[2] = {sb + 2 * 128 * PITCH, sb + 3 * 128 * PITCH};

    const int tid = threadIdx.x;
    const int lane = tid & 31;
    const int wid = tid >> 5;
    const int wm = wid & 3;
    const int wn = wid >> 2;

    float acc[2][8][4];
#pragma unroll
    for (int i = 0; i < 2; i++)
#pragma unroll
        for (int j = 0; j < 8; j++)
#pragma unroll
            for (int t = 0; t < 4; t++) acc[i][j][t] = 0.f;

    const int KpEff = CK ? (bm + 128 < Kp ? bm + 128 : Kp) : Kp;
    const int nK = KpEff >> 5;

    auto load_stage = [&](int s, int b) {
        const char* Ag = (const char*)A + (ll)s * 64;
#pragma unroll
        for (int j = 0; j < 2; j++) {
            int q = tid + j * 256;
            int r = q >> 2, c = q & 3;
            cp16(Abase[b] + r * PITCH + c * 16, Ag + (ll)(bm + r) * lda * 2 + c * 16);
        }
        const char* Bg = (const char*)B + (ll)s * 64;
#pragma unroll
        for (int j = 0; j < 2; j++) {
            int q = tid + j * 256;
            int r = q >> 2, c = q & 3;
            cp16(Bbase[b] + r * PITCH + c * 16, Bg + (ll)(bn + r) * ldb * 2 + c * 16);
        }
    };

    load_stage(0, 0); CP_COMMIT();
    if (nK > 1) load_stage(1, 1);
    CP_COMMIT();

    for (int i = 0; i < nK; i++) {
        const int buf = i & 1;
        CP_WAIT1();
        __syncthreads();
        const uint32_t Ab = Abase[buf], Bb = Bbase[buf];
#pragma unroll
        for (int ks = 0; ks < 2; ks++) {
            uint32_t a[2][4];
#pragma unroll
            for (int mt = 0; mt < 2; mt++) {
                const int row = wm * 32 + mt * 16 + (lane & 15);
                ldmx4(a[mt], Ab + row * PITCH + (ks * 2 + (lane >> 4)) * 16);
            }
            uint32_t bf[4][4];
#pragma unroll
            for (int p = 0; p < 4; p++) {
                const int nrow = wn * 64 + p * 16 + ((lane >> 4) << 3) + (lane & 7);
                ldmx4(bf[p], Bb + nrow * PITCH + (ks * 2 + ((lane >> 3) & 1)) * 16);
            }
#pragma unroll
            for (int mt = 0; mt < 2; mt++)
#pragma unroll
                for (int j = 0; j < 8; j++)
                    mma_fp(acc[mt][j], a[mt], bf[j >> 1][(j & 1) * 2], bf[j >> 1][(j & 1) * 2 + 1]);
        }
        __syncthreads();
        if (i + 2 < nK) load_stage(i + 2, buf);
        CP_COMMIT();
    }

    const int r0 = lane >> 2;
    const int c0 = (lane & 3) * 2;
#pragma unroll
    for (int mt = 0; mt < 2; mt++) {
#pragma unroll
        for (int j = 0; j < 8; j++) {
            const int col = bn + wn * 64 + j * 8 + c0;
            const ll row0 = bm + wm * 32 + mt * 16 + r0;
            const ll row1 = row0 + 8;
            float2 v0 = {alpha * acc[mt][j][0], alpha * acc[mt][j][1]};
            float2 v1 = {alpha * acc[mt][j][2], alpha * acc[mt][j][3]};
            if (OUT16) {
                *reinterpret_cast<__half2*>(Ch + row0 * ldc + col) = __floats2half2_rn(v0.x, v0.y);
                *reinterpret_cast<__half2*>(Ch + row1 * ldc + col) = __floats2half2_rn(v1.x, v1.y);
            } else {
                *reinterpret_cast<float2*>(C + row0 * ldc + col) = v0;
                *reinterpret_cast<float2*>(C + row1 * ldc + col) = v1;
            }
        }
    }
}

// ======================= split/pack helpers =======================
__device__ __forceinline__ void split2f(float x, unsigned short& h, unsigned short& l) {
    __nv_bfloat16 hb = __float2bfloat16_rn(x);
    __nv_bfloat16 lb = __float2bfloat16_rn(x - __bfloat162float(hb));
    h = __bfloat16_as_ushort(hb);
    l = __bfloat16_as_ushort(lb);
}

// transpose+split bf16 ([hi|lo|hi] weights, c1 only)
__global__ void splitT_k(
    const float* __restrict__ in, int ldin,
    __nv_bfloat16* __restrict__ out, int K)
{
    __shared__ float t[32][33];
    const int k0 = blockIdx.x * 32, n0 = blockIdx.y * 32;
    const int tx = threadIdx.x, ty = threadIdx.y;
#pragma unroll
    for (int j = 0; j < 4; j++)
        t[ty + j * 8][tx] = in[(ll)(k0 + ty + j * 8) * ldin + n0 + tx];
    __syncthreads();
#pragma unroll
    for (int j = 0; j < 4; j++) {
        const int n = n0 + ty + j * 8, k = k0 + tx;
        const float x = t[tx][ty + j * 8];
        unsigned short h, l;
        split2f(x, h, l);
        __nv_bfloat16* base = out + (ll)n * ((ll)3 * K) + k;
        base[0] = __ushort_as_bfloat16(h);
        base[K] = __ushort_as_bfloat16(l);
        base[2 * K] = __ushort_as_bfloat16(h);
    }
}

// transpose to fp16 1-term with z batching
__global__ void splitT_h16_k(
    const float* __restrict__ in, int ldin, ll inZcols,
    __half* __restrict__ out, ll outZ, int K)
{
    __shared__ float t[32][33];
    const int k0 = blockIdx.x * 32, n0 = blockIdx.y * 32;
    const int tx = threadIdx.x, ty = threadIdx.y;
    const float* ip = in + (ll)blockIdx.z * inZcols;
#pragma unroll
    for (int j = 0; j < 4; j++)
        t[ty + j * 8][tx] = ip[(ll)(k0 + ty + j * 8) * ldin + n0 + tx];
    __syncthreads();
    __half* op = out + (ll)blockIdx.z * outZ;
#pragma unroll
    for (int j = 0; j < 4; j++) {
        const int n = n0 + ty + j * 8, k = k0 + tx;
        op[(ll)n * K + k] = __float2half_rn(t[tx][ty + j * 8]);
    }
}

// transpose to fp16 2-term [hi|hi] (QKV weights): out row = [hi(K) | hi(K)], stride 2K
__global__ void splitT_h16dup_k(
    const float* __restrict__ in, int ldin,
    __half* __restrict__ out, int K)
{
    __shared__ float t[32][33];
    const int k0 = blockIdx.x * 32, n0 = blockIdx.y * 32;
    const int tx = threadIdx.x, ty = threadIdx.y;
#pragma unroll
    for (int j = 0; j < 4; j++)
        t[ty + j * 8][tx] = in[(ll)(k0 + ty + j * 8) * ldin + n0 + tx];
    __syncthreads();
#pragma unroll
    for (int j = 0; j < 4; j++) {
        const int n = n0 + ty + j * 8, k = k0 + tx;
        const __half hv = __float2half_rn(t[tx][ty + j * 8]);
        __half* base = out + (ll)n * (2 * K) + k;
        base[0] = hv;
        base[K] = hv;
    }
}

// interleaved gate/up fp16 transpose pack
__global__ void splitT_gu_k(
    const float* __restrict__ gatew, const float* __restrict__ upw,
    __half* __restrict__ out)
{
    __shared__ float t[32][33];
    const int k0 = blockIdx.x * 32, n0 = blockIdx.y * 32;
    const int tx = threadIdx.x, ty = threadIdx.y;
    const int base = n0 >> 1;
    const float* src = (tx < 16) ? gatew : upw;
    const int scol = base + (tx & 15);
#pragma unroll
    for (int j = 0; j < 4; j++)
        t[ty + j * 8][tx] = src[(ll)(k0 + ty + j * 8) * 8192 + scol];
    __syncthreads();
#pragma unroll
    for (int j = 0; j < 4; j++) {
        const int nl = ty + j * 8;
        const int grp = nl >> 4, w16 = nl & 15;
        const int half = w16 >> 3, col = grp * 8 + (w16 & 7);
        const int s = half * 16 + col;
        out[(ll)(n0 + nl) * 2048 + k0 + tx] = __float2half_rn(t[tx][s]);
    }
}

// ======================= fused elementwise kernels =======================
// rmsnorm -> fp16 2-term [hi|lo] pack (row stride 4096)
__global__ __launch_bounds__(256) void rmsnorm_h16x2_k(
    const float* __restrict__ x, const float* __restrict__ w, __half* __restrict__ out)
{
    const int r = blockIdx.x, tid = threadIdx.x;
    const float* xr = x + (ll)r * DIMN;
    float ss = 0.f;
    for (int i = tid; i < DIMN; i += 256) { float v = xr[i]; ss += v * v; }
    __shared__ float red[256];
    red[tid] = ss; __syncthreads();
    for (int s = 128; s > 0; s >>= 1) { if (tid < s) red[tid] += red[tid + s]; __syncthreads(); }
    const float scale = rsqrtf(red[0] * (1.0f / DIMN) + RMS_EPS);
    __half* orow = out + (ll)r * 4096;
    for (int i = tid; i < DIMN; i += 256) {
        const float v = xr[i] * scale * w[i];
        const __half hv = __float2half_rn(v);
        const __half lv = __float2half_rn(v - __half2float(hv));
        orow[i] = hv;
        orow[2048 + i] = lv;
    }
}

__global__ __launch_bounds__(256) void rmsnorm_h16_k(
    const float* __restrict__ x, const float* __restrict__ w, __half* __restrict__ out)
{
    const int r = blockIdx.x, tid = threadIdx.x;
    const float* xr = x + (ll)r * DIMN;
    float ss = 0.f;
    for (int i = tid; i < DIMN; i += 256) { float v = xr[i]; ss += v * v; }
    __shared__ float red[256];
    red[tid] = ss; __syncthreads();
    for (int s = 128; s > 0; s >>= 1) { if (tid < s) red[tid] += red[tid + s]; __syncthreads(); }
    const float scale = rsqrtf(red[0] * (1.0f / DIMN) + RMS_EPS);
    __half* orow = out + (ll)r * DIMN;
    for (int i = tid; i < DIMN; i += 256)
        orow[i] = __float2half_rn(xr[i] * scale * w[i]);
}

__global__ __launch_bounds__(256) void spike_rope_h16_k(
    const float* __restrict__ q, int stride, __half* __restrict__ out)
{
    const int idx = blockIdx.x * 256 + threadIdx.x;
    const int d = idx & 63;
    const int h = (idx >> 6) & (NHEADS - 1);
    const int s = idx >> 10;
    const ll base = (ll)s * stride + h * HDIM;
    const float a = q[base + d];
    const float b = q[base + d + 64];
    const float sa = a > 1.0f ? 1.f : 0.f;
    const float sb = b > 1.0f ? 1.f : 0.f;
    const float invf = powf(10000.0f, -(float)d * (1.0f / 64.0f));
    const float fr = (float)s * invf;
    double sd, cd;
    sincos((double)fr, &sd, &cd);
    const float c = (float)cd, si = (float)sd;
    __half* op = out + (ll)h * (SEQL * HDIM) + (ll)s * HDIM;
    op[d]      = __float2half_rn(sa * c - sb * si);
    op[d + 64] = __float2half_rn(sb * c + sa * si);
}

__global__ __launch_bounds__(256) void spike_k(float* __restrict__ q, int stride)
{
    const int idx = blockIdx.x * 256 + threadIdx.x;
    const int d = idx & 127;
    const int h = (idx >> 7) & (NHEADS - 1);
    const int s = idx >> 11;
    const ll base = (ll)s * stride + h * HDIM;
    q[base + d] = q[base + d] > 1.0f ? 1.f : 0.f;
}

// causal softmax: fp16 in/out; single pass with register-cached exp
__global__ __launch_bounds__(256) void softmax_h16_k(
    const __half* __restrict__ sc, __half* __restrict__ pr)
{
    const int q = blockIdx.x, h = blockIdx.y, tid = threadIdx.x;
    const __half* row = sc + ((ll)h * SEQL + q) * SEQL;
    __half* orow = pr + ((ll)h * SEQL + q) * SEQL;
    const int n = q + 1;
    __shared__ float red[256];
    float ev[8];
    float sum = 0.f;
    int j = 0;
    for (int i = tid; i < n; i += 256, j++) {
        ev[j] = expf(__half2float(row[i]));
        sum += ev[j];
    }
    red[tid] = sum; __syncthreads();
    for (int s = 128; s > 0; s >>= 1) { if (tid < s) red[tid] += red[tid + s]; __syncthreads(); }
    const float inv = 1.0f / red[0];
    j = 0;
    for (int i = tid; i < n; i += 256, j++)
        orow[i] = __float2half_rn(ev[j] * inv);
    const int nz = (n + 127) & ~127;
    const __half z = __float2half_rn(0.f);
    for (int i = n + tid; i < nz; i += 256) orow[i] = z;
}

// LTC combine + fused output packs
__global__ __launch_bounds__(256) void ltc_combine_k(
    const float* __restrict__ t, int nz, ll zstride,
    const float* __restrict__ tb, const float* __restrict__ gb,
    const float* __restrict__ ib, const float* __restrict__ hb,
    float* __restrict__ out, __nv_bfloat16* __restrict__ bf3, __half* __restrict__ h16)
{
    const int i = blockIdx.x * 256 + threadIdx.x;
    const int r = i >> 8;
    const int n = i & (LTCN - 1);
    float tv = 0.f, gv = 0.f, iv = 0.f;
    for (int z = 0; z < nz; z++) {
        const float* base = t + (ll)z * zstride + (ll)r * 768;
        tv += base[n]; gv += base[256 + n]; iv += base[512 + n];
    }
    const float tau = 0.1f + 9.9f / (1.f + expf(-(tv + tb[n])));
    const float gt  = 1.f / (1.f + expf(-(gv + gb[n])));
    const float ic  = tanhf(iv + ib[n]);
    const float hc  = tanhf(hb[n]);
    const float target = gt * ic + (1.f - gt) * hc;
    const float o = tanhf(target / (tau + 1e-8f));
    out[i] = o;
    if (bf3) {
        unsigned short hsh, lsh;
        split2f(o, hsh, lsh);
        __nv_bfloat16* bp = bf3 + (ll)r * 768 + n;
        bp[0] = __ushort_as_bfloat16(hsh);
        bp[256] = __ushort_as_bfloat16(hsh);
        bp[512] = __ushort_as_bfloat16(lsh);
    }
    if (h16) h16[i] = __float2half_rn(o);
}

// ======================= launcher =======================
static inline float* SYMF(const void* s) { void* p; cudaGetSymbolAddress(&p, s); return (float*)p; }
static inline __nv_bfloat16* SYMB(const void* s) { void* p; cudaGetSymbolAddress(&p, s); return (__nv_bfloat16*)p; }
static inline __half* SYMH(const void* s) { void* p; cudaGetSymbolAddress(&p, s); return (__half*)p; }

extern "C" void kernel_launch(void* const* d_in, const int* in_sizes, int n_in,
                              void* d_out, int out_size)
{
    (void)in_sizes; (void)n_in; (void)out_size;
    const float* x     = (const float*)d_in[0];
    const float* anw   = (const float*)d_in[1];
    const float* fnw   = (const float*)d_in[2];
    const float* qw    = (const float*)d_in[3];
    const float* kw    = (const float*)d_in[4];
    const float* vw    = (const float*)d_in[5];
    const float* ow    = (const float*)d_in[6];
    const float* gatew = (const float*)d_in[7];
    const float* upw   = (const float*)d_in[8];
    const float* downw = (const float*)d_in[9];
    const float* projw = (const float*)d_in[10];
    const float* c0tw  = (const float*)d_in[11];
    const float* c0tb  = (const float*)d_in[12];
    const float* c0gw  = (const float*)d_in[13];
    const float* c0gb  = (const float*)d_in[14];
    const float* c0iw  = (const float*)d_in[15];
    const float* c0ib  = (const float*)d_in[16];
    const float* c0hb  = (const float*)d_in[18];
    const float* c1tw  = (const float*)d_in[19];
    const float* c1tb  = (const float*)d_in[20];
    const float* c1gw  = (const float*)d_in[21];
    const float* c1gb  = (const float*)d_in[22];
    const float* c1iw  = (const float*)d_in[23];
    const float* c1ib  = (const float*)d_in[24];
    const float* c1hb  = (const float*)d_in[26];
    float* out = (float*)d_out;

    float* qkv   = SYMF(g_qkv);
    __half* Hsc  = SYMH(g_sc16);
    float* h     = SYMF(g_h);
    float* part  = SYMF(g_part);
    float* l0    = SYMF(g_l0);    float* l1    = SYMF(g_l1);

    __nv_bfloat16* Pc1  = SYMB(p_c1w);  __nv_bfloat16* Pl0  = SYMB(p_l0);

    __half* Hxn2 = SYMH(h_xn2);  __half* Hqkw = SYMH(h_qkvw);
    __half* Hq   = SYMH(h_q);    __half* Hk   = SYMH(h_k);
    __half* Hpr  = SYMH(h_pr);   __half* Hvt  = SYMH(h_vt);
    __half* Hat  = SYMH(h_at);   __half* How  = SYMH(h_ow);
    __half* Hxn  = SYMH(h_xn);   __half* Hguw = SYMH(h_guw);
    __half* Hdw  = SYMH(h_dw);   __half* Hpw  = SYMH(h_pw);
    __half* Hc0w = SYMH(h_c0w);  __half* Hin  = SYMH(h_in);
    __half* Hl1  = SYMH(h_l1);   __half* Hen  = SYMH(h_en);

    const int SMEM3 = 3 * 30720;
    cudaFuncSetAttribute((const void*)hgemm256<false, false, false, false>, cudaFuncAttributeMaxDynamicSharedMemorySize, SMEM3);
    cudaFuncSetAttribute((const void*)hgemm256<true, true, true, false>,    cudaFuncAttributeMaxDynamicSharedMemorySize, SMEM3);
    cudaFuncSetAttribute((const void*)hgemm256<false, true, false, false>,  cudaFuncAttributeMaxDynamicSharedMemorySize, SMEM3);
    cudaFuncSetAttribute((const void*)hgemm256<false, true, true, true>,    cudaFuncAttributeMaxDynamicSharedMemorySize, SMEM3);
    cudaFuncSetAttribute((const void*)hgemm_gu,                             cudaFuncAttributeMaxDynamicSharedMemorySize, SMEM3);

    const dim3 t32x8(32, 8);
    const float att_scale = 0.08838834764831845f;

    // ---- pack weights ----
    splitT_h16dup_k<<<dim3(64, 64), t32x8>>>(qw, 2048, Hqkw, 2048);
    splitT_h16dup_k<<<dim3(64, 64), t32x8>>>(kw, 2048, Hqkw + 2048LL * 4096, 2048);
    splitT_h16dup_k<<<dim3(64, 64), t32x8>>>(vw, 2048, Hqkw + 4096LL * 4096, 2048);
    splitT_k<<<dim3(8, 8), t32x8>>>(c1tw, 256, Pc1, 256);
    splitT_k<<<dim3(8, 8), t32x8>>>(c1gw, 256, Pc1 + 256LL * 768, 256);
    splitT_k<<<dim3(8, 8), t32x8>>>(c1iw, 256, Pc1 + 512LL * 768, 256);
    splitT_h16_k<<<dim3(64, 64), t32x8>>>(ow, 2048, 0, How, 0, 2048);
    splitT_gu_k<<<dim3(64, 512), t32x8>>>(gatew, upw, Hguw);
    splitT_h16_k<<<dim3(256, 64), t32x8>>>(downw, 2048, 0, Hdw, 0, 8192);
    splitT_h16_k<<<dim3(8, 256), t32x8>>>(projw, 8192, 0, Hpw, 0, 256);
    splitT_h16_k<<<dim3(256, 8), t32x8>>>(c0tw, 256, 0, Hc0w, 0, 8192);
    splitT_h16_k<<<dim3(256, 8), t32x8>>>(c0gw, 256, 0, Hc0w + 256LL * 8192, 0, 8192);
    splitT_h16_k<<<dim3(256, 8), t32x8>>>(c0iw, 256, 0, Hc0w + 512LL * 8192, 0, 8192);

    // ---- attention ----
    rmsnorm_h16x2_k<<<SEQL, 256>>>(x, anw, Hxn2);
    // QKV: fp16 2-term cross split, K'=4096
    hgemm256<false, true, false, false><<<dim3(24, 16), 256, SMEM3>>>(
        (const __nv_bfloat16*)Hxn2, 4096, 0, (const __nv_bfloat16*)Hqkw, 4096, 0,
        qkv, 6144, 0, nullptr, 0, 0, 4096, 1.f);
    spike_rope_h16_k<<<SEQL * NHEADS * 64 / 256, 256>>>(qkv, 6144, Hq);
    spike_rope_h16_k<<<SEQL * NHEADS * 64 / 256, 256>>>(qkv + 2048, 6144, Hk);
    spike_k<<<SEQL * NHEADS * 128 / 256, 256>>>(qkv + 4096, 6144);
    splitT_h16_k<<<dim3(64, 4, 16), t32x8>>>(qkv + 4096, 6144, 128, Hvt, 128LL * 2048, 2048);
    // scores: fp16 in/out, causal tile skip
    hgemm256<true, true, true, false><<<dim3(8, 16, 16), 256, SMEM3>>>(
        (const __nv_bfloat16*)Hq, 128, 2048LL * 128, (const __nv_bfloat16*)Hk, 128, 2048LL * 128,
        (float*)Hsc, 2048, (ll)SEQL * SEQL, nullptr, 0, 0, 128, att_scale);
    softmax_h16_k<<<dim3(SEQL, NHEADS), 256>>>(Hsc, Hpr);
    // AV: fp16, causal K-truncation, fp16 output
    hgemm<true, true><<<dim3(1, 16, 16), 256>>>(
        (const __nv_bfloat16*)Hpr, 2048, 2048LL * 2048, (const __nv_bfloat16*)Hvt, 2048, 128LL * 2048,
        (float*)Hat, 2048, 128, 2048, 1.f);
    // O projection: fp16 + fp32 residual
    hgemm256<false, true, false, false><<<dim3(8, 16), 256, SMEM3>>>(
        (const __nv_bfloat16*)Hat, 2048, 0, (const __nv_bfloat16*)How, 2048, 0,
        h, 2048, 0, x, 2048, 0, 2048, 1.f);

    // ---- LTC feed-forward ----
    rmsnorm_h16_k<<<SEQL, 256>>>(h, fnw, Hxn);
    hgemm_gu<<<dim3(64, 16), 256, SMEM3>>>(Hxn, Hguw, Hin);
    // cell 0: split-K x8
    hgemm256<false, true, false, false><<<dim3(3, 16, 8), 256, SMEM3>>>(
        (const __nv_bfloat16*)Hin, 8192, 1024, (const __nv_bfloat16*)Hc0w, 8192, 1024,
        part, 768, 2048LL * 768, nullptr, 0, 0, 1024, 1.f);
    ltc_combine_k<<<2048, 256>>>(part, 8, 2048LL * 768, c0tb, c0gb, c0ib, c0hb, l0, Pl0, nullptr);
    // cell 1 (3-term bf16)
    hgemm256<false, false, false, false><<<dim3(3, 16), 256, SMEM3>>>(
        Pl0, 768, 0, Pc1, 768, 0, part, 768, 0, nullptr, 0, 0, 768, 1.f);
    ltc_combine_k<<<2048, 256>>>(part, 1, 0, c1tb, c1gb, c1ib, c1hb, l1, nullptr, Hl1);
    // enhanced = inter(fp16) + l1 @ proj -> fp16
    hgemm256<false, true, true, true><<<dim3(32, 16), 256, SMEM3>>>(
        (const __nv_bfloat16*)Hl1, 256, 0, (const __nv_bfloat16*)Hpw, 256, 0,
        (float*)Hen, 8192, 0, (const float*)Hin, 8192, 0, 256, 1.f);
    // out = h + enhanced @ down_w
    hgemm256<false, true, false, false><<<dim3(8, 16), 256, SMEM3>>>(
        (const __nv_bfloat16*)Hen, 8192, 0, (const __nv_bfloat16*)Hdw, 8192, 0,
        out, 2048, 0, h, 2048, 0, 8192, 1.f);
}